// round 10
// baseline (speedup 1.0000x reference)
#include <cuda_runtime.h>
#include <cuda_bf16.h>
#include <math.h>
#include <cstdint>

#define BSZ 16
#define SEQ 512
#define DM  512
#define NH  8
#define DKH 64
#define MTOT (BSZ*SEQ)
#define NEG_INF (__int_as_float(0xff800000))

// ===================== scratch =====================
__device__ __nv_bfloat16 g_Ain[3u*2u*4194304u];
__device__ __nv_bfloat16 g_Qb [2u*4194304u];     // [p][bh][mt(4)][st(2)][8KB]
__device__ __nv_bfloat16 g_Kb [2u*4194304u];
__device__ __nv_bfloat16 g_Vtb[2u*4194304u];     // [p][bh][st(16)][4KB]
__device__ float g_X [MTOT*DM];
__device__ float g_Y [MTOT*DM];
__device__ __nv_bfloat16 g_Yb[2u*4194304u];
__device__ __nv_bfloat16 g_Hb[2u*1048576u];
__device__ unsigned long long g_sacc[4];
__device__ unsigned char g_Wpk[5u*1024u*1024u];

// ===================== asm helpers =====================
__device__ __forceinline__ uint32_t smem_to_u32(const void* p) {
    uint32_t a;
    asm("{ .reg .u64 t; cvta.to.shared.u64 t, %1; cvt.u32.u64 %0, t; }" : "=r"(a) : "l"(p));
    return a;
}
__device__ __forceinline__ void ldsm4(uint32_t* r, uint32_t addr) {
    asm volatile("ldmatrix.sync.aligned.m8n8.x4.shared.b16 {%0,%1,%2,%3}, [%4];"
        : "=r"(r[0]), "=r"(r[1]), "=r"(r[2]), "=r"(r[3]) : "r"(addr));
}
__device__ __forceinline__ void mma16816(float* c, const uint32_t* a, const uint32_t* b) {
    asm volatile("mma.sync.aligned.m16n8k16.row.col.f32.bf16.bf16.f32 "
        "{%0,%1,%2,%3}, {%4,%5,%6,%7}, {%8,%9}, {%0,%1,%2,%3};"
        : "+f"(c[0]), "+f"(c[1]), "+f"(c[2]), "+f"(c[3])
        : "r"(a[0]), "r"(a[1]), "r"(a[2]), "r"(a[3]), "r"(b[0]), "r"(b[1]));
}
__device__ __forceinline__ uint32_t pack_hi(float x, float y, float& lx, float& ly) {
    __nv_bfloat162 h = __floats2bfloat162_rn(x, y);
    lx = x - __bfloat162float(h.x);
    ly = y - __bfloat162float(h.y);
    return *reinterpret_cast<uint32_t*>(&h);
}
__device__ __forceinline__ uint32_t pack_lo(float lx, float ly) {
    __nv_bfloat162 l = __floats2bfloat162_rn(lx, ly);
    return *reinterpret_cast<uint32_t*>(&l);
}
__device__ __forceinline__ int swzoff(int r, int kb) {
    return r * 64 + ((((kb >> 4) ^ ((r >> 1) & 3)) << 4)) + (kb & 15);
}
#define BULK_G2S(dst, src, bytes, mbar) \
    asm volatile("cp.async.bulk.shared::cluster.global.mbarrier::complete_tx::bytes [%0], [%1], %2, [%3];" \
        :: "r"(dst), "l"(src), "r"(bytes), "r"(mbar) : "memory")
#define MBARRIER_INIT(mbar, cnt) \
    asm volatile("mbarrier.init.shared.b64 [%0], %1;" :: "r"((uint32_t)(mbar)), "r"((uint32_t)(cnt)) : "memory")
#define MBARRIER_EXPECT_TX(mbar, bytes) \
    asm volatile("mbarrier.arrive.expect_tx.shared.b64 _, [%0], %1;" :: "r"((uint32_t)(mbar)), "r"((uint32_t)(bytes)) : "memory")
#define MBARRIER_WAIT_PARITY(mbar, parity) do { \
    uint32_t _m = (uint32_t)(mbar); uint32_t _p = (uint32_t)(parity); uint32_t _d; \
    asm volatile("{\n\t.reg .pred p;\n\tmbarrier.try_wait.parity.acquire.cta.shared::cta.b64 p, [%1], %2;\n\tselp.b32 %0, 1, 0, p;\n\t}" \
        : "=r"(_d) : "r"(_m), "r"(_p) : "memory"); \
    if (!_d) { \
        asm volatile("{\n\t.reg .pred P1;\n\tWL_%=:\n\tmbarrier.try_wait.parity.acquire.cta.shared::cta.b64 P1, [%0], %1, 0x989680;\n\t@P1 bra.uni WD_%=;\n\tbra.uni WL_%=;\n\tWD_%=:\n\t}" \
            :: "r"(_m), "r"(_p) : "memory"); \
    } } while (0)

// ===================== weight pre-split =====================
__global__ __launch_bounds__(256) void wconv_all(
    const float* __restrict__ Wq, const float* __restrict__ Wk,
    const float* __restrict__ Wv, const float* __restrict__ Wo,
    const float* __restrict__ Wi2, unsigned char* __restrict__ dst)
{
    if (blockIdx.x == 0 && threadIdx.x < 4) g_sacc[threadIdx.x] = 0ull;
    int bb = blockIdx.x;
    const float* W; unsigned char* d; int K;
    if      (bb < 512)  { W = Wq;  d = dst;              K = 512; }
    else if (bb < 1024) { W = Wk;  d = dst + 1048576u;   K = 512; bb -= 512; }
    else if (bb < 1536) { W = Wv;  d = dst + 2097152u;   K = 512; bb -= 1024; }
    else if (bb < 2048) { W = Wo;  d = dst + 3145728u;   K = 512; bb -= 1536; }
    else                { W = Wi2; d = dst + 4194304u;   K = 128; bb -= 2048; }
    int NK = (K == 512) ? 262144 : 65536;
    int S = K >> 5;
    int idx = bb * 256 + threadIdx.x;
    int halfK = K >> 1;
    int n = idx / halfK;
    int k = (idx - n * halfK) * 2;
    float x0 = W[(size_t)n * K + k];
    float x1 = W[(size_t)n * K + k + 1];
    float lx, ly;
    uint32_t hp = pack_hi(x0, x1, lx, ly);
    uint32_t lp = pack_lo(lx, ly);
    int nt = n >> 7, rr = n & 127, st = k >> 5, kb = (k & 31) * 2;
    size_t blk = ((size_t)nt * S + st) * 8192 + swzoff(rr, kb);
    *(uint32_t*)(d + blk)                  = hp;
    *(uint32_t*)(d + (size_t)NK * 2 + blk) = lp;
}

// ===================== input activation pre-split ==================================
__global__ __launch_bounds__(256) void aconv_kernel(
    const float* __restrict__ q, const float* __restrict__ k, const float* __restrict__ v)
{
    const float* src = blockIdx.y == 0 ? q : blockIdx.y == 1 ? k : v;
    char* dst = (char*)g_Ain + (size_t)blockIdx.y * 16777216u;
    size_t e = ((size_t)blockIdx.x * 256 + threadIdx.x) * 4;
    float4 x = *(const float4*)(src + e);
    float l0, l1, l2, l3;
    uint2 hp; hp.x = pack_hi(x.x, x.y, l0, l1); hp.y = pack_hi(x.z, x.w, l2, l3);
    uint2 lp; lp.x = pack_lo(l0, l1);           lp.y = pack_lo(l2, l3);
    int r = (int)(e >> 9), kk = (int)(e & 511);
    int mt = r >> 7, rr = r & 127, st = kk >> 5, kb = (kk & 31) * 2;
    size_t blk = ((size_t)mt * 16 + st) * 8192 + swzoff(rr, kb);
    *(uint2*)(dst + blk)            = hp;
    *(uint2*)(dst + 8388608u + blk) = lp;
}

// ===================== unified pre-packed GEMM (3-deep bulk pipeline) ==============
#define PGB 32768
#define PG_SMEM (3*PGB + 64)

__global__ __launch_bounds__(256, 2) void pgemm_kernel(
    const char* __restrict__ Ab0, long Apl, long Az,
    const char* __restrict__ Bb0, long Bpl, long Bz,
    int K, int mode0,
    const float* __restrict__ b0, const float* __restrict__ b1, const float* __restrict__ b2,
    float* __restrict__ C, const float* __restrict__ scale)
{
    extern __shared__ char sm[];
    const uint32_t sbase = smem_to_u32(sm);
    const uint32_t mbb = sbase + 3 * PGB;
    const int tid = threadIdx.x, wid = tid >> 5, lane = tid & 31;
    const int bx = blockIdx.x, by = blockIdx.y, z = blockIdx.z;
    const int mode = mode0 + z;
    const char* Ab = Ab0 + (size_t)z * Az;
    const char* Bb = Bb0 + (size_t)z * Bz;
    const float* bias = (z == 0) ? b0 : (z == 1) ? b1 : b2;
    const int S = K >> 5;
    const int bm = by * 128, bn = bx * 128;

    if (tid == 0) { MBARRIER_INIT(mbb, 1); MBARRIER_INIT(mbb + 8, 1); MBARRIER_INIT(mbb + 16, 1); }
    __syncthreads();

    float acc[16][4];
#pragma unroll
    for (int i = 0; i < 16; i++)
#pragma unroll
        for (int j = 0; j < 4; j++) acc[i][j] = 0.f;

    auto issue = [&](int s) {
        int buf = s % 3;
        uint32_t mb = mbb + buf * 8;
        uint32_t d = sbase + buf * PGB;
        MBARRIER_EXPECT_TX(mb, 32768);
        const char* As = Ab + (((size_t)by * S + s) << 13);
        const char* Bs = Bb + (((size_t)bx * S + s) << 13);
        BULK_G2S(d,         As,       8192, mb);
        BULK_G2S(d + 8192,  As + Apl, 8192, mb);
        BULK_G2S(d + 16384, Bs,       8192, mb);
        BULK_G2S(d + 24576, Bs + Bpl, 8192, mb);
    };

    const int wm = (wid >> 2) * 64, wn = (wid & 3) * 32;
    const int boff_n = ((lane >> 4) << 3) + (lane & 7);

    auto compute = [&](int buf) {
        uint32_t Ahi = sbase + buf * PGB;
        uint32_t Bhi = Ahi + 16384;
#pragma unroll
        for (int kh = 0; kh < 2; kh++) {
            const int qa = (kh * 2 + (lane >> 4)) << 4;
            const int qb = (kh * 2 + ((lane >> 3) & 1)) << 4;
            uint32_t bh[8], bl[8], a[16];
#pragma unroll
            for (int nf2 = 0; nf2 < 2; nf2++) {
                int rb = wn + nf2 * 16 + boff_n;
                uint32_t baddr = Bhi + swzoff(rb, qb);
                ldsm4(bh + nf2 * 4, baddr);
                ldsm4(bl + nf2 * 4, baddr + 8192);
            }
#pragma unroll
            for (int mf = 0; mf < 4; mf++) {
                int ra = wm + mf * 16 + (lane & 15);
                ldsm4(a + mf * 4, Ahi + swzoff(ra, qa));
            }
#pragma unroll
            for (int mf = 0; mf < 4; mf++)
#pragma unroll
                for (int nf = 0; nf < 4; nf++)
                    mma16816(acc[mf * 4 + nf], a + mf * 4, bh + nf * 2);
#pragma unroll
            for (int mf = 0; mf < 4; mf++)
#pragma unroll
                for (int nf = 0; nf < 4; nf++)
                    mma16816(acc[mf * 4 + nf], a + mf * 4, bl + nf * 2);
#pragma unroll
            for (int mf = 0; mf < 4; mf++) {
                int ra = wm + mf * 16 + (lane & 15);
                ldsm4(a + mf * 4, Ahi + 8192 + swzoff(ra, qa));
            }
#pragma unroll
            for (int mf = 0; mf < 4; mf++)
#pragma unroll
                for (int nf = 0; nf < 4; nf++)
                    mma16816(acc[mf * 4 + nf], a + mf * 4, bh + nf * 2);
        }
    };

    if (tid == 0) { issue(0); if (S > 1) issue(1); }
    for (int s = 0; s < S; s++) {
        if (s + 2 < S && tid == 0) issue(s + 2);
        MBARRIER_WAIT_PARITY(mbb + (s % 3) * 8, (s / 3) & 1);
        compute(s % 3);
        __syncthreads();
    }

    const float isc = (mode == 3) ? scale[0] : 0.f;
#pragma unroll
    for (int mf = 0; mf < 4; mf++) {
#pragma unroll
        for (int nf = 0; nf < 4; nf++) {
            float* cc = acc[mf * 4 + nf];
            int col = bn + wn + nf * 8 + (lane & 3) * 2;
            float bv0 = bias[col], bv1 = bias[col + 1];
#pragma unroll
            for (int rp = 0; rp < 2; rp++) {
                int m = bm + wm + mf * 16 + (lane >> 2) + rp * 8;
                float v0 = cc[rp * 2 + 0] + bv0;
                float v1 = cc[rp * 2 + 1] + bv1;
                if (mode == 0) {
                    *(float2*)(C + (size_t)m * DM + col) = make_float2(v0, v1);
                } else if (mode == 3) {
                    const float* ad = g_X + (size_t)m * DM + col;
                    *(float2*)(g_Y + (size_t)m * DM + col) =
                        make_float2(ad[0] + isc * v0, ad[1] + isc * v1);
                } else if (mode == 4 || mode == 5) {
                    if (mode == 4) { v0 *= 0.125f; v1 *= 0.125f; }
                    int bb = m >> 9, si = m & 511, hh = col >> 6, d = col & 63;
                    int bh_ = bb * 8 + hh, mt = si >> 7, rr = si & 127;
                    int st = d >> 5, kb = (d & 31) * 2;
                    size_t blk = (((size_t)(bh_ * 4 + mt) * 2 + st) << 13) + swzoff(rr, kb);
                    char* base = (mode == 4) ? (char*)g_Qb : (char*)g_Kb;
                    float l0, l1;
                    uint32_t hp = pack_hi(v0, v1, l0, l1);
                    uint32_t lp = pack_lo(l0, l1);
                    *(uint32_t*)(base + blk)            = hp;
                    *(uint32_t*)(base + 8388608u + blk) = lp;
                } else {
                    int bb = m >> 9, si = m & 511, hh = col >> 6, d = col & 63;
                    int bh_ = bb * 8 + hh, st = si >> 5, kb = (si & 31) * 2;
                    size_t blk = ((size_t)(bh_ * 16 + st)) * 4096;
                    char* base = (char*)g_Vtb;
                    __nv_bfloat16 h0 = __float2bfloat16(v0);
                    __nv_bfloat16 h1 = __float2bfloat16(v1);
                    int o0 = swzoff(d, kb), o1 = swzoff(d + 1, kb);
                    *(__nv_bfloat16*)(base + blk + o0) = h0;
                    *(__nv_bfloat16*)(base + 8388608u + blk + o0) =
                        __float2bfloat16(v0 - __bfloat162float(h0));
                    *(__nv_bfloat16*)(base + blk + o1) = h1;
                    *(__nv_bfloat16*)(base + 8388608u + blk + o1) =
                        __float2bfloat16(v1 - __bfloat162float(h1));
                }
            }
        }
    }
}

// ===================== fused attention: QK^T -> softmax/temporal -> AV =============
// One CTA per (64-row chunk c, bh). 512 threads. S and A live in smem only.
// smem: S/A 131072 | Q 16384 | K 2x32768 | V 2x8192 | mbarriers
#define FA_SQ   131072
#define FA_K    147456
#define FA_V    212992
#define FA_MB   229376
#define FA_SMEM 229440

__global__ __launch_bounds__(512, 1) void fattn_kernel(const float* __restrict__ gammas)
{
    extern __shared__ char sm[];
    const uint32_t sbase = smem_to_u32(sm);
    const uint32_t mbK = sbase + FA_MB, mbV = sbase + FA_MB + 16;
    const int c = blockIdx.x, bh = blockIdx.y;
    const int b = bh >> 3, h = bh & 7;
    const int tid = threadIdx.x, wid = tid >> 5, lane = tid & 31;
    const int Ti = c >> 1;                    // last 128-col tile needed
    const int nst = 4 * (Ti + 1);             // V s-tiles (32 each)

    if (tid == 0) {
        MBARRIER_INIT(mbK, 1); MBARRIER_INIT(mbK + 8, 1);
        MBARRIER_INIT(mbV, 1); MBARRIER_INIT(mbV + 8, 1);
        asm volatile("fence.proxy.async.shared::cta;" ::: "memory");
        // K tile 0 + Q chunk on mbK[0]
        MBARRIER_EXPECT_TX(mbK, 49152);
#pragma unroll
        for (int p = 0; p < 2; p++)
#pragma unroll
            for (int st = 0; st < 2; st++) {
                const char* ks = (const char*)g_Kb + (size_t)p * 8388608u +
                                 (((size_t)(bh * 4 + 0) * 2 + st) << 13);
                BULK_G2S(sbase + FA_K + p * 16384 + st * 8192, ks, 8192, mbK);
                const char* qs = (const char*)g_Qb + (size_t)p * 8388608u +
                                 (((size_t)(bh * 4 + (c >> 1)) * 2 + st) << 13) + (c & 1) * 4096;
                BULK_G2S(sbase + FA_SQ + p * 8192 + st * 4096, qs, 4096, mbK);
            }
        if (Ti > 0) {
            MBARRIER_EXPECT_TX(mbK + 8, 32768);
#pragma unroll
            for (int p = 0; p < 2; p++)
#pragma unroll
                for (int st = 0; st < 2; st++) {
                    const char* ks = (const char*)g_Kb + (size_t)p * 8388608u +
                                     (((size_t)(bh * 4 + 1) * 2 + st) << 13);
                    BULK_G2S(sbase + FA_K + 32768 + p * 16384 + st * 8192, ks, 8192, mbK + 8);
                }
        }
        // V tiles 0,1
#pragma unroll
        for (int sv = 0; sv < 2; sv++) {
            MBARRIER_EXPECT_TX(mbV + sv * 8, 8192);
#pragma unroll
            for (int p = 0; p < 2; p++) {
                const char* vs = (const char*)g_Vtb + (size_t)p * 8388608u +
                                 (((size_t)(bh * 16 + sv)) << 12);
                BULK_G2S(sbase + FA_V + sv * 8192 + p * 4096, vs, 4096, mbV + sv * 8);
            }
        }
    }
    __syncthreads();

    // ---------- Phase 1: QK^T -> S (fp32, smem, chunk-swizzled rows) ----------
    {
        const int wm = (wid >> 2) * 16, wn = (wid & 3) * 32;
        const int boff_n = ((lane >> 4) << 3) + (lane & 7);
        for (int nt = 0; nt <= Ti; nt++) {
            MBARRIER_WAIT_PARITY(mbK + (nt & 1) * 8, (nt >> 1) & 1);
            uint32_t Kbuf = sbase + FA_K + (nt & 1) * 32768;
            float acc[4][4];
#pragma unroll
            for (int i = 0; i < 4; i++)
#pragma unroll
                for (int j = 0; j < 4; j++) acc[i][j] = 0.f;
#pragma unroll
            for (int st = 0; st < 2; st++) {
#pragma unroll
                for (int kh = 0; kh < 2; kh++) {
                    const int qa = (kh * 2 + (lane >> 4)) << 4;
                    const int qb = (kh * 2 + ((lane >> 3) & 1)) << 4;
                    uint32_t ah[4], al[4], bh_[8], bl_[8];
                    int ra = wm + (lane & 15);
                    uint32_t aaddr = sbase + FA_SQ + st * 4096 + swzoff(ra, qa);
                    ldsm4(ah, aaddr);
                    ldsm4(al, aaddr + 8192);
#pragma unroll
                    for (int nf2 = 0; nf2 < 2; nf2++) {
                        int rb = wn + nf2 * 16 + boff_n;
                        uint32_t baddr = Kbuf + st * 8192 + swzoff(rb, qb);
                        ldsm4(bh_ + nf2 * 4, baddr);
                        ldsm4(bl_ + nf2 * 4, baddr + 16384);
                    }
#pragma unroll
                    for (int nf = 0; nf < 4; nf++) mma16816(acc[nf], ah, bh_ + nf * 2);
#pragma unroll
                    for (int nf = 0; nf < 4; nf++) mma16816(acc[nf], ah, bl_ + nf * 2);
#pragma unroll
                    for (int nf = 0; nf < 4; nf++) mma16816(acc[nf], al, bh_ + nf * 2);
                }
            }
            // store S tile to smem
#pragma unroll
            for (int nf = 0; nf < 4; nf++) {
                int col = 128 * nt + wn + nf * 8 + (lane & 3) * 2;
                int q = col >> 2, sub = (col & 3) * 4;
#pragma unroll
                for (int rp = 0; rp < 2; rp++) {
                    int r = wm + (lane >> 2) + rp * 8;
                    uint32_t addr = sbase + r * 2048 + ((q ^ ((r & 7) << 3)) << 4) + sub;
                    float2 v2 = make_float2(acc[nf][rp * 2], acc[nf][rp * 2 + 1]);
                    asm volatile("st.shared.v2.f32 [%0], {%1, %2};" :: "r"(addr), "f"(v2.x), "f"(v2.y));
                }
            }
            __syncthreads();
            if (tid == 0 && nt + 2 <= Ti) {
                int buf = nt & 1;
                MBARRIER_EXPECT_TX(mbK + buf * 8, 32768);
#pragma unroll
                for (int p = 0; p < 2; p++)
#pragma unroll
                    for (int st = 0; st < 2; st++) {
                        const char* ks = (const char*)g_Kb + (size_t)p * 8388608u +
                                         (((size_t)(bh * 4 + nt + 2) * 2 + st) << 13);
                        BULK_G2S(sbase + FA_K + buf * 32768 + p * 16384 + st * 8192, ks, 8192, mbK + buf * 8);
                    }
            }
        }
    }

    // ---------- Phase 2: row pass (softmax/scan/temporal) -> A bf16 hi/lo in place ---
    {
        float gv = gammas[h];
        float gam = -(fmaxf(gv, 0.f) + log1pf(__expf(-fabsf(gv))));
        for (int rl = 0; rl < 4; rl++) {
            int il = wid * 4 + rl;
            int i = 64 * c + il;
            int rx = (il & 7) << 3;
            if (i == 0) {
                // zero A row 0, tile 0
                uint2 zz = make_uint2(0u, 0u);
                int q64 = lane >> 1, sub = (lane & 1) * 8;
                uint32_t ad = sbase + ((q64 ^ rx) << 4) + sub;
                asm volatile("st.shared.v2.u32 [%0], {%1, %2};" :: "r"(ad), "r"(zz.x), "r"(zz.y));
                asm volatile("st.shared.v2.u32 [%0], {%1, %2};" :: "r"(ad + 1024), "r"(zz.x), "r"(zz.y));
                continue;
            }
            float sc[4][4], e[4][4], ls[4];
#pragma unroll
            for (int t = 0; t < 4; t++) {
                if (t > Ti) { ls[t] = 0.f; continue; }
                int ch = lane + 32 * t;
                uint32_t ad = sbase + il * 2048 + (((ch ^ rx) & 127) << 4);
                float4 sv;
                asm volatile("ld.shared.v4.f32 {%0,%1,%2,%3}, [%4];"
                    : "=f"(sv.x), "=f"(sv.y), "=f"(sv.z), "=f"(sv.w) : "r"(ad));
                int j0 = 4 * ch;
                sc[t][0] = (j0 + 0 < i) ? sv.x : NEG_INF;
                sc[t][1] = (j0 + 1 < i) ? sv.y : NEG_INF;
                sc[t][2] = (j0 + 2 < i) ? sv.z : NEG_INF;
                sc[t][3] = (j0 + 3 < i) ? sv.w : NEG_INF;
            }
            float m = NEG_INF;
#pragma unroll
            for (int t = 0; t < 4; t++) {
                if (t > Ti) break;
#pragma unroll
                for (int l = 0; l < 4; l++) m = fmaxf(m, sc[t][l]);
            }
#pragma unroll
            for (int off = 16; off; off >>= 1)
                m = fmaxf(m, __shfl_xor_sync(0xffffffffu, m, off));
#pragma unroll
            for (int t = 0; t < 4; t++) {
                if (t > Ti) break;
                ls[t] = 0.f;
#pragma unroll
                for (int l = 0; l < 4; l++) { e[t][l] = __expf(sc[t][l] - m); ls[t] += e[t][l]; }
            }
            float excl[4], tot[4];
#pragma unroll
            for (int t = 0; t < 4; t++) {
                if (t > Ti) break;
                float x = ls[t];
#pragma unroll
                for (int off = 1; off < 32; off <<= 1) {
                    float y = __shfl_up_sync(0xffffffffu, x, off);
                    if (lane >= off) x += y;
                }
                excl[t] = x - ls[t];
                tot[t]  = __shfl_sync(0xffffffffu, x, 31);
            }
            float baseA[4], T = 0.f;
#pragma unroll
            for (int t = 0; t < 4; t++) {
                if (t > Ti) break;
                baseA[t] = T; T += tot[t];
            }
            float invT = 1.f / T;
#pragma unroll
            for (int t = 0; t < 4; t++) {
                if (t > Ti) break;
                float run = baseA[t] + excl[t];
#pragma unroll
                for (int l = 0; l < 4; l++) {
                    run += e[t][l];
                    int j = 4 * lane + 128 * t + l;
                    float suf  = fmaxf(T - run, 0.f);
                    float dist = sqrtf(fmaxf(suf * invT * (float)(i - j), 0.f));
                    float tmp  = __expf(dist * gam);
                    tmp = fminf(fmaxf(tmp, 1e-5f), 1e5f);
                    sc[t][l] = (j < i) ? sc[t][l] * tmp : NEG_INF;
                }
            }
            float m2 = NEG_INF;
#pragma unroll
            for (int t = 0; t < 4; t++) {
                if (t > Ti) break;
#pragma unroll
                for (int l = 0; l < 4; l++) m2 = fmaxf(m2, sc[t][l]);
            }
#pragma unroll
            for (int off = 16; off; off >>= 1)
                m2 = fmaxf(m2, __shfl_xor_sync(0xffffffffu, m2, off));
            float Z = 0.f;
#pragma unroll
            for (int t = 0; t < 4; t++) {
                if (t > Ti) break;
#pragma unroll
                for (int l = 0; l < 4; l++) { e[t][l] = __expf(sc[t][l] - m2); Z += e[t][l]; }
            }
#pragma unroll
            for (int off = 16; off; off >>= 1)
                Z += __shfl_xor_sync(0xffffffffu, Z, off);
            float invZ = 1.f / Z;
#pragma unroll
            for (int t = 0; t < 4; t++) {
                if (t > Ti) break;
                float a0 = e[t][0] * invZ, a1 = e[t][1] * invZ;
                float a2 = e[t][2] * invZ, a3 = e[t][3] * invZ;
                float l0, l1, l2, l3;
                uint2 hp; hp.x = pack_hi(a0, a1, l0, l1); hp.y = pack_hi(a2, a3, l2, l3);
                uint2 lp; lp.x = pack_lo(l0, l1);         lp.y = pack_lo(l2, l3);
                int ch = lane + 32 * t;
                int q64 = ch >> 1, sub = (ch & 1) * 8;
                uint32_t ad = sbase + il * 2048 + (((q64 ^ rx) & 63) << 4) + sub;
                asm volatile("st.shared.v2.u32 [%0], {%1, %2};" :: "r"(ad), "r"(hp.x), "r"(hp.y));
                asm volatile("st.shared.v2.u32 [%0], {%1, %2};" :: "r"(ad + 1024), "r"(lp.x), "r"(lp.y));
            }
        }
    }
    __syncthreads();

    // ---------- Phase 3: AV -> g_X ----------
    {
        const int wm = (wid >> 2) * 16, wn = (wid & 3) * 16;
        const int boff_n = ((lane >> 4) << 3) + (lane & 7);
        float acc[2][4];
#pragma unroll
        for (int i = 0; i < 2; i++)
#pragma unroll
            for (int j = 0; j < 4; j++) acc[i][j] = 0.f;

        for (int sv = 0; sv < nst; sv++) {
            MBARRIER_WAIT_PARITY(mbV + (sv & 1) * 8, (sv >> 1) & 1);
            uint32_t Vbuf = sbase + FA_V + (sv & 1) * 8192;
#pragma unroll
            for (int kh = 0; kh < 2; kh++) {
                const int qa = sv * 4 + kh * 2 + (lane >> 4);
                const int qb = (kh * 2 + ((lane >> 3) & 1)) << 4;
                uint32_t ah[4], al[4], vh[4], vl[4];
                int ra = wm + (lane & 15);
                uint32_t aaddr = sbase + ra * 2048 + (((qa ^ ((ra & 7) << 3)) & 63) << 4);
                ldsm4(ah, aaddr);
                ldsm4(al, aaddr + 1024);
                int rb = wn + boff_n;
                uint32_t vaddr = Vbuf + swzoff(rb, qb);
                ldsm4(vh, vaddr);
                ldsm4(vl, vaddr + 4096);
#pragma unroll
                for (int nf = 0; nf < 2; nf++) mma16816(acc[nf], ah, vh + nf * 2);
#pragma unroll
                for (int nf = 0; nf < 2; nf++) mma16816(acc[nf], ah, vl + nf * 2);
#pragma unroll
                for (int nf = 0; nf < 2; nf++) mma16816(acc[nf], al, vh + nf * 2);
            }
            __syncthreads();
            if (tid == 0 && sv + 2 < nst) {
                int buf = sv & 1;
                MBARRIER_EXPECT_TX(mbV + buf * 8, 8192);
#pragma unroll
                for (int p = 0; p < 2; p++) {
                    const char* vs = (const char*)g_Vtb + (size_t)p * 8388608u +
                                     (((size_t)(bh * 16 + sv + 2)) << 12);
                    BULK_G2S(sbase + FA_V + buf * 8192 + p * 4096, vs, 4096, mbV + buf * 8);
                }
            }
        }
#pragma unroll
        for (int nf = 0; nf < 2; nf++) {
            int col = wn + nf * 8 + (lane & 3) * 2;
#pragma unroll
            for (int rp = 0; rp < 2; rp++) {
                int row = 64 * c + wm + (lane >> 2) + rp * 8;
                *(float2*)(g_X + ((size_t)(b * 512 + row)) * 512 + h * 64 + col) =
                    make_float2(acc[nf][rp * 2], acc[nf][rp * 2 + 1]);
            }
        }
    }
}

// ===================== parallel norm01 stats =====================
__global__ __launch_bounds__(256) void stats_kernel(
    const int* __restrict__ sgap, const int* __restrict__ pcount)
{
    __shared__ long long sh[32];
    int idx = blockIdx.x * 256 + threadIdx.x;
    long long a = sgap[idx], b = pcount[idx];
    long long s0 = a, q0 = a * a, s1 = b, q1 = b * b;
#pragma unroll
    for (int off = 16; off; off >>= 1) {
        s0 += __shfl_xor_sync(0xffffffffu, s0, off);
        q0 += __shfl_xor_sync(0xffffffffu, q0, off);
        s1 += __shfl_xor_sync(0xffffffffu, s1, off);
        q1 += __shfl_xor_sync(0xffffffffu, q1, off);
    }
    int wd = threadIdx.x >> 5, ln = threadIdx.x & 31;
    if (ln == 0) { sh[wd] = s0; sh[8+wd] = q0; sh[16+wd] = s1; sh[24+wd] = q1; }
    __syncthreads();
    if (threadIdx.x == 0) {
        long long S0=0,Q0=0,S1=0,Q1=0;
        for (int i = 0; i < 8; i++) { S0+=sh[i]; Q0+=sh[8+i]; S1+=sh[16+i]; Q1+=sh[24+i]; }
        atomicAdd(&g_sacc[0], (unsigned long long)S0);
        atomicAdd(&g_sacc[1], (unsigned long long)Q0);
        atomicAdd(&g_sacc[2], (unsigned long long)S1);
        atomicAdd(&g_sacc[3], (unsigned long long)Q1);
    }
}

// ===================== interference hidden layer -> bf16 blocks ===================
__global__ __launch_bounds__(256) void hidden_kernel(
    const int* __restrict__ sgap, const int* __restrict__ pcount,
    const float* __restrict__ Wi1, const float* __restrict__ bi1)
{
    float n = (float)MTOT;
    float S0 = (float)(long long)g_sacc[0], Q0 = (float)(long long)g_sacc[1];
    float S1 = (float)(long long)g_sacc[2], Q1 = (float)(long long)g_sacc[3];
    float m0 = S0 / n, m1 = S1 / n;
    float v0 = (Q0 - n*m0*m0) / (n - 1.f);
    float v1 = (Q1 - n*m1*m1) / (n - 1.f);
    float inv0 = 1.f / (sqrtf(fmaxf(v0, 0.f)) + 1e-6f);
    float inv1 = 1.f / (sqrtf(fmaxf(v1, 0.f)) + 1e-6f);

    int idx = blockIdx.x * 256 + threadIdx.x;
    int r = idx >> 6, c2 = (idx & 63) * 2;
    float ii0 = 0.5f * (tanhf(((float)sgap[r]   - m0) * inv0) + 1.f);
    float ii1 = 0.5f * (tanhf(((float)pcount[r] - m1) * inv1) + 1.f);
    float h0 = fmaxf(ii0 * Wi1[2*c2+0] + ii1 * Wi1[2*c2+1] + bi1[c2],   0.f);
    float h1 = fmaxf(ii0 * Wi1[2*c2+2] + ii1 * Wi1[2*c2+3] + bi1[c2+1], 0.f);
    float l0, l1;
    uint32_t hp = pack_hi(h0, h1, l0, l1);
    uint32_t lp = pack_lo(l0, l1);
    int mt = r >> 7, rr = r & 127, st = c2 >> 5, kb = (c2 & 31) * 2;
    size_t blk = ((size_t)mt * 4 + st) * 8192 + swzoff(rr, kb);
    char* base = (char*)g_Hb;
    *(uint32_t*)(base + blk)            = hp;
    *(uint32_t*)(base + 2097152u + blk) = lp;
}

// ===================== LayerNorm + pack to bf16 blocks ============================
__global__ __launch_bounds__(256) void ln_pack_kernel(
    const float* __restrict__ gw, const float* __restrict__ bw)
{
    int r = blockIdx.x * 8 + (threadIdx.x >> 5);
    int lane = threadIdx.x & 31;
    const float4* row = (const float4*)(g_Y + (size_t)r * DM);
    float4 xv[4];
    float s = 0.f, q = 0.f;
#pragma unroll
    for (int c = 0; c < 4; c++) {
        xv[c] = row[lane + 32 * c];
        s += xv[c].x + xv[c].y + xv[c].z + xv[c].w;
        q += xv[c].x*xv[c].x + xv[c].y*xv[c].y + xv[c].z*xv[c].z + xv[c].w*xv[c].w;
    }
#pragma unroll
    for (int off = 16; off; off >>= 1) {
        s += __shfl_xor_sync(0xffffffffu, s, off);
        q += __shfl_xor_sync(0xffffffffu, q, off);
    }
    float mu   = s * (1.f / 512.f);
    float rstd = rsqrtf(q * (1.f / 512.f) - mu * mu + 1e-5f);
    int mt = r >> 7, rr = r & 127;
    char* base = (char*)g_Yb;
#pragma unroll
    for (int c = 0; c < 4; c++) {
        float4 g4 = ((const float4*)gw)[lane + 32 * c];
        float4 b4 = ((const float4*)bw)[lane + 32 * c];
        float n0 = (xv[c].x - mu) * rstd * g4.x + b4.x;
        float n1 = (xv[c].y - mu) * rstd * g4.y + b4.y;
        float n2 = (xv[c].z - mu) * rstd * g4.z + b4.z;
        float n3 = (xv[c].w - mu) * rstd * g4.w + b4.w;
        float l0, l1, l2, l3;
        uint2 hp; hp.x = pack_hi(n0, n1, l0, l1); hp.y = pack_hi(n2, n3, l2, l3);
        uint2 lp; lp.x = pack_lo(l0, l1);         lp.y = pack_lo(l2, l3);
        int st = (lane >> 3) + 4 * c, kb = (lane & 7) * 8;
        size_t blk = ((size_t)mt * 16 + st) * 8192 + swzoff(rr, kb);
        *(uint2*)(base + blk)            = hp;
        *(uint2*)(base + 8388608u + blk) = lp;
    }
}

// ===================== launcher =====================
extern "C" void kernel_launch(void* const* d_in, const int* in_sizes, int n_in,
                              void* d_out, int out_size)
{
    const float* q      = (const float*)d_in[0];
    const float* k      = (const float*)d_in[1];
    const float* v      = (const float*)d_in[2];
    const int*   sgap   = (const int*)d_in[3];
    const int*   pcount = (const int*)d_in[4];
    const float* Wq = (const float*)d_in[5];  const float* bq = (const float*)d_in[6];
    const float* Wk = (const float*)d_in[7];  const float* bk = (const float*)d_in[8];
    const float* Wv = (const float*)d_in[9];  const float* bv = (const float*)d_in[10];
    const float* Wo = (const float*)d_in[11]; const float* bo = (const float*)d_in[12];
    const float* gammas = (const float*)d_in[13];
    const float* ln_g = (const float*)d_in[14]; const float* ln_b = (const float*)d_in[15];
    const float* Wi1 = (const float*)d_in[16];  const float* bi1 = (const float*)d_in[17];
    const float* Wi2 = (const float*)d_in[18];  const float* bi2 = (const float*)d_in[19];
    const float* iscale = (const float*)d_in[20];
    float* out = (float*)d_out;

    char *Ain, *Yb, *Hb;
    unsigned char* Wpk;
    cudaGetSymbolAddress((void**)&Ain, g_Ain);
    cudaGetSymbolAddress((void**)&Yb,  g_Yb);
    cudaGetSymbolAddress((void**)&Hb,  g_Hb);
    cudaGetSymbolAddress((void**)&Wpk, g_Wpk);

    cudaFuncSetAttribute(pgemm_kernel, cudaFuncAttributeMaxDynamicSharedMemorySize, PG_SMEM);
    cudaFuncSetAttribute(fattn_kernel, cudaFuncAttributeMaxDynamicSharedMemorySize, FA_SMEM);

    wconv_all<<<2176, 256>>>(Wq, Wk, Wv, Wo, Wi2, Wpk);
    aconv_kernel<<<dim3(4096, 3), 256>>>(q, k, v);
    stats_kernel<<<32, 256>>>(sgap, pcount);

    pgemm_kernel<<<dim3(4, 64, 3), 256, PG_SMEM>>>(
        Ain, 8388608L, 16777216L, (const char*)Wpk, 524288L, 1048576L,
        512, 4, bq, bk, bv, nullptr, nullptr);

    fattn_kernel<<<dim3(8, 128), 512, FA_SMEM>>>(gammas);

    hidden_kernel<<<2048, 256>>>(sgap, pcount, Wi1, bi1);
    pgemm_kernel<<<dim3(4, 64, 1), 256, PG_SMEM>>>(
        Hb, 2097152L, 0L, (const char*)Wpk + 4194304u, 131072L, 0L,
        128, 3, bi2, nullptr, nullptr, nullptr, iscale);

    ln_pack_kernel<<<1024, 256>>>(ln_g, ln_b);

    pgemm_kernel<<<dim3(4, 64, 1), 256, PG_SMEM>>>(
        Yb, 8388608L, 0L, (const char*)Wpk + 3145728u, 524288L, 0L,
        512, 0, bo, nullptr, nullptr, out, nullptr);
}

// round 11
// speedup vs baseline: 1.2483x; 1.2483x over previous
#include <cuda_runtime.h>
#include <cuda_bf16.h>
#include <math.h>
#include <cstdint>

#define BSZ 16
#define SEQ 512
#define DM  512
#define NH  8
#define DKH 64
#define MTOT (BSZ*SEQ)
#define NEG_INF (__int_as_float(0xff800000))
#define QKVPLN 4194304u
#define APLN 33554432u

// ===================== scratch =====================
__device__ __nv_bfloat16 g_Ain[3u*2u*4194304u];
__device__ __nv_bfloat16 g_Qb [2*QKVPLN];
__device__ __nv_bfloat16 g_Kb [2*QKVPLN];
__device__ __nv_bfloat16 g_Vtb[2*QKVPLN];
__device__ float         g_S  [APLN];
__device__ __nv_bfloat16 g_A  [2*APLN];
__device__ float g_X [MTOT*DM];
__device__ float g_Y [MTOT*DM];
__device__ __nv_bfloat16 g_Yb[2u*4194304u];
__device__ __nv_bfloat16 g_Hb[2u*1048576u];
__device__ unsigned long long g_sacc[4];
__device__ unsigned char g_Wpk[5u*1024u*1024u];

// ===================== asm helpers =====================
__device__ __forceinline__ uint32_t smem_to_u32(const void* p) {
    uint32_t a;
    asm("{ .reg .u64 t; cvta.to.shared.u64 t, %1; cvt.u32.u64 %0, t; }" : "=r"(a) : "l"(p));
    return a;
}
__device__ __forceinline__ void ldsm4(uint32_t* r, uint32_t addr) {
    asm volatile("ldmatrix.sync.aligned.m8n8.x4.shared.b16 {%0,%1,%2,%3}, [%4];"
        : "=r"(r[0]), "=r"(r[1]), "=r"(r[2]), "=r"(r[3]) : "r"(addr));
}
__device__ __forceinline__ void mma16816(float* c, const uint32_t* a, const uint32_t* b) {
    asm volatile("mma.sync.aligned.m16n8k16.row.col.f32.bf16.bf16.f32 "
        "{%0,%1,%2,%3}, {%4,%5,%6,%7}, {%8,%9}, {%0,%1,%2,%3};"
        : "+f"(c[0]), "+f"(c[1]), "+f"(c[2]), "+f"(c[3])
        : "r"(a[0]), "r"(a[1]), "r"(a[2]), "r"(a[3]), "r"(b[0]), "r"(b[1]));
}
__device__ __forceinline__ uint32_t pack_hi(float x, float y, float& lx, float& ly) {
    __nv_bfloat162 h = __floats2bfloat162_rn(x, y);
    lx = x - __bfloat162float(h.x);
    ly = y - __bfloat162float(h.y);
    return *reinterpret_cast<uint32_t*>(&h);
}
__device__ __forceinline__ uint32_t pack_lo(float lx, float ly) {
    __nv_bfloat162 l = __floats2bfloat162_rn(lx, ly);
    return *reinterpret_cast<uint32_t*>(&l);
}
__device__ __forceinline__ int swzoff(int r, int kb) {
    return r * 64 + ((((kb >> 4) ^ ((r >> 1) & 3)) << 4)) + (kb & 15);
}
#define BULK_G2S(dst, src, bytes, mbar) \
    asm volatile("cp.async.bulk.shared::cluster.global.mbarrier::complete_tx::bytes [%0], [%1], %2, [%3];" \
        :: "r"(dst), "l"(src), "r"(bytes), "r"(mbar) : "memory")
#define MBARRIER_INIT(mbar, cnt) \
    asm volatile("mbarrier.init.shared.b64 [%0], %1;" :: "r"((uint32_t)(mbar)), "r"((uint32_t)(cnt)) : "memory")
#define MBARRIER_EXPECT_TX(mbar, bytes) \
    asm volatile("mbarrier.arrive.expect_tx.shared.b64 _, [%0], %1;" :: "r"((uint32_t)(mbar)), "r"((uint32_t)(bytes)) : "memory")
#define MBARRIER_WAIT_PARITY(mbar, parity) do { \
    uint32_t _m = (uint32_t)(mbar); uint32_t _p = (uint32_t)(parity); uint32_t _d; \
    asm volatile("{\n\t.reg .pred p;\n\tmbarrier.try_wait.parity.acquire.cta.shared::cta.b64 p, [%1], %2;\n\tselp.b32 %0, 1, 0, p;\n\t}" \
        : "=r"(_d) : "r"(_m), "r"(_p) : "memory"); \
    if (!_d) { \
        asm volatile("{\n\t.reg .pred P1;\n\tWL_%=:\n\tmbarrier.try_wait.parity.acquire.cta.shared::cta.b64 P1, [%0], %1, 0x989680;\n\t@P1 bra.uni WD_%=;\n\tbra.uni WL_%=;\n\tWD_%=:\n\t}" \
            :: "r"(_m), "r"(_p) : "memory"); \
    } } while (0)

// ===================== fused prep: weight pre-split + activation pre-split =========
// blocks [0,2176): weights; [2176,14464): activations
__global__ __launch_bounds__(256) void prep_kernel(
    const float* __restrict__ Wq, const float* __restrict__ Wk,
    const float* __restrict__ Wv, const float* __restrict__ Wo,
    const float* __restrict__ Wi2, unsigned char* __restrict__ wdst,
    const float* __restrict__ q, const float* __restrict__ k, const float* __restrict__ v)
{
    int bb = blockIdx.x;
    if (bb < 2176) {
        if (bb == 0 && threadIdx.x < 4) g_sacc[threadIdx.x] = 0ull;
        const float* W; unsigned char* d; int K;
        if      (bb < 512)  { W = Wq;  d = wdst;              K = 512; }
        else if (bb < 1024) { W = Wk;  d = wdst + 1048576u;   K = 512; bb -= 512; }
        else if (bb < 1536) { W = Wv;  d = wdst + 2097152u;   K = 512; bb -= 1024; }
        else if (bb < 2048) { W = Wo;  d = wdst + 3145728u;   K = 512; bb -= 1536; }
        else                { W = Wi2; d = wdst + 4194304u;   K = 128; bb -= 2048; }
        int NK = (K == 512) ? 262144 : 65536;
        int S = K >> 5;
        int idx = bb * 256 + threadIdx.x;
        int halfK = K >> 1;
        int n = idx / halfK;
        int kk = (idx - n * halfK) * 2;
        float x0 = W[(size_t)n * K + kk];
        float x1 = W[(size_t)n * K + kk + 1];
        float lx, ly;
        uint32_t hp = pack_hi(x0, x1, lx, ly);
        uint32_t lp = pack_lo(lx, ly);
        int nt = n >> 7, rr = n & 127, st = kk >> 5, kb = (kk & 31) * 2;
        size_t blk = ((size_t)nt * S + st) * 8192 + swzoff(rr, kb);
        *(uint32_t*)(d + blk)                  = hp;
        *(uint32_t*)(d + (size_t)NK * 2 + blk) = lp;
    } else {
        int a = bb - 2176;
        int zy = a >> 12, zx = a & 4095;
        const float* src = zy == 0 ? q : zy == 1 ? k : v;
        char* dst = (char*)g_Ain + (size_t)zy * 16777216u;
        size_t e = ((size_t)zx * 256 + threadIdx.x) * 4;
        float4 x = *(const float4*)(src + e);
        float l0, l1, l2, l3;
        uint2 hp; hp.x = pack_hi(x.x, x.y, l0, l1); hp.y = pack_hi(x.z, x.w, l2, l3);
        uint2 lp; lp.x = pack_lo(l0, l1);           lp.y = pack_lo(l2, l3);
        int r = (int)(e >> 9), kk = (int)(e & 511);
        int mt = r >> 7, rr = r & 127, st = kk >> 5, kb = (kk & 31) * 2;
        size_t blk = ((size_t)mt * 16 + st) * 8192 + swzoff(rr, kb);
        *(uint2*)(dst + blk)            = hp;
        *(uint2*)(dst + 8388608u + blk) = lp;
    }
}

// ===================== unified pre-packed GEMM (2-deep bulk pipeline) ==============
#define PGB 32768
#define PG_SMEM (2*PGB + 64)

__global__ __launch_bounds__(256, 2) void pgemm_kernel(
    const char* __restrict__ Ab0, long Apl, long Az,
    const char* __restrict__ Bb0, long Bpl, long Bz,
    int K, int mode0,
    const float* __restrict__ b0, const float* __restrict__ b1, const float* __restrict__ b2,
    float* __restrict__ C, const float* __restrict__ scale)
{
    extern __shared__ char sm[];
    const uint32_t sbase = smem_to_u32(sm);
    const uint32_t mb0 = sbase + 2 * PGB, mb1 = mb0 + 8;
    const int tid = threadIdx.x, wid = tid >> 5, lane = tid & 31;
    const int bx = blockIdx.x, by = blockIdx.y, z = blockIdx.z;
    const int mode = mode0 + z;
    const char* Ab = Ab0 + (size_t)z * Az;
    const char* Bb = Bb0 + (size_t)z * Bz;
    const float* bias = (z == 0) ? b0 : (z == 1) ? b1 : b2;
    const int S = K >> 5;
    const int bm = by * 128, bn = bx * 128;

    if (tid == 0) { MBARRIER_INIT(mb0, 1); MBARRIER_INIT(mb1, 1); }
    __syncthreads();

    float acc[16][4];
#pragma unroll
    for (int i = 0; i < 16; i++)
#pragma unroll
        for (int j = 0; j < 4; j++) acc[i][j] = 0.f;

    auto issue = [&](int s, int buf) {
        uint32_t mb = buf ? mb1 : mb0;
        uint32_t d = sbase + buf * PGB;
        MBARRIER_EXPECT_TX(mb, 32768);
        const char* As = Ab + (((size_t)by * S + s) << 13);
        const char* Bs = Bb + (((size_t)bx * S + s) << 13);
        BULK_G2S(d,         As,       8192, mb);
        BULK_G2S(d + 8192,  As + Apl, 8192, mb);
        BULK_G2S(d + 16384, Bs,       8192, mb);
        BULK_G2S(d + 24576, Bs + Bpl, 8192, mb);
    };

    const int wm = (wid >> 2) * 64, wn = (wid & 3) * 32;
    const int boff_n = ((lane >> 4) << 3) + (lane & 7);

    auto compute = [&](int buf) {
        uint32_t Ahi = sbase + buf * PGB;
        uint32_t Bhi = Ahi + 16384;
#pragma unroll
        for (int kh = 0; kh < 2; kh++) {
            const int qa = (kh * 2 + (lane >> 4)) << 4;
            const int qb = (kh * 2 + ((lane >> 3) & 1)) << 4;
            uint32_t bh[8], bl[8], a[16];
#pragma unroll
            for (int nf2 = 0; nf2 < 2; nf2++) {
                int rb = wn + nf2 * 16 + boff_n;
                uint32_t baddr = Bhi + swzoff(rb, qb);
                ldsm4(bh + nf2 * 4, baddr);
                ldsm4(bl + nf2 * 4, baddr + 8192);
            }
#pragma unroll
            for (int mf = 0; mf < 4; mf++) {
                int ra = wm + mf * 16 + (lane & 15);
                ldsm4(a + mf * 4, Ahi + swzoff(ra, qa));
            }
#pragma unroll
            for (int mf = 0; mf < 4; mf++)
#pragma unroll
                for (int nf = 0; nf < 4; nf++)
                    mma16816(acc[mf * 4 + nf], a + mf * 4, bh + nf * 2);
#pragma unroll
            for (int mf = 0; mf < 4; mf++)
#pragma unroll
                for (int nf = 0; nf < 4; nf++)
                    mma16816(acc[mf * 4 + nf], a + mf * 4, bl + nf * 2);
#pragma unroll
            for (int mf = 0; mf < 4; mf++) {
                int ra = wm + mf * 16 + (lane & 15);
                ldsm4(a + mf * 4, Ahi + 8192 + swzoff(ra, qa));
            }
#pragma unroll
            for (int mf = 0; mf < 4; mf++)
#pragma unroll
                for (int nf = 0; nf < 4; nf++)
                    mma16816(acc[mf * 4 + nf], a + mf * 4, bh + nf * 2);
        }
    };

    if (tid == 0) issue(0, 0);
    for (int s = 0; s < S; s++) {
        if (s + 1 < S && tid == 0) issue(s + 1, (s + 1) & 1);
        MBARRIER_WAIT_PARITY((s & 1) ? mb1 : mb0, (s >> 1) & 1);
        compute(s & 1);
        __syncthreads();
    }

    const float isc = (mode == 3) ? scale[0] : 0.f;
#pragma unroll
    for (int mf = 0; mf < 4; mf++) {
#pragma unroll
        for (int nf = 0; nf < 4; nf++) {
            float* cc = acc[mf * 4 + nf];
            int col = bn + wn + nf * 8 + (lane & 3) * 2;
            float bv0 = bias[col], bv1 = bias[col + 1];
#pragma unroll
            for (int rp = 0; rp < 2; rp++) {
                int m = bm + wm + mf * 16 + (lane >> 2) + rp * 8;
                float v0 = cc[rp * 2 + 0] + bv0;
                float v1 = cc[rp * 2 + 1] + bv1;
                if (mode == 0) {
                    *(float2*)(C + (size_t)m * DM + col) = make_float2(v0, v1);
                } else if (mode == 3) {
                    const float* ad = g_X + (size_t)m * DM + col;
                    *(float2*)(g_Y + (size_t)m * DM + col) =
                        make_float2(ad[0] + isc * v0, ad[1] + isc * v1);
                } else if (mode == 4 || mode == 5) {
                    if (mode == 4) { v0 *= 0.125f; v1 *= 0.125f; }
                    int bb = m >> 9, si = m & 511, hh = col >> 6, d = col & 63;
                    int bh_ = bb * 8 + hh, mt = si >> 7, rr = si & 127;
                    int st = d >> 5, kb = (d & 31) * 2;
                    size_t blk = (((size_t)(bh_ * 4 + mt) * 2 + st) << 13) + swzoff(rr, kb);
                    char* base = (mode == 4) ? (char*)g_Qb : (char*)g_Kb;
                    float l0, l1;
                    uint32_t hp = pack_hi(v0, v1, l0, l1);
                    uint32_t lp = pack_lo(l0, l1);
                    *(uint32_t*)(base + blk)            = hp;
                    *(uint32_t*)(base + 8388608u + blk) = lp;
                } else {
                    int bb = m >> 9, si = m & 511, hh = col >> 6, d = col & 63;
                    int bh_ = bb * 8 + hh, st = si >> 5, kb = (si & 31) * 2;
                    size_t blk = ((size_t)(bh_ * 16 + st)) * 4096;
                    char* base = (char*)g_Vtb;
                    __nv_bfloat16 h0 = __float2bfloat16(v0);
                    __nv_bfloat16 h1 = __float2bfloat16(v1);
                    int o0 = swzoff(d, kb), o1 = swzoff(d + 1, kb);
                    *(__nv_bfloat16*)(base + blk + o0) = h0;
                    *(__nv_bfloat16*)(base + 8388608u + blk + o0) =
                        __float2bfloat16(v0 - __bfloat162float(h0));
                    *(__nv_bfloat16*)(base + blk + o1) = h1;
                    *(__nv_bfloat16*)(base + 8388608u + blk + o1) =
                        __float2bfloat16(v1 - __bfloat162float(h1));
                }
            }
        }
    }
}

// ===================== QK^T batched GEMM (triangular grid, bulk single-shot) ======
#define SK_SMEM (65536 + 64)

__global__ __launch_bounds__(256, 2) void qk_kernel()
{
    extern __shared__ char sm[];
    const uint32_t sbase = smem_to_u32(sm);
    const uint32_t mb = sbase + 65536;
    const int t = blockIdx.x;
    const int by = (t >= 6) ? 3 : (t >= 3) ? 2 : (t >= 1) ? 1 : 0;
    const int bx = t - ((by * (by + 1)) >> 1);
    const int bn = bx * 128, bm = by * 128;
    const int bh = blockIdx.y;
    const int tid = threadIdx.x, wid = tid >> 5, lane = tid & 31;

    if (tid == 0) {
        MBARRIER_INIT(mb, 1);
        asm volatile("fence.proxy.async.shared::cta;" ::: "memory");
        MBARRIER_EXPECT_TX(mb, 65536);
        const char* Qb = (const char*)g_Qb;
        const char* Kb = (const char*)g_Kb;
#pragma unroll
        for (int p = 0; p < 2; p++)
#pragma unroll
            for (int s = 0; s < 2; s++) {
                const char* qsrc = Qb + (size_t)p * 8388608u + (((size_t)(bh * 4 + by) * 2 + s) << 13);
                const char* ksrc = Kb + (size_t)p * 8388608u + (((size_t)(bh * 4 + bx) * 2 + s) << 13);
                BULK_G2S(sbase + p * 16384 + s * 8192,         qsrc, 8192, mb);
                BULK_G2S(sbase + 32768 + p * 16384 + s * 8192, ksrc, 8192, mb);
            }
    }
    __syncthreads();
    MBARRIER_WAIT_PARITY(mb, 0);

    const int wm = (wid >> 2) * 64, wn = (wid & 3) * 32;
    const int boff_n = ((lane >> 4) << 3) + (lane & 7);

    float acc[16][4];
#pragma unroll
    for (int i = 0; i < 16; i++)
#pragma unroll
        for (int j = 0; j < 4; j++) acc[i][j] = 0.f;

#pragma unroll
    for (int kh = 0; kh < 4; kh++) {
        const int chunk = (kh >> 1) * 8192;
        const int qa = ((kh & 1) * 2 + (lane >> 4)) << 4;
        const int qb = ((kh & 1) * 2 + ((lane >> 3) & 1)) << 4;
        uint32_t bh_[8], bl_[8], a[16];
#pragma unroll
        for (int nf2 = 0; nf2 < 2; nf2++) {
            int rb = wn + nf2 * 16 + boff_n;
            uint32_t baddr = sbase + 32768 + chunk + swzoff(rb, qb);
            ldsm4(bh_ + nf2 * 4, baddr);
            ldsm4(bl_ + nf2 * 4, baddr + 16384);
        }
#pragma unroll
        for (int mf = 0; mf < 4; mf++) {
            int ra = wm + mf * 16 + (lane & 15);
            ldsm4(a + mf * 4, sbase + chunk + swzoff(ra, qa));
        }
#pragma unroll
        for (int mf = 0; mf < 4; mf++)
#pragma unroll
            for (int nf = 0; nf < 4; nf++)
                mma16816(acc[mf * 4 + nf], a + mf * 4, bh_ + nf * 2);
#pragma unroll
        for (int mf = 0; mf < 4; mf++)
#pragma unroll
            for (int nf = 0; nf < 4; nf++)
                mma16816(acc[mf * 4 + nf], a + mf * 4, bl_ + nf * 2);
#pragma unroll
        for (int mf = 0; mf < 4; mf++) {
            int ra = wm + mf * 16 + (lane & 15);
            ldsm4(a + mf * 4, sbase + 16384 + chunk + swzoff(ra, qa));
        }
#pragma unroll
        for (int mf = 0; mf < 4; mf++)
#pragma unroll
            for (int nf = 0; nf < 4; nf++)
                mma16816(acc[mf * 4 + nf], a + mf * 4, bh_ + nf * 2);
    }

    float* Sp = g_S + (size_t)bh * 512 * 512;
#pragma unroll
    for (int mf = 0; mf < 4; mf++)
#pragma unroll
        for (int nf = 0; nf < 4; nf++) {
            float* cc = acc[mf * 4 + nf];
            int col = bn + wn + nf * 8 + (lane & 3) * 2;
#pragma unroll
            for (int rp = 0; rp < 2; rp++) {
                int m = bm + wm + mf * 16 + (lane >> 2) + rp * 8;
                *(float2*)(Sp + (size_t)m * 512 + col) =
                    make_float2(cc[rp * 2], cc[rp * 2 + 1]);
            }
        }
}

// ===================== row kernel (causal-truncated tiles) =========================
__global__ __launch_bounds__(256) void row_kernel(const float* __restrict__ gammas)
{
    const int bh = blockIdx.y, h = bh & 7;
    const int wid = threadIdx.x >> 5, lane = threadIdx.x & 31;
    const int i = blockIdx.x * 8 + wid;
    const int Ti = i >> 7;
    const int mt = i >> 7, rr = i & 127;
    char* Abase = (char*)g_A;

    if (i == 0) {
        uint2 zz = make_uint2(0u, 0u);
        int st = lane >> 3, kb = (lane & 7) * 8;
        size_t blk = ((size_t)(bh * 4 + 0) * 16 + st) * 8192 + swzoff(0, kb);
        *(uint2*)(Abase + blk)             = zz;
        *(uint2*)(Abase + 67108864u + blk) = zz;
        return;
    }

    float gv = gammas[h];
    float gam = -(fmaxf(gv, 0.f) + log1pf(__expf(-fabsf(gv))));

    const float4* Srow = (const float4*)(g_S + ((size_t)bh * 512 + i) * 512);
    float sc[4][4], e[4][4], ls[4];
#pragma unroll
    for (int t = 0; t < 4; t++) {
        if (t > Ti) { ls[t] = 0.f; continue; }
        float4 sv = Srow[lane + 32 * t];
        int j0 = 4 * (lane + 32 * t);
        sc[t][0] = (j0 + 0 < i) ? sv.x : NEG_INF;
        sc[t][1] = (j0 + 1 < i) ? sv.y : NEG_INF;
        sc[t][2] = (j0 + 2 < i) ? sv.z : NEG_INF;
        sc[t][3] = (j0 + 3 < i) ? sv.w : NEG_INF;
    }

    float m = NEG_INF;
#pragma unroll
    for (int t = 0; t < 4; t++) {
        if (t > Ti) break;
#pragma unroll
        for (int l = 0; l < 4; l++) m = fmaxf(m, sc[t][l]);
    }
#pragma unroll
    for (int off = 16; off; off >>= 1)
        m = fmaxf(m, __shfl_xor_sync(0xffffffffu, m, off));

#pragma unroll
    for (int t = 0; t < 4; t++) {
        if (t > Ti) break;
        ls[t] = 0.f;
#pragma unroll
        for (int l = 0; l < 4; l++) { e[t][l] = __expf(sc[t][l] - m); ls[t] += e[t][l]; }
    }
    float excl[4], tot[4];
#pragma unroll
    for (int t = 0; t < 4; t++) {
        if (t > Ti) break;
        float x = ls[t];
#pragma unroll
        for (int off = 1; off < 32; off <<= 1) {
            float y = __shfl_up_sync(0xffffffffu, x, off);
            if (lane >= off) x += y;
        }
        excl[t] = x - ls[t];
        tot[t]  = __shfl_sync(0xffffffffu, x, 31);
    }
    float baseA[4], T = 0.f;
#pragma unroll
    for (int t = 0; t < 4; t++) {
        if (t > Ti) break;
        baseA[t] = T; T += tot[t];
    }
    float invT = 1.f / T;

#pragma unroll
    for (int t = 0; t < 4; t++) {
        if (t > Ti) break;
        float run = baseA[t] + excl[t];
#pragma unroll
        for (int l = 0; l < 4; l++) {
            run += e[t][l];
            int j = 4 * lane + 128 * t + l;
            float suf  = fmaxf(T - run, 0.f);
            float dist = sqrtf(fmaxf(suf * invT * (float)(i - j), 0.f));
            float tmp  = __expf(dist * gam);
            tmp = fminf(fmaxf(tmp, 1e-5f), 1e5f);
            sc[t][l] = (j < i) ? sc[t][l] * tmp : NEG_INF;
        }
    }

    float m2 = NEG_INF;
#pragma unroll
    for (int t = 0; t < 4; t++) {
        if (t > Ti) break;
#pragma unroll
        for (int l = 0; l < 4; l++) m2 = fmaxf(m2, sc[t][l]);
    }
#pragma unroll
    for (int off = 16; off; off >>= 1)
        m2 = fmaxf(m2, __shfl_xor_sync(0xffffffffu, m2, off));
    float Z = 0.f;
#pragma unroll
    for (int t = 0; t < 4; t++) {
        if (t > Ti) break;
#pragma unroll
        for (int l = 0; l < 4; l++) { e[t][l] = __expf(sc[t][l] - m2); Z += e[t][l]; }
    }
#pragma unroll
    for (int off = 16; off; off >>= 1)
        Z += __shfl_xor_sync(0xffffffffu, Z, off);
    float invZ = 1.f / Z;

#pragma unroll
    for (int t = 0; t < 4; t++) {
        if (t > Ti) break;
        float a0 = e[t][0] * invZ, a1 = e[t][1] * invZ;
        float a2 = e[t][2] * invZ, a3 = e[t][3] * invZ;
        float l0, l1, l2, l3;
        uint2 hp; hp.x = pack_hi(a0, a1, l0, l1); hp.y = pack_hi(a2, a3, l2, l3);
        uint2 lp; lp.x = pack_lo(l0, l1);         lp.y = pack_lo(l2, l3);
        int st = (lane >> 3) + 4 * t, kb = (lane & 7) * 8;
        size_t blk = ((size_t)(bh * 4 + mt) * 16 + st) * 8192 + swzoff(rr, kb);
        *(uint2*)(Abase + blk)             = hp;
        *(uint2*)(Abase + 67108864u + blk) = lp;
    }
}

// ===================== AV batched GEMM (2-deep bulk pipeline, causal) =============
#define AVB 24576
#define AV_SMEM (2*AVB + 64)

__global__ __launch_bounds__(256, 2) void av_kernel()
{
    extern __shared__ char sm[];
    const uint32_t sbase = smem_to_u32(sm);
    const uint32_t mb0 = sbase + 2 * AVB, mb1 = mb0 + 8;
    const int mt = blockIdx.x;
    const int bm = mt * 128;
    const int bh = blockIdx.y;
    const int b = bh >> 3, h = bh & 7;
    const int tid = threadIdx.x, wid = tid >> 5, lane = tid & 31;
    const int nst = (bm + 128) >> 5;

    if (tid == 0) { MBARRIER_INIT(mb0, 1); MBARRIER_INIT(mb1, 1); }
    __syncthreads();

    float acc[8][4];
#pragma unroll
    for (int i = 0; i < 8; i++)
#pragma unroll
        for (int j = 0; j < 4; j++) acc[i][j] = 0.f;

    auto issue = [&](int s, int buf) {
        uint32_t mb = buf ? mb1 : mb0;
        uint32_t d = sbase + buf * AVB;
        MBARRIER_EXPECT_TX(mb, 24576);
        const char* Ap = (const char*)g_A + (((size_t)(bh * 4 + mt) * 16 + s) << 13);
        const char* Vp = (const char*)g_Vtb + ((size_t)(bh * 16 + s)) * 4096;
        BULK_G2S(d,         Ap,              8192, mb);
        BULK_G2S(d + 8192,  Ap + 67108864u,  8192, mb);
        BULK_G2S(d + 16384, Vp,              4096, mb);
        BULK_G2S(d + 20480, Vp + 8388608u,   4096, mb);
    };

    const int wm = (wid >> 1) * 32, wn = (wid & 1) * 32;
    const int boff_n = ((lane >> 4) << 3) + (lane & 7);

    auto compute = [&](int buf) {
        uint32_t Ab = sbase + buf * AVB;
        uint32_t Vb = Ab + 16384;
#pragma unroll
        for (int kh = 0; kh < 2; kh++) {
            const int qa = (kh * 2 + (lane >> 4)) << 4;
            const int qb = (kh * 2 + ((lane >> 3) & 1)) << 4;
            uint32_t bh_[8], bl_[8], a[8];
#pragma unroll
            for (int nf2 = 0; nf2 < 2; nf2++) {
                int rb = wn + nf2 * 16 + boff_n;
                uint32_t baddr = Vb + swzoff(rb, qb);
                ldsm4(bh_ + nf2 * 4, baddr);
                ldsm4(bl_ + nf2 * 4, baddr + 4096);
            }
#pragma unroll
            for (int mf = 0; mf < 2; mf++) {
                int ra = wm + mf * 16 + (lane & 15);
                ldsm4(a + mf * 4, Ab + swzoff(ra, qa));
            }
#pragma unroll
            for (int mf = 0; mf < 2; mf++)
#pragma unroll
                for (int nf = 0; nf < 4; nf++)
                    mma16816(acc[mf * 4 + nf], a + mf * 4, bh_ + nf * 2);
#pragma unroll
            for (int mf = 0; mf < 2; mf++)
#pragma unroll
                for (int nf = 0; nf < 4; nf++)
                    mma16816(acc[mf * 4 + nf], a + mf * 4, bl_ + nf * 2);
#pragma unroll
            for (int mf = 0; mf < 2; mf++) {
                int ra = wm + mf * 16 + (lane & 15);
                ldsm4(a + mf * 4, Ab + 8192 + swzoff(ra, qa));
            }
#pragma unroll
            for (int mf = 0; mf < 2; mf++)
#pragma unroll
                for (int nf = 0; nf < 4; nf++)
                    mma16816(acc[mf * 4 + nf], a + mf * 4, bh_ + nf * 2);
        }
    };

    if (tid == 0) issue(0, 0);
    for (int s = 0; s < nst; s++) {
        if (s + 1 < nst && tid == 0) issue(s + 1, (s + 1) & 1);
        MBARRIER_WAIT_PARITY((s & 1) ? mb1 : mb0, (s >> 1) & 1);
        compute(s & 1);
        __syncthreads();
    }

#pragma unroll
    for (int mf = 0; mf < 2; mf++)
#pragma unroll
        for (int nf = 0; nf < 4; nf++) {
            float* cc = acc[mf * 4 + nf];
            int col = wn + nf * 8 + (lane & 3) * 2;
#pragma unroll
            for (int rp = 0; rp < 2; rp++) {
                int mrow = bm + wm + mf * 16 + (lane >> 2) + rp * 8;
                *(float2*)(g_X + ((size_t)(b * 512 + mrow)) * 512 + h * 64 + col) =
                    make_float2(cc[rp * 2], cc[rp * 2 + 1]);
            }
        }
}

// ===================== parallel norm01 stats =====================
__global__ __launch_bounds__(256) void stats_kernel(
    const int* __restrict__ sgap, const int* __restrict__ pcount)
{
    __shared__ long long sh[32];
    int idx = blockIdx.x * 256 + threadIdx.x;
    long long a = sgap[idx], b = pcount[idx];
    long long s0 = a, q0 = a * a, s1 = b, q1 = b * b;
#pragma unroll
    for (int off = 16; off; off >>= 1) {
        s0 += __shfl_xor_sync(0xffffffffu, s0, off);
        q0 += __shfl_xor_sync(0xffffffffu, q0, off);
        s1 += __shfl_xor_sync(0xffffffffu, s1, off);
        q1 += __shfl_xor_sync(0xffffffffu, q1, off);
    }
    int wd = threadIdx.x >> 5, ln = threadIdx.x & 31;
    if (ln == 0) { sh[wd] = s0; sh[8+wd] = q0; sh[16+wd] = s1; sh[24+wd] = q1; }
    __syncthreads();
    if (threadIdx.x == 0) {
        long long S0=0,Q0=0,S1=0,Q1=0;
        for (int i = 0; i < 8; i++) { S0+=sh[i]; Q0+=sh[8+i]; S1+=sh[16+i]; Q1+=sh[24+i]; }
        atomicAdd(&g_sacc[0], (unsigned long long)S0);
        atomicAdd(&g_sacc[1], (unsigned long long)Q0);
        atomicAdd(&g_sacc[2], (unsigned long long)S1);
        atomicAdd(&g_sacc[3], (unsigned long long)Q1);
    }
}

// ===================== interference hidden layer -> bf16 blocks ===================
__global__ __launch_bounds__(256) void hidden_kernel(
    const int* __restrict__ sgap, const int* __restrict__ pcount,
    const float* __restrict__ Wi1, const float* __restrict__ bi1)
{
    float n = (float)MTOT;
    float S0 = (float)(long long)g_sacc[0], Q0 = (float)(long long)g_sacc[1];
    float S1 = (float)(long long)g_sacc[2], Q1 = (float)(long long)g_sacc[3];
    float m0 = S0 / n, m1 = S1 / n;
    float v0 = (Q0 - n*m0*m0) / (n - 1.f);
    float v1 = (Q1 - n*m1*m1) / (n - 1.f);
    float inv0 = 1.f / (sqrtf(fmaxf(v0, 0.f)) + 1e-6f);
    float inv1 = 1.f / (sqrtf(fmaxf(v1, 0.f)) + 1e-6f);

    int idx = blockIdx.x * 256 + threadIdx.x;
    int r = idx >> 6, c2 = (idx & 63) * 2;
    float ii0 = 0.5f * (tanhf(((float)sgap[r]   - m0) * inv0) + 1.f);
    float ii1 = 0.5f * (tanhf(((float)pcount[r] - m1) * inv1) + 1.f);
    float h0 = fmaxf(ii0 * Wi1[2*c2+0] + ii1 * Wi1[2*c2+1] + bi1[c2],   0.f);
    float h1 = fmaxf(ii0 * Wi1[2*c2+2] + ii1 * Wi1[2*c2+3] + bi1[c2+1], 0.f);
    float l0, l1;
    uint32_t hp = pack_hi(h0, h1, l0, l1);
    uint32_t lp = pack_lo(l0, l1);
    int mt = r >> 7, rr = r & 127, st = c2 >> 5, kb = (c2 & 31) * 2;
    size_t blk = ((size_t)mt * 4 + st) * 8192 + swzoff(rr, kb);
    char* base = (char*)g_Hb;
    *(uint32_t*)(base + blk)            = hp;
    *(uint32_t*)(base + 2097152u + blk) = lp;
}

// ===================== LayerNorm + pack to bf16 blocks ============================
__global__ __launch_bounds__(256) void ln_pack_kernel(
    const float* __restrict__ gw, const float* __restrict__ bw)
{
    int r = blockIdx.x * 8 + (threadIdx.x >> 5);
    int lane = threadIdx.x & 31;
    const float4* row = (const float4*)(g_Y + (size_t)r * DM);
    float4 xv[4];
    float s = 0.f, q = 0.f;
#pragma unroll
    for (int c = 0; c < 4; c++) {
        xv[c] = row[lane + 32 * c];
        s += xv[c].x + xv[c].y + xv[c].z + xv[c].w;
        q += xv[c].x*xv[c].x + xv[c].y*xv[c].y + xv[c].z*xv[c].z + xv[c].w*xv[c].w;
    }
#pragma unroll
    for (int off = 16; off; off >>= 1) {
        s += __shfl_xor_sync(0xffffffffu, s, off);
        q += __shfl_xor_sync(0xffffffffu, q, off);
    }
    float mu   = s * (1.f / 512.f);
    float rstd = rsqrtf(q * (1.f / 512.f) - mu * mu + 1e-5f);
    int mt = r >> 7, rr = r & 127;
    char* base = (char*)g_Yb;
#pragma unroll
    for (int c = 0; c < 4; c++) {
        float4 g4 = ((const float4*)gw)[lane + 32 * c];
        float4 b4 = ((const float4*)bw)[lane + 32 * c];
        float n0 = (xv[c].x - mu) * rstd * g4.x + b4.x;
        float n1 = (xv[c].y - mu) * rstd * g4.y + b4.y;
        float n2 = (xv[c].z - mu) * rstd * g4.z + b4.z;
        float n3 = (xv[c].w - mu) * rstd * g4.w + b4.w;
        float l0, l1, l2, l3;
        uint2 hp; hp.x = pack_hi(n0, n1, l0, l1); hp.y = pack_hi(n2, n3, l2, l3);
        uint2 lp; lp.x = pack_lo(l0, l1);         lp.y = pack_lo(l2, l3);
        int st = (lane >> 3) + 4 * c, kb = (lane & 7) * 8;
        size_t blk = ((size_t)mt * 16 + st) * 8192 + swzoff(rr, kb);
        *(uint2*)(base + blk)            = hp;
        *(uint2*)(base + 8388608u + blk) = lp;
    }
}

// ===================== launcher =====================
extern "C" void kernel_launch(void* const* d_in, const int* in_sizes, int n_in,
                              void* d_out, int out_size)
{
    const float* q      = (const float*)d_in[0];
    const float* k      = (const float*)d_in[1];
    const float* v      = (const float*)d_in[2];
    const int*   sgap   = (const int*)d_in[3];
    const int*   pcount = (const int*)d_in[4];
    const float* Wq = (const float*)d_in[5];  const float* bq = (const float*)d_in[6];
    const float* Wk = (const float*)d_in[7];  const float* bk = (const float*)d_in[8];
    const float* Wv = (const float*)d_in[9];  const float* bv = (const float*)d_in[10];
    const float* Wo = (const float*)d_in[11]; const float* bo = (const float*)d_in[12];
    const float* gammas = (const float*)d_in[13];
    const float* ln_g = (const float*)d_in[14]; const float* ln_b = (const float*)d_in[15];
    const float* Wi1 = (const float*)d_in[16];  const float* bi1 = (const float*)d_in[17];
    const float* Wi2 = (const float*)d_in[18];  const float* bi2 = (const float*)d_in[19];
    const float* iscale = (const float*)d_in[20];
    float* out = (float*)d_out;

    char *Ain, *Yb, *Hb;
    unsigned char* Wpk;
    cudaGetSymbolAddress((void**)&Ain, g_Ain);
    cudaGetSymbolAddress((void**)&Yb,  g_Yb);
    cudaGetSymbolAddress((void**)&Hb,  g_Hb);
    cudaGetSymbolAddress((void**)&Wpk, g_Wpk);

    cudaFuncSetAttribute(pgemm_kernel, cudaFuncAttributeMaxDynamicSharedMemorySize, PG_SMEM);
    cudaFuncSetAttribute(qk_kernel, cudaFuncAttributeMaxDynamicSharedMemorySize, SK_SMEM);
    cudaFuncSetAttribute(av_kernel, cudaFuncAttributeMaxDynamicSharedMemorySize, AV_SMEM);

    prep_kernel<<<14464, 256>>>(Wq, Wk, Wv, Wo, Wi2, Wpk, q, k, v);
    stats_kernel<<<32, 256>>>(sgap, pcount);

    pgemm_kernel<<<dim3(4, 64, 3), 256, PG_SMEM>>>(
        Ain, 8388608L, 16777216L, (const char*)Wpk, 524288L, 1048576L,
        512, 4, bq, bk, bv, nullptr, nullptr);

    qk_kernel<<<dim3(10, 128), 256, SK_SMEM>>>();
    row_kernel<<<dim3(64, 128), 256>>>(gammas);
    av_kernel<<<dim3(4, 128), 256, AV_SMEM>>>();

    hidden_kernel<<<2048, 256>>>(sgap, pcount, Wi1, bi1);
    pgemm_kernel<<<dim3(4, 64, 1), 256, PG_SMEM>>>(
        Hb, 2097152L, 0L, (const char*)Wpk + 4194304u, 131072L, 0L,
        128, 3, bi2, nullptr, nullptr, nullptr, iscale);

    ln_pack_kernel<<<1024, 256>>>(ln_g, ln_b);

    pgemm_kernel<<<dim3(4, 64, 1), 256, PG_SMEM>>>(
        Yb, 8388608L, 0L, (const char*)Wpk + 3145728u, 524288L, 0L,
        512, 0, bo, nullptr, nullptr, out, nullptr);
}

// round 12
// speedup vs baseline: 1.2598x; 1.0092x over previous
#include <cuda_runtime.h>
#include <cuda_bf16.h>
#include <math.h>
#include <cstdint>

#define BSZ 16
#define SEQ 512
#define DM  512
#define NH  8
#define DKH 64
#define MTOT (BSZ*SEQ)
#define NEG_INF (__int_as_float(0xff800000))
#define QKVPLN 4194304u
#define APLN 33554432u

// ===================== scratch =====================
__device__ __nv_bfloat16 g_Ain[3u*2u*4194304u];
__device__ __nv_bfloat16 g_Qb [2*QKVPLN];
__device__ __nv_bfloat16 g_Kb [2*QKVPLN];
__device__ __nv_bfloat16 g_Vtb[2*QKVPLN];
__device__ float         g_S  [APLN];
__device__ __nv_bfloat16 g_A  [2*APLN];
__device__ float g_X [MTOT*DM];
__device__ float g_Y [MTOT*DM];
__device__ __nv_bfloat16 g_Yb[2u*4194304u];
__device__ __nv_bfloat16 g_Hb[2u*1048576u];
__device__ unsigned long long g_sacc[4];
__device__ unsigned char g_Wpk[5u*1024u*1024u];

// ===================== asm helpers =====================
__device__ __forceinline__ uint32_t smem_to_u32(const void* p) {
    uint32_t a;
    asm("{ .reg .u64 t; cvta.to.shared.u64 t, %1; cvt.u32.u64 %0, t; }" : "=r"(a) : "l"(p));
    return a;
}
__device__ __forceinline__ void ldsm4(uint32_t* r, uint32_t addr) {
    asm volatile("ldmatrix.sync.aligned.m8n8.x4.shared.b16 {%0,%1,%2,%3}, [%4];"
        : "=r"(r[0]), "=r"(r[1]), "=r"(r[2]), "=r"(r[3]) : "r"(addr));
}
__device__ __forceinline__ void mma16816(float* c, const uint32_t* a, const uint32_t* b) {
    asm volatile("mma.sync.aligned.m16n8k16.row.col.f32.bf16.bf16.f32 "
        "{%0,%1,%2,%3}, {%4,%5,%6,%7}, {%8,%9}, {%0,%1,%2,%3};"
        : "+f"(c[0]), "+f"(c[1]), "+f"(c[2]), "+f"(c[3])
        : "r"(a[0]), "r"(a[1]), "r"(a[2]), "r"(a[3]), "r"(b[0]), "r"(b[1]));
}
__device__ __forceinline__ uint32_t pack_hi(float x, float y, float& lx, float& ly) {
    __nv_bfloat162 h = __floats2bfloat162_rn(x, y);
    lx = x - __bfloat162float(h.x);
    ly = y - __bfloat162float(h.y);
    return *reinterpret_cast<uint32_t*>(&h);
}
__device__ __forceinline__ uint32_t pack_lo(float lx, float ly) {
    __nv_bfloat162 l = __floats2bfloat162_rn(lx, ly);
    return *reinterpret_cast<uint32_t*>(&l);
}
__device__ __forceinline__ int swzoff(int r, int kb) {
    return r * 64 + ((((kb >> 4) ^ ((r >> 1) & 3)) << 4)) + (kb & 15);
}
#define BULK_G2S(dst, src, bytes, mbar) \
    asm volatile("cp.async.bulk.shared::cluster.global.mbarrier::complete_tx::bytes [%0], [%1], %2, [%3];" \
        :: "r"(dst), "l"(src), "r"(bytes), "r"(mbar) : "memory")
#define MBARRIER_INIT(mbar, cnt) \
    asm volatile("mbarrier.init.shared.b64 [%0], %1;" :: "r"((uint32_t)(mbar)), "r"((uint32_t)(cnt)) : "memory")
#define MBARRIER_EXPECT_TX(mbar, bytes) \
    asm volatile("mbarrier.arrive.expect_tx.shared.b64 _, [%0], %1;" :: "r"((uint32_t)(mbar)), "r"((uint32_t)(bytes)) : "memory")
#define MBARRIER_WAIT_PARITY(mbar, parity) do { \
    uint32_t _m = (uint32_t)(mbar); uint32_t _p = (uint32_t)(parity); uint32_t _d; \
    asm volatile("{\n\t.reg .pred p;\n\tmbarrier.try_wait.parity.acquire.cta.shared::cta.b64 p, [%1], %2;\n\tselp.b32 %0, 1, 0, p;\n\t}" \
        : "=r"(_d) : "r"(_m), "r"(_p) : "memory"); \
    if (!_d) { \
        asm volatile("{\n\t.reg .pred P1;\n\tWL_%=:\n\tmbarrier.try_wait.parity.acquire.cta.shared::cta.b64 P1, [%0], %1, 0x989680;\n\t@P1 bra.uni WD_%=;\n\tbra.uni WL_%=;\n\tWD_%=:\n\t}" \
            :: "r"(_m), "r"(_p) : "memory"); \
    } } while (0)

// ===================== fused prep: weight + activation pre-split ===================
__global__ __launch_bounds__(256) void prep_kernel(
    const float* __restrict__ Wq, const float* __restrict__ Wk,
    const float* __restrict__ Wv, const float* __restrict__ Wo,
    const float* __restrict__ Wi2, unsigned char* __restrict__ wdst,
    const float* __restrict__ q, const float* __restrict__ k, const float* __restrict__ v)
{
    int bb = blockIdx.x;
    if (bb < 2176) {
        if (bb == 0 && threadIdx.x < 4) g_sacc[threadIdx.x] = 0ull;
        const float* W; unsigned char* d; int K;
        if      (bb < 512)  { W = Wq;  d = wdst;              K = 512; }
        else if (bb < 1024) { W = Wk;  d = wdst + 1048576u;   K = 512; bb -= 512; }
        else if (bb < 1536) { W = Wv;  d = wdst + 2097152u;   K = 512; bb -= 1024; }
        else if (bb < 2048) { W = Wo;  d = wdst + 3145728u;   K = 512; bb -= 1536; }
        else                { W = Wi2; d = wdst + 4194304u;   K = 128; bb -= 2048; }
        int NK = (K == 512) ? 262144 : 65536;
        int S = K >> 5;
        int idx = bb * 256 + threadIdx.x;
        int halfK = K >> 1;
        int n = idx / halfK;
        int kk = (idx - n * halfK) * 2;
        float x0 = W[(size_t)n * K + kk];
        float x1 = W[(size_t)n * K + kk + 1];
        float lx, ly;
        uint32_t hp = pack_hi(x0, x1, lx, ly);
        uint32_t lp = pack_lo(lx, ly);
        int nt = n >> 7, rr = n & 127, st = kk >> 5, kb = (kk & 31) * 2;
        size_t blk = ((size_t)nt * S + st) * 8192 + swzoff(rr, kb);
        *(uint32_t*)(d + blk)                  = hp;
        *(uint32_t*)(d + (size_t)NK * 2 + blk) = lp;
    } else {
        int a = bb - 2176;
        int zy = a >> 12, zx = a & 4095;
        const float* src = zy == 0 ? q : zy == 1 ? k : v;
        char* dst = (char*)g_Ain + (size_t)zy * 16777216u;
        size_t e = ((size_t)zx * 256 + threadIdx.x) * 4;
        float4 x = *(const float4*)(src + e);
        float l0, l1, l2, l3;
        uint2 hp; hp.x = pack_hi(x.x, x.y, l0, l1); hp.y = pack_hi(x.z, x.w, l2, l3);
        uint2 lp; lp.x = pack_lo(l0, l1);           lp.y = pack_lo(l2, l3);
        int r = (int)(e >> 9), kk = (int)(e & 511);
        int mt = r >> 7, rr = r & 127, st = kk >> 5, kb = (kk & 31) * 2;
        size_t blk = ((size_t)mt * 16 + st) * 8192 + swzoff(rr, kb);
        *(uint2*)(dst + blk)            = hp;
        *(uint2*)(dst + 8388608u + blk) = lp;
    }
}

// ===================== unified pre-packed GEMM (2-deep bulk pipeline) ==============
#define PGB 32768
#define PG_SMEM (2*PGB + 64)

__global__ __launch_bounds__(256, 2) void pgemm_kernel(
    const char* __restrict__ Ab0, long Apl, long Az,
    const char* __restrict__ Bb0, long Bpl, long Bz,
    int K, int mode0,
    const float* __restrict__ b0, const float* __restrict__ b1, const float* __restrict__ b2,
    float* __restrict__ C, const float* __restrict__ scale)
{
    extern __shared__ char sm[];
    const uint32_t sbase = smem_to_u32(sm);
    const uint32_t mb0 = sbase + 2 * PGB, mb1 = mb0 + 8;
    const int tid = threadIdx.x, wid = tid >> 5, lane = tid & 31;
    const int bx = blockIdx.x, by = blockIdx.y, z = blockIdx.z;
    const int mode = mode0 + z;
    const char* Ab = Ab0 + (size_t)z * Az;
    const char* Bb = Bb0 + (size_t)z * Bz;
    const float* bias = (z == 0) ? b0 : (z == 1) ? b1 : b2;
    const int S = K >> 5;
    const int bm = by * 128, bn = bx * 128;

    if (tid == 0) { MBARRIER_INIT(mb0, 1); MBARRIER_INIT(mb1, 1); }
    __syncthreads();

    float acc[16][4];
#pragma unroll
    for (int i = 0; i < 16; i++)
#pragma unroll
        for (int j = 0; j < 4; j++) acc[i][j] = 0.f;

    auto issue = [&](int s, int buf) {
        uint32_t mb = buf ? mb1 : mb0;
        uint32_t d = sbase + buf * PGB;
        MBARRIER_EXPECT_TX(mb, 32768);
        const char* As = Ab + (((size_t)by * S + s) << 13);
        const char* Bs = Bb + (((size_t)bx * S + s) << 13);
        BULK_G2S(d,         As,       8192, mb);
        BULK_G2S(d + 8192,  As + Apl, 8192, mb);
        BULK_G2S(d + 16384, Bs,       8192, mb);
        BULK_G2S(d + 24576, Bs + Bpl, 8192, mb);
    };

    const int wm = (wid >> 2) * 64, wn = (wid & 3) * 32;
    const int boff_n = ((lane >> 4) << 3) + (lane & 7);

    auto compute = [&](int buf) {
        uint32_t Ahi = sbase + buf * PGB;
        uint32_t Bhi = Ahi + 16384;
#pragma unroll
        for (int kh = 0; kh < 2; kh++) {
            const int qa = (kh * 2 + (lane >> 4)) << 4;
            const int qb = (kh * 2 + ((lane >> 3) & 1)) << 4;
            uint32_t bh[8], bl[8], a[16];
#pragma unroll
            for (int nf2 = 0; nf2 < 2; nf2++) {
                int rb = wn + nf2 * 16 + boff_n;
                uint32_t baddr = Bhi + swzoff(rb, qb);
                ldsm4(bh + nf2 * 4, baddr);
                ldsm4(bl + nf2 * 4, baddr + 8192);
            }
#pragma unroll
            for (int mf = 0; mf < 4; mf++) {
                int ra = wm + mf * 16 + (lane & 15);
                ldsm4(a + mf * 4, Ahi + swzoff(ra, qa));
            }
#pragma unroll
            for (int mf = 0; mf < 4; mf++)
#pragma unroll
                for (int nf = 0; nf < 4; nf++)
                    mma16816(acc[mf * 4 + nf], a + mf * 4, bh + nf * 2);
#pragma unroll
            for (int mf = 0; mf < 4; mf++)
#pragma unroll
                for (int nf = 0; nf < 4; nf++)
                    mma16816(acc[mf * 4 + nf], a + mf * 4, bl + nf * 2);
#pragma unroll
            for (int mf = 0; mf < 4; mf++) {
                int ra = wm + mf * 16 + (lane & 15);
                ldsm4(a + mf * 4, Ahi + 8192 + swzoff(ra, qa));
            }
#pragma unroll
            for (int mf = 0; mf < 4; mf++)
#pragma unroll
                for (int nf = 0; nf < 4; nf++)
                    mma16816(acc[mf * 4 + nf], a + mf * 4, bh + nf * 2);
        }
    };

    if (tid == 0) issue(0, 0);
    for (int s = 0; s < S; s++) {
        if (s + 1 < S && tid == 0) issue(s + 1, (s + 1) & 1);
        MBARRIER_WAIT_PARITY((s & 1) ? mb1 : mb0, (s >> 1) & 1);
        compute(s & 1);
        __syncthreads();
    }

    const float isc = (mode == 3) ? scale[0] : 0.f;
#pragma unroll
    for (int mf = 0; mf < 4; mf++) {
#pragma unroll
        for (int nf = 0; nf < 4; nf++) {
            float* cc = acc[mf * 4 + nf];
            int col = bn + wn + nf * 8 + (lane & 3) * 2;
            float bv0 = bias[col], bv1 = bias[col + 1];
#pragma unroll
            for (int rp = 0; rp < 2; rp++) {
                int m = bm + wm + mf * 16 + (lane >> 2) + rp * 8;
                float v0 = cc[rp * 2 + 0] + bv0;
                float v1 = cc[rp * 2 + 1] + bv1;
                if (mode == 0) {
                    *(float2*)(C + (size_t)m * DM + col) = make_float2(v0, v1);
                } else if (mode == 3) {
                    const float* ad = g_X + (size_t)m * DM + col;
                    *(float2*)(g_Y + (size_t)m * DM + col) =
                        make_float2(ad[0] + isc * v0, ad[1] + isc * v1);
                } else if (mode == 4 || mode == 5) {
                    if (mode == 4) { v0 *= 0.125f; v1 *= 0.125f; }
                    int bb = m >> 9, si = m & 511, hh = col >> 6, d = col & 63;
                    int bh_ = bb * 8 + hh, mt = si >> 7, rr = si & 127;
                    int st = d >> 5, kb = (d & 31) * 2;
                    size_t blk = (((size_t)(bh_ * 4 + mt) * 2 + st) << 13) + swzoff(rr, kb);
                    char* base = (mode == 4) ? (char*)g_Qb : (char*)g_Kb;
                    float l0, l1;
                    uint32_t hp = pack_hi(v0, v1, l0, l1);
                    uint32_t lp = pack_lo(l0, l1);
                    *(uint32_t*)(base + blk)            = hp;
                    *(uint32_t*)(base + 8388608u + blk) = lp;
                } else {
                    int bb = m >> 9, si = m & 511, hh = col >> 6, d = col & 63;
                    int bh_ = bb * 8 + hh, st = si >> 5, kb = (si & 31) * 2;
                    size_t blk = ((size_t)(bh_ * 16 + st)) * 4096;
                    char* base = (char*)g_Vtb;
                    __nv_bfloat16 h0 = __float2bfloat16(v0);
                    __nv_bfloat16 h1 = __float2bfloat16(v1);
                    int o0 = swzoff(d, kb), o1 = swzoff(d + 1, kb);
                    *(__nv_bfloat16*)(base + blk + o0) = h0;
                    *(__nv_bfloat16*)(base + 8388608u + blk + o0) =
                        __float2bfloat16(v0 - __bfloat162float(h0));
                    *(__nv_bfloat16*)(base + blk + o1) = h1;
                    *(__nv_bfloat16*)(base + 8388608u + blk + o1) =
                        __float2bfloat16(v1 - __bfloat162float(h1));
                }
            }
        }
    }
}

// ===================== QK^T: paired tiles per Q-strip (double-buffered K) =========
// 6 CTAs per bh: t=0:(by0,bx0,1) 1:(1,0,2) 2:(2,0,2) 3:(2,2,1) 4:(3,0,2) 5:(3,2,2)
// smem: Q 32KB | K buf0 32KB | K buf1 32KB | mbarriers
#define SK_SMEM (98304 + 64)

__global__ __launch_bounds__(256, 2) void qk_kernel()
{
    extern __shared__ char sm[];
    const uint32_t sbase = smem_to_u32(sm);
    const uint32_t mbb = sbase + 98304;
    const int t = blockIdx.x;
    const int by  = (t >= 4) ? 3 : (t >= 2) ? 2 : t;
    const int bx0 = (t == 3 || t == 5) ? 2 : 0;
    const int ntl = (t == 0 || t == 3) ? 1 : 2;
    const int bm = by * 128;
    const int bh = blockIdx.y;
    const int tid = threadIdx.x, wid = tid >> 5, lane = tid & 31;

    if (tid == 0) {
        MBARRIER_INIT(mbb, 1); MBARRIER_INIT(mbb + 8, 1);
        asm volatile("fence.proxy.async.shared::cta;" ::: "memory");
        const char* Qb = (const char*)g_Qb;
        const char* Kb = (const char*)g_Kb;
        MBARRIER_EXPECT_TX(mbb, 65536);
#pragma unroll
        for (int p = 0; p < 2; p++)
#pragma unroll
            for (int s = 0; s < 2; s++) {
                const char* qsrc = Qb + (size_t)p * 8388608u + (((size_t)(bh * 4 + by) * 2 + s) << 13);
                const char* ksrc = Kb + (size_t)p * 8388608u + (((size_t)(bh * 4 + bx0) * 2 + s) << 13);
                BULK_G2S(sbase + p * 16384 + s * 8192,         qsrc, 8192, mbb);
                BULK_G2S(sbase + 32768 + p * 16384 + s * 8192, ksrc, 8192, mbb);
            }
        if (ntl == 2) {
            MBARRIER_EXPECT_TX(mbb + 8, 32768);
#pragma unroll
            for (int p = 0; p < 2; p++)
#pragma unroll
                for (int s = 0; s < 2; s++) {
                    const char* ksrc = Kb + (size_t)p * 8388608u + (((size_t)(bh * 4 + bx0 + 1) * 2 + s) << 13);
                    BULK_G2S(sbase + 65536 + p * 16384 + s * 8192, ksrc, 8192, mbb + 8);
                }
        }
    }
    __syncthreads();

    const int wm = (wid >> 2) * 64, wn = (wid & 3) * 32;
    const int boff_n = ((lane >> 4) << 3) + (lane & 7);

    for (int ti = 0; ti < ntl; ti++) {
        MBARRIER_WAIT_PARITY(mbb + ti * 8, 0);
        const uint32_t Kbuf = sbase + 32768 + ti * 32768;
        const int bn = (bx0 + ti) * 128;

        float acc[16][4];
#pragma unroll
        for (int i = 0; i < 16; i++)
#pragma unroll
            for (int j = 0; j < 4; j++) acc[i][j] = 0.f;

#pragma unroll
        for (int kh = 0; kh < 4; kh++) {
            const int chunk = (kh >> 1) * 8192;
            const int qa = ((kh & 1) * 2 + (lane >> 4)) << 4;
            const int qb = ((kh & 1) * 2 + ((lane >> 3) & 1)) << 4;
            uint32_t bh_[8], bl_[8], a[16];
#pragma unroll
            for (int nf2 = 0; nf2 < 2; nf2++) {
                int rb = wn + nf2 * 16 + boff_n;
                uint32_t baddr = Kbuf + chunk + swzoff(rb, qb);
                ldsm4(bh_ + nf2 * 4, baddr);
                ldsm4(bl_ + nf2 * 4, baddr + 16384);
            }
#pragma unroll
            for (int mf = 0; mf < 4; mf++) {
                int ra = wm + mf * 16 + (lane & 15);
                ldsm4(a + mf * 4, sbase + chunk + swzoff(ra, qa));
            }
#pragma unroll
            for (int mf = 0; mf < 4; mf++)
#pragma unroll
                for (int nf = 0; nf < 4; nf++)
                    mma16816(acc[mf * 4 + nf], a + mf * 4, bh_ + nf * 2);
#pragma unroll
            for (int mf = 0; mf < 4; mf++)
#pragma unroll
                for (int nf = 0; nf < 4; nf++)
                    mma16816(acc[mf * 4 + nf], a + mf * 4, bl_ + nf * 2);
#pragma unroll
            for (int mf = 0; mf < 4; mf++) {
                int ra = wm + mf * 16 + (lane & 15);
                ldsm4(a + mf * 4, sbase + 16384 + chunk + swzoff(ra, qa));
            }
#pragma unroll
            for (int mf = 0; mf < 4; mf++)
#pragma unroll
                for (int nf = 0; nf < 4; nf++)
                    mma16816(acc[mf * 4 + nf], a + mf * 4, bh_ + nf * 2);
        }

        float* Sp = g_S + (size_t)bh * 512 * 512;
#pragma unroll
        for (int mf = 0; mf < 4; mf++)
#pragma unroll
            for (int nf = 0; nf < 4; nf++) {
                float* cc = acc[mf * 4 + nf];
                int col = bn + wn + nf * 8 + (lane & 3) * 2;
#pragma unroll
                for (int rp = 0; rp < 2; rp++) {
                    int m = bm + wm + mf * 16 + (lane >> 2) + rp * 8;
                    *(float2*)(Sp + (size_t)m * 512 + col) =
                        make_float2(cc[rp * 2], cc[rp * 2 + 1]);
                }
            }
    }
}

// ===================== row kernel (causal-truncated tiles) =========================
__global__ __launch_bounds__(256) void row_kernel(const float* __restrict__ gammas)
{
    const int bh = blockIdx.y, h = bh & 7;
    const int wid = threadIdx.x >> 5, lane = threadIdx.x & 31;
    const int i = blockIdx.x * 8 + wid;
    const int Ti = i >> 7;
    const int mt = i >> 7, rr = i & 127;
    char* Abase = (char*)g_A;

    if (i == 0) {
        uint2 zz = make_uint2(0u, 0u);
        int st = lane >> 3, kb = (lane & 7) * 8;
        size_t blk = ((size_t)(bh * 4 + 0) * 16 + st) * 8192 + swzoff(0, kb);
        *(uint2*)(Abase + blk)             = zz;
        *(uint2*)(Abase + 67108864u + blk) = zz;
        return;
    }

    float gv = gammas[h];
    float gam = -(fmaxf(gv, 0.f) + log1pf(__expf(-fabsf(gv))));

    const float4* Srow = (const float4*)(g_S + ((size_t)bh * 512 + i) * 512);
    float sc[4][4], e[4][4], ls[4];
#pragma unroll
    for (int t = 0; t < 4; t++) {
        if (t > Ti) { ls[t] = 0.f; continue; }
        float4 sv = Srow[lane + 32 * t];
        int j0 = 4 * (lane + 32 * t);
        sc[t][0] = (j0 + 0 < i) ? sv.x : NEG_INF;
        sc[t][1] = (j0 + 1 < i) ? sv.y : NEG_INF;
        sc[t][2] = (j0 + 2 < i) ? sv.z : NEG_INF;
        sc[t][3] = (j0 + 3 < i) ? sv.w : NEG_INF;
    }

    float m = NEG_INF;
#pragma unroll
    for (int t = 0; t < 4; t++) {
        if (t > Ti) break;
#pragma unroll
        for (int l = 0; l < 4; l++) m = fmaxf(m, sc[t][l]);
    }
#pragma unroll
    for (int off = 16; off; off >>= 1)
        m = fmaxf(m, __shfl_xor_sync(0xffffffffu, m, off));

#pragma unroll
    for (int t = 0; t < 4; t++) {
        if (t > Ti) break;
        ls[t] = 0.f;
#pragma unroll
        for (int l = 0; l < 4; l++) { e[t][l] = __expf(sc[t][l] - m); ls[t] += e[t][l]; }
    }
    float excl[4], tot[4];
#pragma unroll
    for (int t = 0; t < 4; t++) {
        if (t > Ti) break;
        float x = ls[t];
#pragma unroll
        for (int off = 1; off < 32; off <<= 1) {
            float y = __shfl_up_sync(0xffffffffu, x, off);
            if (lane >= off) x += y;
        }
        excl[t] = x - ls[t];
        tot[t]  = __shfl_sync(0xffffffffu, x, 31);
    }
    float baseA[4], T = 0.f;
#pragma unroll
    for (int t = 0; t < 4; t++) {
        if (t > Ti) break;
        baseA[t] = T; T += tot[t];
    }
    float invT = 1.f / T;

#pragma unroll
    for (int t = 0; t < 4; t++) {
        if (t > Ti) break;
        float run = baseA[t] + excl[t];
#pragma unroll
        for (int l = 0; l < 4; l++) {
            run += e[t][l];
            int j = 4 * lane + 128 * t + l;
            float suf  = fmaxf(T - run, 0.f);
            float dist = sqrtf(fmaxf(suf * invT * (float)(i - j), 0.f));
            float tmp  = __expf(dist * gam);
            tmp = fminf(fmaxf(tmp, 1e-5f), 1e5f);
            sc[t][l] = (j < i) ? sc[t][l] * tmp : NEG_INF;
        }
    }

    float m2 = NEG_INF;
#pragma unroll
    for (int t = 0; t < 4; t++) {
        if (t > Ti) break;
#pragma unroll
        for (int l = 0; l < 4; l++) m2 = fmaxf(m2, sc[t][l]);
    }
#pragma unroll
    for (int off = 16; off; off >>= 1)
        m2 = fmaxf(m2, __shfl_xor_sync(0xffffffffu, m2, off));
    float Z = 0.f;
#pragma unroll
    for (int t = 0; t < 4; t++) {
        if (t > Ti) break;
#pragma unroll
        for (int l = 0; l < 4; l++) { e[t][l] = __expf(sc[t][l] - m2); Z += e[t][l]; }
    }
#pragma unroll
    for (int off = 16; off; off >>= 1)
        Z += __shfl_xor_sync(0xffffffffu, Z, off);
    float invZ = 1.f / Z;

#pragma unroll
    for (int t = 0; t < 4; t++) {
        if (t > Ti) break;
        float a0 = e[t][0] * invZ, a1 = e[t][1] * invZ;
        float a2 = e[t][2] * invZ, a3 = e[t][3] * invZ;
        float l0, l1, l2, l3;
        uint2 hp; hp.x = pack_hi(a0, a1, l0, l1); hp.y = pack_hi(a2, a3, l2, l3);
        uint2 lp; lp.x = pack_lo(l0, l1);         lp.y = pack_lo(l2, l3);
        int st = (lane >> 3) + 4 * t, kb = (lane & 7) * 8;
        size_t blk = ((size_t)(bh * 4 + mt) * 16 + st) * 8192 + swzoff(rr, kb);
        *(uint2*)(Abase + blk)             = hp;
        *(uint2*)(Abase + 67108864u + blk) = lp;
    }
}

// ===================== AV batched GEMM (2-deep bulk pipeline, causal) =============
#define AVB 24576
#define AV_SMEM (2*AVB + 64)

__global__ __launch_bounds__(256, 2) void av_kernel()
{
    extern __shared__ char sm[];
    const uint32_t sbase = smem_to_u32(sm);
    const uint32_t mb0 = sbase + 2 * AVB, mb1 = mb0 + 8;
    const int mt = blockIdx.x;
    const int bm = mt * 128;
    const int bh = blockIdx.y;
    const int b = bh >> 3, h = bh & 7;
    const int tid = threadIdx.x, wid = tid >> 5, lane = tid & 31;
    const int nst = (bm + 128) >> 5;

    if (tid == 0) { MBARRIER_INIT(mb0, 1); MBARRIER_INIT(mb1, 1); }
    __syncthreads();

    float acc[8][4];
#pragma unroll
    for (int i = 0; i < 8; i++)
#pragma unroll
        for (int j = 0; j < 4; j++) acc[i][j] = 0.f;

    auto issue = [&](int s, int buf) {
        uint32_t mb = buf ? mb1 : mb0;
        uint32_t d = sbase + buf * AVB;
        MBARRIER_EXPECT_TX(mb, 24576);
        const char* Ap = (const char*)g_A + (((size_t)(bh * 4 + mt) * 16 + s) << 13);
        const char* Vp = (const char*)g_Vtb + ((size_t)(bh * 16 + s)) * 4096;
        BULK_G2S(d,         Ap,              8192, mb);
        BULK_G2S(d + 8192,  Ap + 67108864u,  8192, mb);
        BULK_G2S(d + 16384, Vp,              4096, mb);
        BULK_G2S(d + 20480, Vp + 8388608u,   4096, mb);
    };

    const int wm = (wid >> 1) * 32, wn = (wid & 1) * 32;
    const int boff_n = ((lane >> 4) << 3) + (lane & 7);

    auto compute = [&](int buf) {
        uint32_t Ab = sbase + buf * AVB;
        uint32_t Vb = Ab + 16384;
#pragma unroll
        for (int kh = 0; kh < 2; kh++) {
            const int qa = (kh * 2 + (lane >> 4)) << 4;
            const int qb = (kh * 2 + ((lane >> 3) & 1)) << 4;
            uint32_t bh_[8], bl_[8], a[8];
#pragma unroll
            for (int nf2 = 0; nf2 < 2; nf2++) {
                int rb = wn + nf2 * 16 + boff_n;
                uint32_t baddr = Vb + swzoff(rb, qb);
                ldsm4(bh_ + nf2 * 4, baddr);
                ldsm4(bl_ + nf2 * 4, baddr + 4096);
            }
#pragma unroll
            for (int mf = 0; mf < 2; mf++) {
                int ra = wm + mf * 16 + (lane & 15);
                ldsm4(a + mf * 4, Ab + swzoff(ra, qa));
            }
#pragma unroll
            for (int mf = 0; mf < 2; mf++)
#pragma unroll
                for (int nf = 0; nf < 4; nf++)
                    mma16816(acc[mf * 4 + nf], a + mf * 4, bh_ + nf * 2);
#pragma unroll
            for (int mf = 0; mf < 2; mf++)
#pragma unroll
                for (int nf = 0; nf < 4; nf++)
                    mma16816(acc[mf * 4 + nf], a + mf * 4, bl_ + nf * 2);
#pragma unroll
            for (int mf = 0; mf < 2; mf++) {
                int ra = wm + mf * 16 + (lane & 15);
                ldsm4(a + mf * 4, Ab + 8192 + swzoff(ra, qa));
            }
#pragma unroll
            for (int mf = 0; mf < 2; mf++)
#pragma unroll
                for (int nf = 0; nf < 4; nf++)
                    mma16816(acc[mf * 4 + nf], a + mf * 4, bh_ + nf * 2);
        }
    };

    if (tid == 0) issue(0, 0);
    for (int s = 0; s < nst; s++) {
        if (s + 1 < nst && tid == 0) issue(s + 1, (s + 1) & 1);
        MBARRIER_WAIT_PARITY((s & 1) ? mb1 : mb0, (s >> 1) & 1);
        compute(s & 1);
        __syncthreads();
    }

#pragma unroll
    for (int mf = 0; mf < 2; mf++)
#pragma unroll
        for (int nf = 0; nf < 4; nf++) {
            float* cc = acc[mf * 4 + nf];
            int col = wn + nf * 8 + (lane & 3) * 2;
#pragma unroll
            for (int rp = 0; rp < 2; rp++) {
                int mrow = bm + wm + mf * 16 + (lane >> 2) + rp * 8;
                *(float2*)(g_X + ((size_t)(b * 512 + mrow)) * 512 + h * 64 + col) =
                    make_float2(cc[rp * 2], cc[rp * 2 + 1]);
            }
        }
}

// ===================== parallel norm01 stats =====================
__global__ __launch_bounds__(256) void stats_kernel(
    const int* __restrict__ sgap, const int* __restrict__ pcount)
{
    __shared__ long long sh[32];
    int idx = blockIdx.x * 256 + threadIdx.x;
    long long a = sgap[idx], b = pcount[idx];
    long long s0 = a, q0 = a * a, s1 = b, q1 = b * b;
#pragma unroll
    for (int off = 16; off; off >>= 1) {
        s0 += __shfl_xor_sync(0xffffffffu, s0, off);
        q0 += __shfl_xor_sync(0xffffffffu, q0, off);
        s1 += __shfl_xor_sync(0xffffffffu, s1, off);
        q1 += __shfl_xor_sync(0xffffffffu, q1, off);
    }
    int wd = threadIdx.x >> 5, ln = threadIdx.x & 31;
    if (ln == 0) { sh[wd] = s0; sh[8+wd] = q0; sh[16+wd] = s1; sh[24+wd] = q1; }
    __syncthreads();
    if (threadIdx.x == 0) {
        long long S0=0,Q0=0,S1=0,Q1=0;
        for (int i = 0; i < 8; i++) { S0+=sh[i]; Q0+=sh[8+i]; S1+=sh[16+i]; Q1+=sh[24+i]; }
        atomicAdd(&g_sacc[0], (unsigned long long)S0);
        atomicAdd(&g_sacc[1], (unsigned long long)Q0);
        atomicAdd(&g_sacc[2], (unsigned long long)S1);
        atomicAdd(&g_sacc[3], (unsigned long long)Q1);
    }
}

// ===================== interference hidden layer -> bf16 blocks ===================
__global__ __launch_bounds__(256) void hidden_kernel(
    const int* __restrict__ sgap, const int* __restrict__ pcount,
    const float* __restrict__ Wi1, const float* __restrict__ bi1)
{
    float n = (float)MTOT;
    float S0 = (float)(long long)g_sacc[0], Q0 = (float)(long long)g_sacc[1];
    float S1 = (float)(long long)g_sacc[2], Q1 = (float)(long long)g_sacc[3];
    float m0 = S0 / n, m1 = S1 / n;
    float v0 = (Q0 - n*m0*m0) / (n - 1.f);
    float v1 = (Q1 - n*m1*m1) / (n - 1.f);
    float inv0 = 1.f / (sqrtf(fmaxf(v0, 0.f)) + 1e-6f);
    float inv1 = 1.f / (sqrtf(fmaxf(v1, 0.f)) + 1e-6f);

    int idx = blockIdx.x * 256 + threadIdx.x;
    int r = idx >> 6, c2 = (idx & 63) * 2;
    float ii0 = 0.5f * (tanhf(((float)sgap[r]   - m0) * inv0) + 1.f);
    float ii1 = 0.5f * (tanhf(((float)pcount[r] - m1) * inv1) + 1.f);
    float h0 = fmaxf(ii0 * Wi1[2*c2+0] + ii1 * Wi1[2*c2+1] + bi1[c2],   0.f);
    float h1 = fmaxf(ii0 * Wi1[2*c2+2] + ii1 * Wi1[2*c2+3] + bi1[c2+1], 0.f);
    float l0, l1;
    uint32_t hp = pack_hi(h0, h1, l0, l1);
    uint32_t lp = pack_lo(l0, l1);
    int mt = r >> 7, rr = r & 127, st = c2 >> 5, kb = (c2 & 31) * 2;
    size_t blk = ((size_t)mt * 4 + st) * 8192 + swzoff(rr, kb);
    char* base = (char*)g_Hb;
    *(uint32_t*)(base + blk)            = hp;
    *(uint32_t*)(base + 2097152u + blk) = lp;
}

// ===================== LayerNorm + pack to bf16 blocks ============================
__global__ __launch_bounds__(256) void ln_pack_kernel(
    const float* __restrict__ gw, const float* __restrict__ bw)
{
    int r = blockIdx.x * 8 + (threadIdx.x >> 5);
    int lane = threadIdx.x & 31;
    const float4* row = (const float4*)(g_Y + (size_t)r * DM);
    float4 xv[4];
    float s = 0.f, q = 0.f;
#pragma unroll
    for (int c = 0; c < 4; c++) {
        xv[c] = row[lane + 32 * c];
        s += xv[c].x + xv[c].y + xv[c].z + xv[c].w;
        q += xv[c].x*xv[c].x + xv[c].y*xv[c].y + xv[c].z*xv[c].z + xv[c].w*xv[c].w;
    }
#pragma unroll
    for (int off = 16; off; off >>= 1) {
        s += __shfl_xor_sync(0xffffffffu, s, off);
        q += __shfl_xor_sync(0xffffffffu, q, off);
    }
    float mu   = s * (1.f / 512.f);
    float rstd = rsqrtf(q * (1.f / 512.f) - mu * mu + 1e-5f);
    int mt = r >> 7, rr = r & 127;
    char* base = (char*)g_Yb;
#pragma unroll
    for (int c = 0; c < 4; c++) {
        float4 g4 = ((const float4*)gw)[lane + 32 * c];
        float4 b4 = ((const float4*)bw)[lane + 32 * c];
        float n0 = (xv[c].x - mu) * rstd * g4.x + b4.x;
        float n1 = (xv[c].y - mu) * rstd * g4.y + b4.y;
        float n2 = (xv[c].z - mu) * rstd * g4.z + b4.z;
        float n3 = (xv[c].w - mu) * rstd * g4.w + b4.w;
        float l0, l1, l2, l3;
        uint2 hp; hp.x = pack_hi(n0, n1, l0, l1); hp.y = pack_hi(n2, n3, l2, l3);
        uint2 lp; lp.x = pack_lo(l0, l1);         lp.y = pack_lo(l2, l3);
        int st = (lane >> 3) + 4 * c, kb = (lane & 7) * 8;
        size_t blk = ((size_t)mt * 16 + st) * 8192 + swzoff(rr, kb);
        *(uint2*)(base + blk)            = hp;
        *(uint2*)(base + 8388608u + blk) = lp;
    }
}

// ===================== launcher =====================
extern "C" void kernel_launch(void* const* d_in, const int* in_sizes, int n_in,
                              void* d_out, int out_size)
{
    const float* q      = (const float*)d_in[0];
    const float* k      = (const float*)d_in[1];
    const float* v      = (const float*)d_in[2];
    const int*   sgap   = (const int*)d_in[3];
    const int*   pcount = (const int*)d_in[4];
    const float* Wq = (const float*)d_in[5];  const float* bq = (const float*)d_in[6];
    const float* Wk = (const float*)d_in[7];  const float* bk = (const float*)d_in[8];
    const float* Wv = (const float*)d_in[9];  const float* bv = (const float*)d_in[10];
    const float* Wo = (const float*)d_in[11]; const float* bo = (const float*)d_in[12];
    const float* gammas = (const float*)d_in[13];
    const float* ln_g = (const float*)d_in[14]; const float* ln_b = (const float*)d_in[15];
    const float* Wi1 = (const float*)d_in[16];  const float* bi1 = (const float*)d_in[17];
    const float* Wi2 = (const float*)d_in[18];  const float* bi2 = (const float*)d_in[19];
    const float* iscale = (const float*)d_in[20];
    float* out = (float*)d_out;

    char *Ain, *Yb, *Hb;
    unsigned char* Wpk;
    cudaGetSymbolAddress((void**)&Ain, g_Ain);
    cudaGetSymbolAddress((void**)&Yb,  g_Yb);
    cudaGetSymbolAddress((void**)&Hb,  g_Hb);
    cudaGetSymbolAddress((void**)&Wpk, g_Wpk);

    cudaFuncSetAttribute(pgemm_kernel, cudaFuncAttributeMaxDynamicSharedMemorySize, PG_SMEM);
    cudaFuncSetAttribute(qk_kernel, cudaFuncAttributeMaxDynamicSharedMemorySize, SK_SMEM);
    cudaFuncSetAttribute(av_kernel, cudaFuncAttributeMaxDynamicSharedMemorySize, AV_SMEM);

    prep_kernel<<<14464, 256>>>(Wq, Wk, Wv, Wo, Wi2, Wpk, q, k, v);
    stats_kernel<<<32, 256>>>(sgap, pcount);

    pgemm_kernel<<<dim3(4, 64, 3), 256, PG_SMEM>>>(
        Ain, 8388608L, 16777216L, (const char*)Wpk, 524288L, 1048576L,
        512, 4, bq, bk, bv, nullptr, nullptr);

    qk_kernel<<<dim3(6, 128), 256, SK_SMEM>>>();
    row_kernel<<<dim3(64, 128), 256>>>(gammas);
    av_kernel<<<dim3(4, 128), 256, AV_SMEM>>>();

    hidden_kernel<<<2048, 256>>>(sgap, pcount, Wi1, bi1);
    pgemm_kernel<<<dim3(4, 64, 1), 256, PG_SMEM>>>(
        Hb, 2097152L, 0L, (const char*)Wpk + 4194304u, 131072L, 0L,
        128, 3, bi2, nullptr, nullptr, nullptr, iscale);

    ln_pack_kernel<<<1024, 256>>>(ln_g, ln_b);

    pgemm_kernel<<<dim3(4, 64, 1), 256, PG_SMEM>>>(
        Yb, 8388608L, 0L, (const char*)Wpk + 3145728u, 524288L, 0L,
        512, 0, bo, nullptr, nullptr, out, nullptr);
}

// round 13
// speedup vs baseline: 1.3685x; 1.0862x over previous
#include <cuda_runtime.h>
#include <cuda_bf16.h>
#include <math.h>
#include <cstdint>

#define BSZ 16
#define SEQ 512
#define DM  512
#define NH  8
#define DKH 64
#define MTOT (BSZ*SEQ)
#define NEG_INF (__int_as_float(0xff800000))
#define QKVPLN 4194304u
#define APLN 33554432u

// ===================== scratch =====================
__device__ __nv_bfloat16 g_Ain[3u*2u*4194304u];
__device__ __nv_bfloat16 g_Qb [2*QKVPLN];
__device__ __nv_bfloat16 g_Kb [2*QKVPLN];
__device__ __nv_bfloat16 g_Vtb[2*QKVPLN];
__device__ float         g_S  [APLN];
__device__ __nv_bfloat16 g_A  [2*APLN];
__device__ float g_X [MTOT*DM];
__device__ float g_Y [MTOT*DM];
__device__ __nv_bfloat16 g_Yb[2u*4194304u];
__device__ __nv_bfloat16 g_Hb[2u*1048576u];
__device__ unsigned long long g_sacc[4];
__device__ unsigned char g_Wpk[5u*1024u*1024u];

// ===================== asm helpers =====================
__device__ __forceinline__ uint32_t smem_to_u32(const void* p) {
    uint32_t a;
    asm("{ .reg .u64 t; cvta.to.shared.u64 t, %1; cvt.u32.u64 %0, t; }" : "=r"(a) : "l"(p));
    return a;
}
__device__ __forceinline__ void ldsm4(uint32_t* r, uint32_t addr) {
    asm volatile("ldmatrix.sync.aligned.m8n8.x4.shared.b16 {%0,%1,%2,%3}, [%4];"
        : "=r"(r[0]), "=r"(r[1]), "=r"(r[2]), "=r"(r[3]) : "r"(addr));
}
__device__ __forceinline__ void mma16816(float* c, const uint32_t* a, const uint32_t* b) {
    asm volatile("mma.sync.aligned.m16n8k16.row.col.f32.bf16.bf16.f32 "
        "{%0,%1,%2,%3}, {%4,%5,%6,%7}, {%8,%9}, {%0,%1,%2,%3};"
        : "+f"(c[0]), "+f"(c[1]), "+f"(c[2]), "+f"(c[3])
        : "r"(a[0]), "r"(a[1]), "r"(a[2]), "r"(a[3]), "r"(b[0]), "r"(b[1]));
}
__device__ __forceinline__ uint32_t pack_hi(float x, float y, float& lx, float& ly) {
    __nv_bfloat162 h = __floats2bfloat162_rn(x, y);
    lx = x - __bfloat162float(h.x);
    ly = y - __bfloat162float(h.y);
    return *reinterpret_cast<uint32_t*>(&h);
}
__device__ __forceinline__ uint32_t pack_lo(float lx, float ly) {
    __nv_bfloat162 l = __floats2bfloat162_rn(lx, ly);
    return *reinterpret_cast<uint32_t*>(&l);
}
__device__ __forceinline__ int swzoff(int r, int kb) {
    return r * 64 + ((((kb >> 4) ^ ((r >> 1) & 3)) << 4)) + (kb & 15);
}
#define BULK_G2S(dst, src, bytes, mbar) \
    asm volatile("cp.async.bulk.shared::cluster.global.mbarrier::complete_tx::bytes [%0], [%1], %2, [%3];" \
        :: "r"(dst), "l"(src), "r"(bytes), "r"(mbar) : "memory")
#define MBARRIER_INIT(mbar, cnt) \
    asm volatile("mbarrier.init.shared.b64 [%0], %1;" :: "r"((uint32_t)(mbar)), "r"((uint32_t)(cnt)) : "memory")
#define MBARRIER_EXPECT_TX(mbar, bytes) \
    asm volatile("mbarrier.arrive.expect_tx.shared.b64 _, [%0], %1;" :: "r"((uint32_t)(mbar)), "r"((uint32_t)(bytes)) : "memory")
#define MBARRIER_WAIT_PARITY(mbar, parity) do { \
    uint32_t _m = (uint32_t)(mbar); uint32_t _p = (uint32_t)(parity); uint32_t _d; \
    asm volatile("{\n\t.reg .pred p;\n\tmbarrier.try_wait.parity.acquire.cta.shared::cta.b64 p, [%1], %2;\n\tselp.b32 %0, 1, 0, p;\n\t}" \
        : "=r"(_d) : "r"(_m), "r"(_p) : "memory"); \
    if (!_d) { \
        asm volatile("{\n\t.reg .pred P1;\n\tWL_%=:\n\tmbarrier.try_wait.parity.acquire.cta.shared::cta.b64 P1, [%0], %1, 0x989680;\n\t@P1 bra.uni WD_%=;\n\tbra.uni WL_%=;\n\tWD_%=:\n\t}" \
            :: "r"(_m), "r"(_p) : "memory"); \
    } } while (0)

// ===================== fused prep: weight + activation pre-split ===================
__global__ __launch_bounds__(256) void prep_kernel(
    const float* __restrict__ Wq, const float* __restrict__ Wk,
    const float* __restrict__ Wv, const float* __restrict__ Wo,
    const float* __restrict__ Wi2, unsigned char* __restrict__ wdst,
    const float* __restrict__ q, const float* __restrict__ k, const float* __restrict__ v)
{
    int bb = blockIdx.x;
    if (bb < 2176) {
        if (bb == 0 && threadIdx.x < 4) g_sacc[threadIdx.x] = 0ull;
        const float* W; unsigned char* d; int K;
        if      (bb < 512)  { W = Wq;  d = wdst;              K = 512; }
        else if (bb < 1024) { W = Wk;  d = wdst + 1048576u;   K = 512; bb -= 512; }
        else if (bb < 1536) { W = Wv;  d = wdst + 2097152u;   K = 512; bb -= 1024; }
        else if (bb < 2048) { W = Wo;  d = wdst + 3145728u;   K = 512; bb -= 1536; }
        else                { W = Wi2; d = wdst + 4194304u;   K = 128; bb -= 2048; }
        int NK = (K == 512) ? 262144 : 65536;
        int S = K >> 5;
        int idx = bb * 256 + threadIdx.x;
        int halfK = K >> 1;
        int n = idx / halfK;
        int kk = (idx - n * halfK) * 2;
        float x0 = W[(size_t)n * K + kk];
        float x1 = W[(size_t)n * K + kk + 1];
        float lx, ly;
        uint32_t hp = pack_hi(x0, x1, lx, ly);
        uint32_t lp = pack_lo(lx, ly);
        int nt = n >> 7, rr = n & 127, st = kk >> 5, kb = (kk & 31) * 2;
        size_t blk = ((size_t)nt * S + st) * 8192 + swzoff(rr, kb);
        *(uint32_t*)(d + blk)                  = hp;
        *(uint32_t*)(d + (size_t)NK * 2 + blk) = lp;
    } else {
        int a = bb - 2176;
        int zy = a >> 12, zx = a & 4095;
        const float* src = zy == 0 ? q : zy == 1 ? k : v;
        char* dst = (char*)g_Ain + (size_t)zy * 16777216u;
        size_t e = ((size_t)zx * 256 + threadIdx.x) * 4;
        float4 x = *(const float4*)(src + e);
        float l0, l1, l2, l3;
        uint2 hp; hp.x = pack_hi(x.x, x.y, l0, l1); hp.y = pack_hi(x.z, x.w, l2, l3);
        uint2 lp; lp.x = pack_lo(l0, l1);           lp.y = pack_lo(l2, l3);
        int r = (int)(e >> 9), kk = (int)(e & 511);
        int mt = r >> 7, rr = r & 127, st = kk >> 5, kb = (kk & 31) * 2;
        size_t blk = ((size_t)mt * 16 + st) * 8192 + swzoff(rr, kb);
        *(uint2*)(dst + blk)            = hp;
        *(uint2*)(dst + 8388608u + blk) = lp;
    }
}

// ===================== unified pre-packed GEMM (2-deep bulk pipeline) ==============
#define PGB 32768
#define PG_SMEM (2*PGB + 64)

__global__ __launch_bounds__(256, 2) void pgemm_kernel(
    const char* __restrict__ Ab0, long Apl, long Az,
    const char* __restrict__ Bb0, long Bpl, long Bz,
    int K, int mode0,
    const float* __restrict__ b0, const float* __restrict__ b1, const float* __restrict__ b2,
    float* __restrict__ C, const float* __restrict__ scale)
{
    extern __shared__ char sm[];
    const uint32_t sbase = smem_to_u32(sm);
    const uint32_t mb0 = sbase + 2 * PGB, mb1 = mb0 + 8;
    const int tid = threadIdx.x, wid = tid >> 5, lane = tid & 31;
    const int bx = blockIdx.x, by = blockIdx.y, z = blockIdx.z;
    const int mode = mode0 + z;
    const char* Ab = Ab0 + (size_t)z * Az;
    const char* Bb = Bb0 + (size_t)z * Bz;
    const float* bias = (z == 0) ? b0 : (z == 1) ? b1 : b2;
    const int S = K >> 5;
    const int bm = by * 128, bn = bx * 128;

    if (tid == 0) { MBARRIER_INIT(mb0, 1); MBARRIER_INIT(mb1, 1); }
    __syncthreads();

    float acc[16][4];
#pragma unroll
    for (int i = 0; i < 16; i++)
#pragma unroll
        for (int j = 0; j < 4; j++) acc[i][j] = 0.f;

    auto issue = [&](int s, int buf) {
        uint32_t mb = buf ? mb1 : mb0;
        uint32_t d = sbase + buf * PGB;
        MBARRIER_EXPECT_TX(mb, 32768);
        const char* As = Ab + (((size_t)by * S + s) << 13);
        const char* Bs = Bb + (((size_t)bx * S + s) << 13);
        BULK_G2S(d,         As,       8192, mb);
        BULK_G2S(d + 8192,  As + Apl, 8192, mb);
        BULK_G2S(d + 16384, Bs,       8192, mb);
        BULK_G2S(d + 24576, Bs + Bpl, 8192, mb);
    };

    const int wm = (wid >> 2) * 64, wn = (wid & 3) * 32;
    const int boff_n = ((lane >> 4) << 3) + (lane & 7);

    auto compute = [&](int buf) {
        uint32_t Ahi = sbase + buf * PGB;
        uint32_t Bhi = Ahi + 16384;
#pragma unroll
        for (int kh = 0; kh < 2; kh++) {
            const int qa = (kh * 2 + (lane >> 4)) << 4;
            const int qb = (kh * 2 + ((lane >> 3) & 1)) << 4;
            uint32_t bh[8], bl[8], a[16];
#pragma unroll
            for (int nf2 = 0; nf2 < 2; nf2++) {
                int rb = wn + nf2 * 16 + boff_n;
                uint32_t baddr = Bhi + swzoff(rb, qb);
                ldsm4(bh + nf2 * 4, baddr);
                ldsm4(bl + nf2 * 4, baddr + 8192);
            }
#pragma unroll
            for (int mf = 0; mf < 4; mf++) {
                int ra = wm + mf * 16 + (lane & 15);
                ldsm4(a + mf * 4, Ahi + swzoff(ra, qa));
            }
#pragma unroll
            for (int mf = 0; mf < 4; mf++)
#pragma unroll
                for (int nf = 0; nf < 4; nf++)
                    mma16816(acc[mf * 4 + nf], a + mf * 4, bh + nf * 2);
#pragma unroll
            for (int mf = 0; mf < 4; mf++)
#pragma unroll
                for (int nf = 0; nf < 4; nf++)
                    mma16816(acc[mf * 4 + nf], a + mf * 4, bl + nf * 2);
#pragma unroll
            for (int mf = 0; mf < 4; mf++) {
                int ra = wm + mf * 16 + (lane & 15);
                ldsm4(a + mf * 4, Ahi + 8192 + swzoff(ra, qa));
            }
#pragma unroll
            for (int mf = 0; mf < 4; mf++)
#pragma unroll
                for (int nf = 0; nf < 4; nf++)
                    mma16816(acc[mf * 4 + nf], a + mf * 4, bh + nf * 2);
        }
    };

    if (tid == 0) issue(0, 0);
    for (int s = 0; s < S; s++) {
        if (s + 1 < S && tid == 0) issue(s + 1, (s + 1) & 1);
        MBARRIER_WAIT_PARITY((s & 1) ? mb1 : mb0, (s >> 1) & 1);
        compute(s & 1);
        __syncthreads();
    }

    const float isc = (mode == 3) ? scale[0] : 0.f;
#pragma unroll
    for (int mf = 0; mf < 4; mf++) {
#pragma unroll
        for (int nf = 0; nf < 4; nf++) {
            float* cc = acc[mf * 4 + nf];
            int col = bn + wn + nf * 8 + (lane & 3) * 2;
            float bv0 = bias[col], bv1 = bias[col + 1];
#pragma unroll
            for (int rp = 0; rp < 2; rp++) {
                int m = bm + wm + mf * 16 + (lane >> 2) + rp * 8;
                float v0 = cc[rp * 2 + 0] + bv0;
                float v1 = cc[rp * 2 + 1] + bv1;
                if (mode == 0) {
                    *(float2*)(C + (size_t)m * DM + col) = make_float2(v0, v1);
                } else if (mode == 3) {
                    const float* ad = g_X + (size_t)m * DM + col;
                    *(float2*)(g_Y + (size_t)m * DM + col) =
                        make_float2(ad[0] + isc * v0, ad[1] + isc * v1);
                } else if (mode == 4 || mode == 5) {
                    if (mode == 4) { v0 *= 0.125f; v1 *= 0.125f; }
                    int bb = m >> 9, si = m & 511, hh = col >> 6, d = col & 63;
                    int bh_ = bb * 8 + hh, mt = si >> 7, rr = si & 127;
                    int st = d >> 5, kb = (d & 31) * 2;
                    size_t blk = (((size_t)(bh_ * 4 + mt) * 2 + st) << 13) + swzoff(rr, kb);
                    char* base = (mode == 4) ? (char*)g_Qb : (char*)g_Kb;
                    float l0, l1;
                    uint32_t hp = pack_hi(v0, v1, l0, l1);
                    uint32_t lp = pack_lo(l0, l1);
                    *(uint32_t*)(base + blk)            = hp;
                    *(uint32_t*)(base + 8388608u + blk) = lp;
                } else {
                    int bb = m >> 9, si = m & 511, hh = col >> 6, d = col & 63;
                    int bh_ = bb * 8 + hh, st = si >> 5, kb = (si & 31) * 2;
                    size_t blk = ((size_t)(bh_ * 16 + st)) * 4096;
                    char* base = (char*)g_Vtb;
                    __nv_bfloat16 h0 = __float2bfloat16(v0);
                    __nv_bfloat16 h1 = __float2bfloat16(v1);
                    int o0 = swzoff(d, kb), o1 = swzoff(d + 1, kb);
                    *(__nv_bfloat16*)(base + blk + o0) = h0;
                    *(__nv_bfloat16*)(base + 8388608u + blk + o0) =
                        __float2bfloat16(v0 - __bfloat162float(h0));
                    *(__nv_bfloat16*)(base + blk + o1) = h1;
                    *(__nv_bfloat16*)(base + 8388608u + blk + o1) =
                        __float2bfloat16(v1 - __bfloat162float(h1));
                }
            }
        }
    }
}

// ===================== QK^T: paired tiles per Q-strip =============================
#define SK_SMEM (98304 + 64)

__global__ __launch_bounds__(256, 2) void qk_kernel()
{
    extern __shared__ char sm[];
    const uint32_t sbase = smem_to_u32(sm);
    const uint32_t mbb = sbase + 98304;
    const int t = blockIdx.x;
    const int by  = (t >= 4) ? 3 : (t >= 2) ? 2 : t;
    const int bx0 = (t == 3 || t == 5) ? 2 : 0;
    const int ntl = (t == 0 || t == 3) ? 1 : 2;
    const int bm = by * 128;
    const int bh = blockIdx.y;
    const int tid = threadIdx.x, wid = tid >> 5, lane = tid & 31;

    if (tid == 0) {
        MBARRIER_INIT(mbb, 1); MBARRIER_INIT(mbb + 8, 1);
        asm volatile("fence.proxy.async.shared::cta;" ::: "memory");
        const char* Qb = (const char*)g_Qb;
        const char* Kb = (const char*)g_Kb;
        MBARRIER_EXPECT_TX(mbb, 65536);
#pragma unroll
        for (int p = 0; p < 2; p++)
#pragma unroll
            for (int s = 0; s < 2; s++) {
                const char* qsrc = Qb + (size_t)p * 8388608u + (((size_t)(bh * 4 + by) * 2 + s) << 13);
                const char* ksrc = Kb + (size_t)p * 8388608u + (((size_t)(bh * 4 + bx0) * 2 + s) << 13);
                BULK_G2S(sbase + p * 16384 + s * 8192,         qsrc, 8192, mbb);
                BULK_G2S(sbase + 32768 + p * 16384 + s * 8192, ksrc, 8192, mbb);
            }
        if (ntl == 2) {
            MBARRIER_EXPECT_TX(mbb + 8, 32768);
#pragma unroll
            for (int p = 0; p < 2; p++)
#pragma unroll
                for (int s = 0; s < 2; s++) {
                    const char* ksrc = Kb + (size_t)p * 8388608u + (((size_t)(bh * 4 + bx0 + 1) * 2 + s) << 13);
                    BULK_G2S(sbase + 65536 + p * 16384 + s * 8192, ksrc, 8192, mbb + 8);
                }
        }
    }
    __syncthreads();

    const int wm = (wid >> 2) * 64, wn = (wid & 3) * 32;
    const int boff_n = ((lane >> 4) << 3) + (lane & 7);

    for (int ti = 0; ti < ntl; ti++) {
        MBARRIER_WAIT_PARITY(mbb + ti * 8, 0);
        const uint32_t Kbuf = sbase + 32768 + ti * 32768;
        const int bn = (bx0 + ti) * 128;

        float acc[16][4];
#pragma unroll
        for (int i = 0; i < 16; i++)
#pragma unroll
            for (int j = 0; j < 4; j++) acc[i][j] = 0.f;

#pragma unroll
        for (int kh = 0; kh < 4; kh++) {
            const int chunk = (kh >> 1) * 8192;
            const int qa = ((kh & 1) * 2 + (lane >> 4)) << 4;
            const int qb = ((kh & 1) * 2 + ((lane >> 3) & 1)) << 4;
            uint32_t bh_[8], bl_[8], a[16];
#pragma unroll
            for (int nf2 = 0; nf2 < 2; nf2++) {
                int rb = wn + nf2 * 16 + boff_n;
                uint32_t baddr = Kbuf + chunk + swzoff(rb, qb);
                ldsm4(bh_ + nf2 * 4, baddr);
                ldsm4(bl_ + nf2 * 4, baddr + 16384);
            }
#pragma unroll
            for (int mf = 0; mf < 4; mf++) {
                int ra = wm + mf * 16 + (lane & 15);
                ldsm4(a + mf * 4, sbase + chunk + swzoff(ra, qa));
            }
#pragma unroll
            for (int mf = 0; mf < 4; mf++)
#pragma unroll
                for (int nf = 0; nf < 4; nf++)
                    mma16816(acc[mf * 4 + nf], a + mf * 4, bh_ + nf * 2);
#pragma unroll
            for (int mf = 0; mf < 4; mf++)
#pragma unroll
                for (int nf = 0; nf < 4; nf++)
                    mma16816(acc[mf * 4 + nf], a + mf * 4, bl_ + nf * 2);
#pragma unroll
            for (int mf = 0; mf < 4; mf++) {
                int ra = wm + mf * 16 + (lane & 15);
                ldsm4(a + mf * 4, sbase + 16384 + chunk + swzoff(ra, qa));
            }
#pragma unroll
            for (int mf = 0; mf < 4; mf++)
#pragma unroll
                for (int nf = 0; nf < 4; nf++)
                    mma16816(acc[mf * 4 + nf], a + mf * 4, bh_ + nf * 2);
        }

        float* Sp = g_S + (size_t)bh * 512 * 512;
#pragma unroll
        for (int mf = 0; mf < 4; mf++)
#pragma unroll
            for (int nf = 0; nf < 4; nf++) {
                float* cc = acc[mf * 4 + nf];
                int col = bn + wn + nf * 8 + (lane & 3) * 2;
#pragma unroll
                for (int rp = 0; rp < 2; rp++) {
                    int m = bm + wm + mf * 16 + (lane >> 2) + rp * 8;
                    *(float2*)(Sp + (size_t)m * 512 + col) =
                        make_float2(cc[rp * 2], cc[rp * 2 + 1]);
                }
            }
    }
}

// ===================== row kernel (causal-truncated tiles) =========================
__global__ __launch_bounds__(256) void row_kernel(const float* __restrict__ gammas)
{
    const int bh = blockIdx.y, h = bh & 7;
    const int wid = threadIdx.x >> 5, lane = threadIdx.x & 31;
    const int i = blockIdx.x * 8 + wid;
    const int Ti = i >> 7;
    const int mt = i >> 7, rr = i & 127;
    char* Abase = (char*)g_A;

    if (i == 0) {
        uint2 zz = make_uint2(0u, 0u);
        int st = lane >> 3, kb = (lane & 7) * 8;
        size_t blk = ((size_t)(bh * 4 + 0) * 16 + st) * 8192 + swzoff(0, kb);
        *(uint2*)(Abase + blk)             = zz;
        *(uint2*)(Abase + 67108864u + blk) = zz;
        return;
    }

    float gv = gammas[h];
    float gam = -(fmaxf(gv, 0.f) + log1pf(__expf(-fabsf(gv))));

    const float4* Srow = (const float4*)(g_S + ((size_t)bh * 512 + i) * 512);
    float sc[4][4], e[4][4], ls[4];
#pragma unroll
    for (int t = 0; t < 4; t++) {
        if (t > Ti) { ls[t] = 0.f; continue; }
        float4 sv = Srow[lane + 32 * t];
        int j0 = 4 * (lane + 32 * t);
        sc[t][0] = (j0 + 0 < i) ? sv.x : NEG_INF;
        sc[t][1] = (j0 + 1 < i) ? sv.y : NEG_INF;
        sc[t][2] = (j0 + 2 < i) ? sv.z : NEG_INF;
        sc[t][3] = (j0 + 3 < i) ? sv.w : NEG_INF;
    }

    float m = NEG_INF;
#pragma unroll
    for (int t = 0; t < 4; t++) {
        if (t > Ti) break;
#pragma unroll
        for (int l = 0; l < 4; l++) m = fmaxf(m, sc[t][l]);
    }
#pragma unroll
    for (int off = 16; off; off >>= 1)
        m = fmaxf(m, __shfl_xor_sync(0xffffffffu, m, off));

#pragma unroll
    for (int t = 0; t < 4; t++) {
        if (t > Ti) break;
        ls[t] = 0.f;
#pragma unroll
        for (int l = 0; l < 4; l++) { e[t][l] = __expf(sc[t][l] - m); ls[t] += e[t][l]; }
    }
    float excl[4], tot[4];
#pragma unroll
    for (int t = 0; t < 4; t++) {
        if (t > Ti) break;
        float x = ls[t];
#pragma unroll
        for (int off = 1; off < 32; off <<= 1) {
            float y = __shfl_up_sync(0xffffffffu, x, off);
            if (lane >= off) x += y;
        }
        excl[t] = x - ls[t];
        tot[t]  = __shfl_sync(0xffffffffu, x, 31);
    }
    float baseA[4], T = 0.f;
#pragma unroll
    for (int t = 0; t < 4; t++) {
        if (t > Ti) break;
        baseA[t] = T; T += tot[t];
    }
    float invT = 1.f / T;

#pragma unroll
    for (int t = 0; t < 4; t++) {
        if (t > Ti) break;
        float run = baseA[t] + excl[t];
#pragma unroll
        for (int l = 0; l < 4; l++) {
            run += e[t][l];
            int j = 4 * lane + 128 * t + l;
            float suf  = fmaxf(T - run, 0.f);
            float dist = sqrtf(fmaxf(suf * invT * (float)(i - j), 0.f));
            float tmp  = __expf(dist * gam);
            tmp = fminf(fmaxf(tmp, 1e-5f), 1e5f);
            sc[t][l] = (j < i) ? sc[t][l] * tmp : NEG_INF;
        }
    }

    float m2 = NEG_INF;
#pragma unroll
    for (int t = 0; t < 4; t++) {
        if (t > Ti) break;
#pragma unroll
        for (int l = 0; l < 4; l++) m2 = fmaxf(m2, sc[t][l]);
    }
#pragma unroll
    for (int off = 16; off; off >>= 1)
        m2 = fmaxf(m2, __shfl_xor_sync(0xffffffffu, m2, off));
    float Z = 0.f;
#pragma unroll
    for (int t = 0; t < 4; t++) {
        if (t > Ti) break;
#pragma unroll
        for (int l = 0; l < 4; l++) { e[t][l] = __expf(sc[t][l] - m2); Z += e[t][l]; }
    }
#pragma unroll
    for (int off = 16; off; off >>= 1)
        Z += __shfl_xor_sync(0xffffffffu, Z, off);
    float invZ = 1.f / Z;

#pragma unroll
    for (int t = 0; t < 4; t++) {
        if (t > Ti) break;
        float a0 = e[t][0] * invZ, a1 = e[t][1] * invZ;
        float a2 = e[t][2] * invZ, a3 = e[t][3] * invZ;
        float l0, l1, l2, l3;
        uint2 hp; hp.x = pack_hi(a0, a1, l0, l1); hp.y = pack_hi(a2, a3, l2, l3);
        uint2 lp; lp.x = pack_lo(l0, l1);         lp.y = pack_lo(l2, l3);
        int st = (lane >> 3) + 4 * t, kb = (lane & 7) * 8;
        size_t blk = ((size_t)(bh * 4 + mt) * 16 + st) * 8192 + swzoff(rr, kb);
        *(uint2*)(Abase + blk)             = hp;
        *(uint2*)(Abase + 67108864u + blk) = lp;
    }
}

// ===================== AV batched GEMM (2-deep bulk pipeline, causal) =============
#define AVB 24576
#define AV_SMEM (2*AVB + 64)

__global__ __launch_bounds__(256, 2) void av_kernel()
{
    extern __shared__ char sm[];
    const uint32_t sbase = smem_to_u32(sm);
    const uint32_t mb0 = sbase + 2 * AVB, mb1 = mb0 + 8;
    const int mt = blockIdx.x;
    const int bm = mt * 128;
    const int bh = blockIdx.y;
    const int b = bh >> 3, h = bh & 7;
    const int tid = threadIdx.x, wid = tid >> 5, lane = tid & 31;
    const int nst = (bm + 128) >> 5;

    if (tid == 0) { MBARRIER_INIT(mb0, 1); MBARRIER_INIT(mb1, 1); }
    __syncthreads();

    float acc[8][4];
#pragma unroll
    for (int i = 0; i < 8; i++)
#pragma unroll
        for (int j = 0; j < 4; j++) acc[i][j] = 0.f;

    auto issue = [&](int s, int buf) {
        uint32_t mb = buf ? mb1 : mb0;
        uint32_t d = sbase + buf * AVB;
        MBARRIER_EXPECT_TX(mb, 24576);
        const char* Ap = (const char*)g_A + (((size_t)(bh * 4 + mt) * 16 + s) << 13);
        const char* Vp = (const char*)g_Vtb + ((size_t)(bh * 16 + s)) * 4096;
        BULK_G2S(d,         Ap,              8192, mb);
        BULK_G2S(d + 8192,  Ap + 67108864u,  8192, mb);
        BULK_G2S(d + 16384, Vp,              4096, mb);
        BULK_G2S(d + 20480, Vp + 8388608u,   4096, mb);
    };

    const int wm = (wid >> 1) * 32, wn = (wid & 1) * 32;
    const int boff_n = ((lane >> 4) << 3) + (lane & 7);

    auto compute = [&](int buf) {
        uint32_t Ab = sbase + buf * AVB;
        uint32_t Vb = Ab + 16384;
#pragma unroll
        for (int kh = 0; kh < 2; kh++) {
            const int qa = (kh * 2 + (lane >> 4)) << 4;
            const int qb = (kh * 2 + ((lane >> 3) & 1)) << 4;
            uint32_t bh_[8], bl_[8], a[8];
#pragma unroll
            for (int nf2 = 0; nf2 < 2; nf2++) {
                int rb = wn + nf2 * 16 + boff_n;
                uint32_t baddr = Vb + swzoff(rb, qb);
                ldsm4(bh_ + nf2 * 4, baddr);
                ldsm4(bl_ + nf2 * 4, baddr + 4096);
            }
#pragma unroll
            for (int mf = 0; mf < 2; mf++) {
                int ra = wm + mf * 16 + (lane & 15);
                ldsm4(a + mf * 4, Ab + swzoff(ra, qa));
            }
#pragma unroll
            for (int mf = 0; mf < 2; mf++)
#pragma unroll
                for (int nf = 0; nf < 4; nf++)
                    mma16816(acc[mf * 4 + nf], a + mf * 4, bh_ + nf * 2);
#pragma unroll
            for (int mf = 0; mf < 2; mf++)
#pragma unroll
                for (int nf = 0; nf < 4; nf++)
                    mma16816(acc[mf * 4 + nf], a + mf * 4, bl_ + nf * 2);
#pragma unroll
            for (int mf = 0; mf < 2; mf++) {
                int ra = wm + mf * 16 + (lane & 15);
                ldsm4(a + mf * 4, Ab + 8192 + swzoff(ra, qa));
            }
#pragma unroll
            for (int mf = 0; mf < 2; mf++)
#pragma unroll
                for (int nf = 0; nf < 4; nf++)
                    mma16816(acc[mf * 4 + nf], a + mf * 4, bh_ + nf * 2);
        }
    };

    if (tid == 0) issue(0, 0);
    for (int s = 0; s < nst; s++) {
        if (s + 1 < nst && tid == 0) issue(s + 1, (s + 1) & 1);
        MBARRIER_WAIT_PARITY((s & 1) ? mb1 : mb0, (s >> 1) & 1);
        compute(s & 1);
        __syncthreads();
    }

#pragma unroll
    for (int mf = 0; mf < 2; mf++)
#pragma unroll
        for (int nf = 0; nf < 4; nf++) {
            float* cc = acc[mf * 4 + nf];
            int col = wn + nf * 8 + (lane & 3) * 2;
#pragma unroll
            for (int rp = 0; rp < 2; rp++) {
                int mrow = bm + wm + mf * 16 + (lane >> 2) + rp * 8;
                *(float2*)(g_X + ((size_t)(b * 512 + mrow)) * 512 + h * 64 + col) =
                    make_float2(cc[rp * 2], cc[rp * 2 + 1]);
            }
        }
}

// ===================== parallel norm01 stats =====================
__global__ __launch_bounds__(256) void stats_kernel(
    const int* __restrict__ sgap, const int* __restrict__ pcount)
{
    __shared__ long long sh[32];
    int idx = blockIdx.x * 256 + threadIdx.x;
    long long a = sgap[idx], b = pcount[idx];
    long long s0 = a, q0 = a * a, s1 = b, q1 = b * b;
#pragma unroll
    for (int off = 16; off; off >>= 1) {
        s0 += __shfl_xor_sync(0xffffffffu, s0, off);
        q0 += __shfl_xor_sync(0xffffffffu, q0, off);
        s1 += __shfl_xor_sync(0xffffffffu, s1, off);
        q1 += __shfl_xor_sync(0xffffffffu, q1, off);
    }
    int wd = threadIdx.x >> 5, ln = threadIdx.x & 31;
    if (ln == 0) { sh[wd] = s0; sh[8+wd] = q0; sh[16+wd] = s1; sh[24+wd] = q1; }
    __syncthreads();
    if (threadIdx.x == 0) {
        long long S0=0,Q0=0,S1=0,Q1=0;
        for (int i = 0; i < 8; i++) { S0+=sh[i]; Q0+=sh[8+i]; S1+=sh[16+i]; Q1+=sh[24+i]; }
        atomicAdd(&g_sacc[0], (unsigned long long)S0);
        atomicAdd(&g_sacc[1], (unsigned long long)Q0);
        atomicAdd(&g_sacc[2], (unsigned long long)S1);
        atomicAdd(&g_sacc[3], (unsigned long long)Q1);
    }
}

// ===================== interference hidden layer -> bf16 blocks ===================
__global__ __launch_bounds__(256) void hidden_kernel(
    const int* __restrict__ sgap, const int* __restrict__ pcount,
    const float* __restrict__ Wi1, const float* __restrict__ bi1)
{
    float n = (float)MTOT;
    float S0 = (float)(long long)g_sacc[0], Q0 = (float)(long long)g_sacc[1];
    float S1 = (float)(long long)g_sacc[2], Q1 = (float)(long long)g_sacc[3];
    float m0 = S0 / n, m1 = S1 / n;
    float v0 = (Q0 - n*m0*m0) / (n - 1.f);
    float v1 = (Q1 - n*m1*m1) / (n - 1.f);
    float inv0 = 1.f / (sqrtf(fmaxf(v0, 0.f)) + 1e-6f);
    float inv1 = 1.f / (sqrtf(fmaxf(v1, 0.f)) + 1e-6f);

    int idx = blockIdx.x * 256 + threadIdx.x;
    int r = idx >> 6, c2 = (idx & 63) * 2;
    float ii0 = 0.5f * (tanhf(((float)sgap[r]   - m0) * inv0) + 1.f);
    float ii1 = 0.5f * (tanhf(((float)pcount[r] - m1) * inv1) + 1.f);
    float h0 = fmaxf(ii0 * Wi1[2*c2+0] + ii1 * Wi1[2*c2+1] + bi1[c2],   0.f);
    float h1 = fmaxf(ii0 * Wi1[2*c2+2] + ii1 * Wi1[2*c2+3] + bi1[c2+1], 0.f);
    float l0, l1;
    uint32_t hp = pack_hi(h0, h1, l0, l1);
    uint32_t lp = pack_lo(l0, l1);
    int mt = r >> 7, rr = r & 127, st = c2 >> 5, kb = (c2 & 31) * 2;
    size_t blk = ((size_t)mt * 4 + st) * 8192 + swzoff(rr, kb);
    char* base = (char*)g_Hb;
    *(uint32_t*)(base + blk)            = hp;
    *(uint32_t*)(base + 2097152u + blk) = lp;
}

// ===================== LayerNorm + pack to bf16 blocks ============================
__global__ __launch_bounds__(256) void ln_pack_kernel(
    const float* __restrict__ gw, const float* __restrict__ bw)
{
    int r = blockIdx.x * 8 + (threadIdx.x >> 5);
    int lane = threadIdx.x & 31;
    const float4* row = (const float4*)(g_Y + (size_t)r * DM);
    float4 xv[4];
    float s = 0.f, q = 0.f;
#pragma unroll
    for (int c = 0; c < 4; c++) {
        xv[c] = row[lane + 32 * c];
        s += xv[c].x + xv[c].y + xv[c].z + xv[c].w;
        q += xv[c].x*xv[c].x + xv[c].y*xv[c].y + xv[c].z*xv[c].z + xv[c].w*xv[c].w;
    }
#pragma unroll
    for (int off = 16; off; off >>= 1) {
        s += __shfl_xor_sync(0xffffffffu, s, off);
        q += __shfl_xor_sync(0xffffffffu, q, off);
    }
    float mu   = s * (1.f / 512.f);
    float rstd = rsqrtf(q * (1.f / 512.f) - mu * mu + 1e-5f);
    int mt = r >> 7, rr = r & 127;
    char* base = (char*)g_Yb;
#pragma unroll
    for (int c = 0; c < 4; c++) {
        float4 g4 = ((const float4*)gw)[lane + 32 * c];
        float4 b4 = ((const float4*)bw)[lane + 32 * c];
        float n0 = (xv[c].x - mu) * rstd * g4.x + b4.x;
        float n1 = (xv[c].y - mu) * rstd * g4.y + b4.y;
        float n2 = (xv[c].z - mu) * rstd * g4.z + b4.z;
        float n3 = (xv[c].w - mu) * rstd * g4.w + b4.w;
        float l0, l1, l2, l3;
        uint2 hp; hp.x = pack_hi(n0, n1, l0, l1); hp.y = pack_hi(n2, n3, l2, l3);
        uint2 lp; lp.x = pack_lo(l0, l1);         lp.y = pack_lo(l2, l3);
        int st = (lane >> 3) + 4 * c, kb = (lane & 7) * 8;
        size_t blk = ((size_t)mt * 16 + st) * 8192 + swzoff(rr, kb);
        *(uint2*)(base + blk)            = hp;
        *(uint2*)(base + 8388608u + blk) = lp;
    }
}

// ===================== launcher (fork/join stream overlap) =========================
extern "C" void kernel_launch(void* const* d_in, const int* in_sizes, int n_in,
                              void* d_out, int out_size)
{
    const float* q      = (const float*)d_in[0];
    const float* k      = (const float*)d_in[1];
    const float* v      = (const float*)d_in[2];
    const int*   sgap   = (const int*)d_in[3];
    const int*   pcount = (const int*)d_in[4];
    const float* Wq = (const float*)d_in[5];  const float* bq = (const float*)d_in[6];
    const float* Wk = (const float*)d_in[7];  const float* bk = (const float*)d_in[8];
    const float* Wv = (const float*)d_in[9];  const float* bv = (const float*)d_in[10];
    const float* Wo = (const float*)d_in[11]; const float* bo = (const float*)d_in[12];
    const float* gammas = (const float*)d_in[13];
    const float* ln_g = (const float*)d_in[14]; const float* ln_b = (const float*)d_in[15];
    const float* Wi1 = (const float*)d_in[16];  const float* bi1 = (const float*)d_in[17];
    const float* Wi2 = (const float*)d_in[18];  const float* bi2 = (const float*)d_in[19];
    const float* iscale = (const float*)d_in[20];
    float* out = (float*)d_out;

    char *Ain, *Yb, *Hb;
    unsigned char* Wpk;
    cudaGetSymbolAddress((void**)&Ain, g_Ain);
    cudaGetSymbolAddress((void**)&Yb,  g_Yb);
    cudaGetSymbolAddress((void**)&Hb,  g_Hb);
    cudaGetSymbolAddress((void**)&Wpk, g_Wpk);

    cudaFuncSetAttribute(pgemm_kernel, cudaFuncAttributeMaxDynamicSharedMemorySize, PG_SMEM);
    cudaFuncSetAttribute(qk_kernel, cudaFuncAttributeMaxDynamicSharedMemorySize, SK_SMEM);
    cudaFuncSetAttribute(av_kernel, cudaFuncAttributeMaxDynamicSharedMemorySize, AV_SMEM);

    cudaStream_t s2;
    cudaStreamCreateWithFlags(&s2, cudaStreamNonBlocking);
    cudaEvent_t eP, eV;
    cudaEventCreateWithFlags(&eP, cudaEventDisableTiming);
    cudaEventCreateWithFlags(&eV, cudaEventDisableTiming);

    // main stream: prep (weights+activations+sacc zero)
    prep_kernel<<<14464, 256>>>(Wq, Wk, Wv, Wo, Wi2, Wpk, q, k, v);
    cudaEventRecord(eP, 0);
    cudaStreamWaitEvent(s2, eP, 0);

    // side stream: stats -> V projection -> hidden
    stats_kernel<<<32, 256, 0, s2>>>(sgap, pcount);
    pgemm_kernel<<<dim3(4, 64, 1), 256, PG_SMEM, s2>>>(
        Ain + 2u*16777216u, 8388608L, 0L, (const char*)Wpk + 2097152u, 524288L, 0L,
        512, 6, bv, nullptr, nullptr, nullptr, nullptr);
    hidden_kernel<<<2048, 256, 0, s2>>>(sgap, pcount, Wi1, bi1);
    cudaEventRecord(eV, s2);

    // main stream: Q,K projections -> qk -> row
    pgemm_kernel<<<dim3(4, 64, 2), 256, PG_SMEM>>>(
        Ain, 8388608L, 16777216L, (const char*)Wpk, 524288L, 1048576L,
        512, 4, bq, bk, nullptr, nullptr, nullptr);
    qk_kernel<<<dim3(6, 128), 256, SK_SMEM>>>();
    row_kernel<<<dim3(64, 128), 256>>>(gammas);

    // join: av needs V^T (s2) and A (main)
    cudaStreamWaitEvent(0, eV, 0);
    av_kernel<<<dim3(4, 128), 256, AV_SMEM>>>();

    pgemm_kernel<<<dim3(4, 64, 1), 256, PG_SMEM>>>(
        Hb, 2097152L, 0L, (const char*)Wpk + 4194304u, 131072L, 0L,
        128, 3, bi2, nullptr, nullptr, nullptr, iscale);

    ln_pack_kernel<<<1024, 256>>>(ln_g, ln_b);

    pgemm_kernel<<<dim3(4, 64, 1), 256, PG_SMEM>>>(
        Yb, 8388608L, 0L, (const char*)Wpk + 3145728u, 524288L, 0L,
        512, 0, bo, nullptr, nullptr, out, nullptr);
}

// round 15
// speedup vs baseline: 1.4384x; 1.0511x over previous
#include <cuda_runtime.h>
#include <cuda_bf16.h>
#include <math.h>
#include <cstdint>

#define BSZ 16
#define SEQ 512
#define DM  512
#define NH  8
#define DKH 64
#define MTOT (BSZ*SEQ)
#define NEG_INF (__int_as_float(0xff800000))
#define QKVPLN 4194304u
#define APLN 33554432u

// ===================== scratch =====================
__device__ __nv_bfloat16 g_Ain[3u*2u*4194304u];
__device__ __nv_bfloat16 g_Qb [2*QKVPLN];
__device__ __nv_bfloat16 g_Kb [2*QKVPLN];
__device__ __nv_bfloat16 g_Vtb[2*QKVPLN];
__device__ float         g_S  [APLN];
__device__ __nv_bfloat16 g_A  [2*APLN];
__device__ float g_X [MTOT*DM];
__device__ float g_Y [MTOT*DM];          // holds F = iscale*(H@Wi2^T + bi2)
__device__ __nv_bfloat16 g_Yb[2u*4194304u];
__device__ __nv_bfloat16 g_Hb[2u*1048576u];
__device__ unsigned long long g_sacc[4];
__device__ unsigned char g_Wpk[5u*1024u*1024u];

// ===================== asm helpers =====================
__device__ __forceinline__ uint32_t smem_to_u32(const void* p) {
    uint32_t a;
    asm("{ .reg .u64 t; cvta.to.shared.u64 t, %1; cvt.u32.u64 %0, t; }" : "=r"(a) : "l"(p));
    return a;
}
__device__ __forceinline__ void ldsm4(uint32_t* r, uint32_t addr) {
    asm volatile("ldmatrix.sync.aligned.m8n8.x4.shared.b16 {%0,%1,%2,%3}, [%4];"
        : "=r"(r[0]), "=r"(r[1]), "=r"(r[2]), "=r"(r[3]) : "r"(addr));
}
__device__ __forceinline__ void mma16816(float* c, const uint32_t* a, const uint32_t* b) {
    asm volatile("mma.sync.aligned.m16n8k16.row.col.f32.bf16.bf16.f32 "
        "{%0,%1,%2,%3}, {%4,%5,%6,%7}, {%8,%9}, {%0,%1,%2,%3};"
        : "+f"(c[0]), "+f"(c[1]), "+f"(c[2]), "+f"(c[3])
        : "r"(a[0]), "r"(a[1]), "r"(a[2]), "r"(a[3]), "r"(b[0]), "r"(b[1]));
}
__device__ __forceinline__ uint32_t pack_hi(float x, float y, float& lx, float& ly) {
    __nv_bfloat162 h = __floats2bfloat162_rn(x, y);
    lx = x - __bfloat162float(h.x);
    ly = y - __bfloat162float(h.y);
    return *reinterpret_cast<uint32_t*>(&h);
}
__device__ __forceinline__ uint32_t pack_lo(float lx, float ly) {
    __nv_bfloat162 l = __floats2bfloat162_rn(lx, ly);
    return *reinterpret_cast<uint32_t*>(&l);
}
__device__ __forceinline__ int swzoff(int r, int kb) {
    return r * 64 + ((((kb >> 4) ^ ((r >> 1) & 3)) << 4)) + (kb & 15);
}
#define BULK_G2S(dst, src, bytes, mbar) \
    asm volatile("cp.async.bulk.shared::cluster.global.mbarrier::complete_tx::bytes [%0], [%1], %2, [%3];" \
        :: "r"(dst), "l"(src), "r"(bytes), "r"(mbar) : "memory")
#define MBARRIER_INIT(mbar, cnt) \
    asm volatile("mbarrier.init.shared.b64 [%0], %1;" :: "r"((uint32_t)(mbar)), "r"((uint32_t)(cnt)) : "memory")
#define MBARRIER_EXPECT_TX(mbar, bytes) \
    asm volatile("mbarrier.arrive.expect_tx.shared.b64 _, [%0], %1;" :: "r"((uint32_t)(mbar)), "r"((uint32_t)(bytes)) : "memory")
#define MBARRIER_WAIT_PARITY(mbar, parity) do { \
    uint32_t _m = (uint32_t)(mbar); uint32_t _p = (uint32_t)(parity); uint32_t _d; \
    asm volatile("{\n\t.reg .pred p;\n\tmbarrier.try_wait.parity.acquire.cta.shared::cta.b64 p, [%1], %2;\n\tselp.b32 %0, 1, 0, p;\n\t}" \
        : "=r"(_d) : "r"(_m), "r"(_p) : "memory"); \
    if (!_d) { \
        asm volatile("{\n\t.reg .pred P1;\n\tWL_%=:\n\tmbarrier.try_wait.parity.acquire.cta.shared::cta.b64 P1, [%0], %1, 0x989680;\n\t@P1 bra.uni WD_%=;\n\tbra.uni WL_%=;\n\tWD_%=:\n\t}" \
            :: "r"(_m), "r"(_p) : "memory"); \
    } } while (0)

// ===================== fused prep: weight + activation pre-split ===================
__global__ __launch_bounds__(256) void prep_kernel(
    const float* __restrict__ Wq, const float* __restrict__ Wk,
    const float* __restrict__ Wv, const float* __restrict__ Wo,
    const float* __restrict__ Wi2, unsigned char* __restrict__ wdst,
    const float* __restrict__ q, const float* __restrict__ k, const float* __restrict__ v)
{
    int bb = blockIdx.x;
    if (bb < 2176) {
        if (bb == 0 && threadIdx.x < 4) g_sacc[threadIdx.x] = 0ull;
        const float* W; unsigned char* d; int K;
        if      (bb < 512)  { W = Wq;  d = wdst;              K = 512; }
        else if (bb < 1024) { W = Wk;  d = wdst + 1048576u;   K = 512; bb -= 512; }
        else if (bb < 1536) { W = Wv;  d = wdst + 2097152u;   K = 512; bb -= 1024; }
        else if (bb < 2048) { W = Wo;  d = wdst + 3145728u;   K = 512; bb -= 1536; }
        else                { W = Wi2; d = wdst + 4194304u;   K = 128; bb -= 2048; }
        int NK = (K == 512) ? 262144 : 65536;
        int S = K >> 5;
        int idx = bb * 256 + threadIdx.x;
        int halfK = K >> 1;
        int n = idx / halfK;
        int kk = (idx - n * halfK) * 2;
        float x0 = W[(size_t)n * K + kk];
        float x1 = W[(size_t)n * K + kk + 1];
        float lx, ly;
        uint32_t hp = pack_hi(x0, x1, lx, ly);
        uint32_t lp = pack_lo(lx, ly);
        int nt = n >> 7, rr = n & 127, st = kk >> 5, kb = (kk & 31) * 2;
        size_t blk = ((size_t)nt * S + st) * 8192 + swzoff(rr, kb);
        *(uint32_t*)(d + blk)                  = hp;
        *(uint32_t*)(d + (size_t)NK * 2 + blk) = lp;
    } else {
        int a = bb - 2176;
        int zy = a >> 12, zx = a & 4095;
        const float* src = zy == 0 ? q : zy == 1 ? k : v;
        char* dst = (char*)g_Ain + (size_t)zy * 16777216u;
        size_t e = ((size_t)zx * 256 + threadIdx.x) * 4;
        float4 x = *(const float4*)(src + e);
        float l0, l1, l2, l3;
        uint2 hp; hp.x = pack_hi(x.x, x.y, l0, l1); hp.y = pack_hi(x.z, x.w, l2, l3);
        uint2 lp; lp.x = pack_lo(l0, l1);           lp.y = pack_lo(l2, l3);
        int r = (int)(e >> 9), kk = (int)(e & 511);
        int mt = r >> 7, rr = r & 127, st = kk >> 5, kb = (kk & 31) * 2;
        size_t blk = ((size_t)mt * 16 + st) * 8192 + swzoff(rr, kb);
        *(uint2*)(dst + blk)            = hp;
        *(uint2*)(dst + 8388608u + blk) = lp;
    }
}

// ===================== unified pre-packed GEMM (2-deep bulk pipeline) ==============
// mode 0: plain. mode 4/5: Q/K planes. mode 6: V^T planes. mode 8: g_Y = scale*(acc+bias)
#define PGB 32768
#define PG_SMEM (2*PGB + 64)

__global__ __launch_bounds__(256, 2) void pgemm_kernel(
    const char* __restrict__ Ab0, long Apl, long Az,
    const char* __restrict__ Bb0, long Bpl, long Bz,
    int K, int mode0,
    const float* __restrict__ b0, const float* __restrict__ b1, const float* __restrict__ b2,
    float* __restrict__ C, const float* __restrict__ scale)
{
    extern __shared__ char sm[];
    const uint32_t sbase = smem_to_u32(sm);
    const uint32_t mb0 = sbase + 2 * PGB, mb1 = mb0 + 8;
    const int tid = threadIdx.x, wid = tid >> 5, lane = tid & 31;
    const int bx = blockIdx.x, by = blockIdx.y, z = blockIdx.z;
    const int mode = mode0 + z;
    const char* Ab = Ab0 + (size_t)z * Az;
    const char* Bb = Bb0 + (size_t)z * Bz;
    const float* bias = (z == 0) ? b0 : (z == 1) ? b1 : b2;
    const int S = K >> 5;
    const int bm = by * 128, bn = bx * 128;

    if (tid == 0) { MBARRIER_INIT(mb0, 1); MBARRIER_INIT(mb1, 1); }
    __syncthreads();

    float acc[16][4];
#pragma unroll
    for (int i = 0; i < 16; i++)
#pragma unroll
        for (int j = 0; j < 4; j++) acc[i][j] = 0.f;

    auto issue = [&](int s, int buf) {
        uint32_t mb = buf ? mb1 : mb0;
        uint32_t d = sbase + buf * PGB;
        MBARRIER_EXPECT_TX(mb, 32768);
        const char* As = Ab + (((size_t)by * S + s) << 13);
        const char* Bs = Bb + (((size_t)bx * S + s) << 13);
        BULK_G2S(d,         As,       8192, mb);
        BULK_G2S(d + 8192,  As + Apl, 8192, mb);
        BULK_G2S(d + 16384, Bs,       8192, mb);
        BULK_G2S(d + 24576, Bs + Bpl, 8192, mb);
    };

    const int wm = (wid >> 2) * 64, wn = (wid & 3) * 32;
    const int boff_n = ((lane >> 4) << 3) + (lane & 7);

    auto compute = [&](int buf) {
        uint32_t Ahi = sbase + buf * PGB;
        uint32_t Bhi = Ahi + 16384;
#pragma unroll
        for (int kh = 0; kh < 2; kh++) {
            const int qa = (kh * 2 + (lane >> 4)) << 4;
            const int qb = (kh * 2 + ((lane >> 3) & 1)) << 4;
            uint32_t bh[8], bl[8], a[16];
#pragma unroll
            for (int nf2 = 0; nf2 < 2; nf2++) {
                int rb = wn + nf2 * 16 + boff_n;
                uint32_t baddr = Bhi + swzoff(rb, qb);
                ldsm4(bh + nf2 * 4, baddr);
                ldsm4(bl + nf2 * 4, baddr + 8192);
            }
#pragma unroll
            for (int mf = 0; mf < 4; mf++) {
                int ra = wm + mf * 16 + (lane & 15);
                ldsm4(a + mf * 4, Ahi + swzoff(ra, qa));
            }
#pragma unroll
            for (int mf = 0; mf < 4; mf++)
#pragma unroll
                for (int nf = 0; nf < 4; nf++)
                    mma16816(acc[mf * 4 + nf], a + mf * 4, bh + nf * 2);
#pragma unroll
            for (int mf = 0; mf < 4; mf++)
#pragma unroll
                for (int nf = 0; nf < 4; nf++)
                    mma16816(acc[mf * 4 + nf], a + mf * 4, bl + nf * 2);
#pragma unroll
            for (int mf = 0; mf < 4; mf++) {
                int ra = wm + mf * 16 + (lane & 15);
                ldsm4(a + mf * 4, Ahi + 8192 + swzoff(ra, qa));
            }
#pragma unroll
            for (int mf = 0; mf < 4; mf++)
#pragma unroll
                for (int nf = 0; nf < 4; nf++)
                    mma16816(acc[mf * 4 + nf], a + mf * 4, bh + nf * 2);
        }
    };

    if (tid == 0) issue(0, 0);
    for (int s = 0; s < S; s++) {
        if (s + 1 < S && tid == 0) issue(s + 1, (s + 1) & 1);
        MBARRIER_WAIT_PARITY((s & 1) ? mb1 : mb0, (s >> 1) & 1);
        compute(s & 1);
        __syncthreads();
    }

    const float isc = (mode == 8) ? scale[0] : 0.f;
#pragma unroll
    for (int mf = 0; mf < 4; mf++) {
#pragma unroll
        for (int nf = 0; nf < 4; nf++) {
            float* cc = acc[mf * 4 + nf];
            int col = bn + wn + nf * 8 + (lane & 3) * 2;
            float bv0 = bias[col], bv1 = bias[col + 1];
#pragma unroll
            for (int rp = 0; rp < 2; rp++) {
                int m = bm + wm + mf * 16 + (lane >> 2) + rp * 8;
                float v0 = cc[rp * 2 + 0] + bv0;
                float v1 = cc[rp * 2 + 1] + bv1;
                if (mode == 0) {
                    *(float2*)(C + (size_t)m * DM + col) = make_float2(v0, v1);
                } else if (mode == 8) {
                    *(float2*)(g_Y + (size_t)m * DM + col) =
                        make_float2(isc * v0, isc * v1);
                } else if (mode == 4 || mode == 5) {
                    if (mode == 4) { v0 *= 0.125f; v1 *= 0.125f; }
                    int bb = m >> 9, si = m & 511, hh = col >> 6, d = col & 63;
                    int bh_ = bb * 8 + hh, mt = si >> 7, rr = si & 127;
                    int st = d >> 5, kb = (d & 31) * 2;
                    size_t blk = (((size_t)(bh_ * 4 + mt) * 2 + st) << 13) + swzoff(rr, kb);
                    char* base = (mode == 4) ? (char*)g_Qb : (char*)g_Kb;
                    float l0, l1;
                    uint32_t hp = pack_hi(v0, v1, l0, l1);
                    uint32_t lp = pack_lo(l0, l1);
                    *(uint32_t*)(base + blk)            = hp;
                    *(uint32_t*)(base + 8388608u + blk) = lp;
                } else {  // mode 6
                    int bb = m >> 9, si = m & 511, hh = col >> 6, d = col & 63;
                    int bh_ = bb * 8 + hh, st = si >> 5, kb = (si & 31) * 2;
                    size_t blk = ((size_t)(bh_ * 16 + st)) * 4096;
                    char* base = (char*)g_Vtb;
                    __nv_bfloat16 h0 = __float2bfloat16(v0);
                    __nv_bfloat16 h1 = __float2bfloat16(v1);
                    int o0 = swzoff(d, kb), o1 = swzoff(d + 1, kb);
                    *(__nv_bfloat16*)(base + blk + o0) = h0;
                    *(__nv_bfloat16*)(base + 8388608u + blk + o0) =
                        __float2bfloat16(v0 - __bfloat162float(h0));
                    *(__nv_bfloat16*)(base + blk + o1) = h1;
                    *(__nv_bfloat16*)(base + 8388608u + blk + o1) =
                        __float2bfloat16(v1 - __bfloat162float(h1));
                }
            }
        }
    }
}

// ===================== QK^T: paired tiles per Q-strip =============================
#define SK_SMEM (98304 + 64)

__global__ __launch_bounds__(256, 2) void qk_kernel(int bh0)
{
    extern __shared__ char sm[];
    const uint32_t sbase = smem_to_u32(sm);
    const uint32_t mbb = sbase + 98304;
    const int t = blockIdx.x;
    const int by  = (t >= 4) ? 3 : (t >= 2) ? 2 : t;
    const int bx0 = (t == 3 || t == 5) ? 2 : 0;
    const int ntl = (t == 0 || t == 3) ? 1 : 2;
    const int bm = by * 128;
    const int bh = bh0 + blockIdx.y;
    const int tid = threadIdx.x, wid = tid >> 5, lane = tid & 31;

    if (tid == 0) {
        MBARRIER_INIT(mbb, 1); MBARRIER_INIT(mbb + 8, 1);
        asm volatile("fence.proxy.async.shared::cta;" ::: "memory");
        const char* Qb = (const char*)g_Qb;
        const char* Kb = (const char*)g_Kb;
        MBARRIER_EXPECT_TX(mbb, 65536);
#pragma unroll
        for (int p = 0; p < 2; p++)
#pragma unroll
            for (int s = 0; s < 2; s++) {
                const char* qsrc = Qb + (size_t)p * 8388608u + (((size_t)(bh * 4 + by) * 2 + s) << 13);
                const char* ksrc = Kb + (size_t)p * 8388608u + (((size_t)(bh * 4 + bx0) * 2 + s) << 13);
                BULK_G2S(sbase + p * 16384 + s * 8192,         qsrc, 8192, mbb);
                BULK_G2S(sbase + 32768 + p * 16384 + s * 8192, ksrc, 8192, mbb);
            }
        if (ntl == 2) {
            MBARRIER_EXPECT_TX(mbb + 8, 32768);
#pragma unroll
            for (int p = 0; p < 2; p++)
#pragma unroll
                for (int s = 0; s < 2; s++) {
                    const char* ksrc = Kb + (size_t)p * 8388608u + (((size_t)(bh * 4 + bx0 + 1) * 2 + s) << 13);
                    BULK_G2S(sbase + 65536 + p * 16384 + s * 8192, ksrc, 8192, mbb + 8);
                }
        }
    }
    __syncthreads();

    const int wm = (wid >> 2) * 64, wn = (wid & 3) * 32;
    const int boff_n = ((lane >> 4) << 3) + (lane & 7);

    for (int ti = 0; ti < ntl; ti++) {
        MBARRIER_WAIT_PARITY(mbb + ti * 8, 0);
        const uint32_t Kbuf = sbase + 32768 + ti * 32768;
        const int bn = (bx0 + ti) * 128;

        float acc[16][4];
#pragma unroll
        for (int i = 0; i < 16; i++)
#pragma unroll
            for (int j = 0; j < 4; j++) acc[i][j] = 0.f;

#pragma unroll
        for (int kh = 0; kh < 4; kh++) {
            const int chunk = (kh >> 1) * 8192;
            const int qa = ((kh & 1) * 2 + (lane >> 4)) << 4;
            const int qb = ((kh & 1) * 2 + ((lane >> 3) & 1)) << 4;
            uint32_t bh_[8], bl_[8], a[16];
#pragma unroll
            for (int nf2 = 0; nf2 < 2; nf2++) {
                int rb = wn + nf2 * 16 + boff_n;
                uint32_t baddr = Kbuf + chunk + swzoff(rb, qb);
                ldsm4(bh_ + nf2 * 4, baddr);
                ldsm4(bl_ + nf2 * 4, baddr + 16384);
            }
#pragma unroll
            for (int mf = 0; mf < 4; mf++) {
                int ra = wm + mf * 16 + (lane & 15);
                ldsm4(a + mf * 4, sbase + chunk + swzoff(ra, qa));
            }
#pragma unroll
            for (int mf = 0; mf < 4; mf++)
#pragma unroll
                for (int nf = 0; nf < 4; nf++)
                    mma16816(acc[mf * 4 + nf], a + mf * 4, bh_ + nf * 2);
#pragma unroll
            for (int mf = 0; mf < 4; mf++)
#pragma unroll
                for (int nf = 0; nf < 4; nf++)
                    mma16816(acc[mf * 4 + nf], a + mf * 4, bl_ + nf * 2);
#pragma unroll
            for (int mf = 0; mf < 4; mf++) {
                int ra = wm + mf * 16 + (lane & 15);
                ldsm4(a + mf * 4, sbase + 16384 + chunk + swzoff(ra, qa));
            }
#pragma unroll
            for (int mf = 0; mf < 4; mf++)
#pragma unroll
                for (int nf = 0; nf < 4; nf++)
                    mma16816(acc[mf * 4 + nf], a + mf * 4, bh_ + nf * 2);
        }

        float* Sp = g_S + (size_t)bh * 512 * 512;
#pragma unroll
        for (int mf = 0; mf < 4; mf++)
#pragma unroll
            for (int nf = 0; nf < 4; nf++) {
                float* cc = acc[mf * 4 + nf];
                int col = bn + wn + nf * 8 + (lane & 3) * 2;
#pragma unroll
                for (int rp = 0; rp < 2; rp++) {
                    int m = bm + wm + mf * 16 + (lane >> 2) + rp * 8;
                    *(float2*)(Sp + (size_t)m * 512 + col) =
                        make_float2(cc[rp * 2], cc[rp * 2 + 1]);
                }
            }
    }
}

// ===================== row kernel (causal-truncated tiles) =========================
__global__ __launch_bounds__(256) void row_kernel(const float* __restrict__ gammas, int bh0)
{
    const int bh = bh0 + blockIdx.y, h = bh & 7;
    const int wid = threadIdx.x >> 5, lane = threadIdx.x & 31;
    const int i = blockIdx.x * 8 + wid;
    const int Ti = i >> 7;
    const int mt = i >> 7, rr = i & 127;
    char* Abase = (char*)g_A;

    if (i == 0) {
        uint2 zz = make_uint2(0u, 0u);
        int st = lane >> 3, kb = (lane & 7) * 8;
        size_t blk = ((size_t)(bh * 4 + 0) * 16 + st) * 8192 + swzoff(0, kb);
        *(uint2*)(Abase + blk)             = zz;
        *(uint2*)(Abase + 67108864u + blk) = zz;
        return;
    }

    float gv = gammas[h];
    float gam = -(fmaxf(gv, 0.f) + log1pf(__expf(-fabsf(gv))));

    const float4* Srow = (const float4*)(g_S + ((size_t)bh * 512 + i) * 512);
    float sc[4][4], e[4][4], ls[4];
#pragma unroll
    for (int t = 0; t < 4; t++) {
        if (t > Ti) { ls[t] = 0.f; continue; }
        float4 sv = Srow[lane + 32 * t];
        int j0 = 4 * (lane + 32 * t);
        sc[t][0] = (j0 + 0 < i) ? sv.x : NEG_INF;
        sc[t][1] = (j0 + 1 < i) ? sv.y : NEG_INF;
        sc[t][2] = (j0 + 2 < i) ? sv.z : NEG_INF;
        sc[t][3] = (j0 + 3 < i) ? sv.w : NEG_INF;
    }

    float m = NEG_INF;
#pragma unroll
    for (int t = 0; t < 4; t++) {
        if (t > Ti) break;
#pragma unroll
        for (int l = 0; l < 4; l++) m = fmaxf(m, sc[t][l]);
    }
#pragma unroll
    for (int off = 16; off; off >>= 1)
        m = fmaxf(m, __shfl_xor_sync(0xffffffffu, m, off));

#pragma unroll
    for (int t = 0; t < 4; t++) {
        if (t > Ti) break;
        ls[t] = 0.f;
#pragma unroll
        for (int l = 0; l < 4; l++) { e[t][l] = __expf(sc[t][l] - m); ls[t] += e[t][l]; }
    }
    float excl[4], tot[4];
#pragma unroll
    for (int t = 0; t < 4; t++) {
        if (t > Ti) break;
        float x = ls[t];
#pragma unroll
        for (int off = 1; off < 32; off <<= 1) {
            float y = __shfl_up_sync(0xffffffffu, x, off);
            if (lane >= off) x += y;
        }
        excl[t] = x - ls[t];
        tot[t]  = __shfl_sync(0xffffffffu, x, 31);
    }
    float baseA[4], T = 0.f;
#pragma unroll
    for (int t = 0; t < 4; t++) {
        if (t > Ti) break;
        baseA[t] = T; T += tot[t];
    }
    float invT = 1.f / T;

#pragma unroll
    for (int t = 0; t < 4; t++) {
        if (t > Ti) break;
        float run = baseA[t] + excl[t];
#pragma unroll
        for (int l = 0; l < 4; l++) {
            run += e[t][l];
            int j = 4 * lane + 128 * t + l;
            float suf  = fmaxf(T - run, 0.f);
            float dist = sqrtf(fmaxf(suf * invT * (float)(i - j), 0.f));
            float tmp  = __expf(dist * gam);
            tmp = fminf(fmaxf(tmp, 1e-5f), 1e5f);
            sc[t][l] = (j < i) ? sc[t][l] * tmp : NEG_INF;
        }
    }

    float m2 = NEG_INF;
#pragma unroll
    for (int t = 0; t < 4; t++) {
        if (t > Ti) break;
#pragma unroll
        for (int l = 0; l < 4; l++) m2 = fmaxf(m2, sc[t][l]);
    }
#pragma unroll
    for (int off = 16; off; off >>= 1)
        m2 = fmaxf(m2, __shfl_xor_sync(0xffffffffu, m2, off));
    float Z = 0.f;
#pragma unroll
    for (int t = 0; t < 4; t++) {
        if (t > Ti) break;
#pragma unroll
        for (int l = 0; l < 4; l++) { e[t][l] = __expf(sc[t][l] - m2); Z += e[t][l]; }
    }
#pragma unroll
    for (int off = 16; off; off >>= 1)
        Z += __shfl_xor_sync(0xffffffffu, Z, off);
    float invZ = 1.f / Z;

#pragma unroll
    for (int t = 0; t < 4; t++) {
        if (t > Ti) break;
        float a0 = e[t][0] * invZ, a1 = e[t][1] * invZ;
        float a2 = e[t][2] * invZ, a3 = e[t][3] * invZ;
        float l0, l1, l2, l3;
        uint2 hp; hp.x = pack_hi(a0, a1, l0, l1); hp.y = pack_hi(a2, a3, l2, l3);
        uint2 lp; lp.x = pack_lo(l0, l1);         lp.y = pack_lo(l2, l3);
        int st = (lane >> 3) + 4 * t, kb = (lane & 7) * 8;
        size_t blk = ((size_t)(bh * 4 + mt) * 16 + st) * 8192 + swzoff(rr, kb);
        *(uint2*)(Abase + blk)             = hp;
        *(uint2*)(Abase + 67108864u + blk) = lp;
    }
}

// ===================== AV batched GEMM (2-deep bulk pipeline, causal) =============
#define AVB 24576
#define AV_SMEM (2*AVB + 64)

__global__ __launch_bounds__(256, 2) void av_kernel(int bh0)
{
    extern __shared__ char sm[];
    const uint32_t sbase = smem_to_u32(sm);
    const uint32_t mb0 = sbase + 2 * AVB, mb1 = mb0 + 8;
    const int mt = blockIdx.x;
    const int bm = mt * 128;
    const int bh = bh0 + blockIdx.y;
    const int b = bh >> 3, h = bh & 7;
    const int tid = threadIdx.x, wid = tid >> 5, lane = tid & 31;
    const int nst = (bm + 128) >> 5;

    if (tid == 0) { MBARRIER_INIT(mb0, 1); MBARRIER_INIT(mb1, 1); }
    __syncthreads();

    float acc[8][4];
#pragma unroll
    for (int i = 0; i < 8; i++)
#pragma unroll
        for (int j = 0; j < 4; j++) acc[i][j] = 0.f;

    auto issue = [&](int s, int buf) {
        uint32_t mb = buf ? mb1 : mb0;
        uint32_t d = sbase + buf * AVB;
        MBARRIER_EXPECT_TX(mb, 24576);
        const char* Ap = (const char*)g_A + (((size_t)(bh * 4 + mt) * 16 + s) << 13);
        const char* Vp = (const char*)g_Vtb + ((size_t)(bh * 16 + s)) * 4096;
        BULK_G2S(d,         Ap,              8192, mb);
        BULK_G2S(d + 8192,  Ap + 67108864u,  8192, mb);
        BULK_G2S(d + 16384, Vp,              4096, mb);
        BULK_G2S(d + 20480, Vp + 8388608u,   4096, mb);
    };

    const int wm = (wid >> 1) * 32, wn = (wid & 1) * 32;
    const int boff_n = ((lane >> 4) << 3) + (lane & 7);

    auto compute = [&](int buf) {
        uint32_t Ab = sbase + buf * AVB;
        uint32_t Vb = Ab + 16384;
#pragma unroll
        for (int kh = 0; kh < 2; kh++) {
            const int qa = (kh * 2 + (lane >> 4)) << 4;
            const int qb = (kh * 2 + ((lane >> 3) & 1)) << 4;
            uint32_t bh_[8], bl_[8], a[8];
#pragma unroll
            for (int nf2 = 0; nf2 < 2; nf2++) {
                int rb = wn + nf2 * 16 + boff_n;
                uint32_t baddr = Vb + swzoff(rb, qb);
                ldsm4(bh_ + nf2 * 4, baddr);
                ldsm4(bl_ + nf2 * 4, baddr + 4096);
            }
#pragma unroll
            for (int mf = 0; mf < 2; mf++) {
                int ra = wm + mf * 16 + (lane & 15);
                ldsm4(a + mf * 4, Ab + swzoff(ra, qa));
            }
#pragma unroll
            for (int mf = 0; mf < 2; mf++)
#pragma unroll
                for (int nf = 0; nf < 4; nf++)
                    mma16816(acc[mf * 4 + nf], a + mf * 4, bh_ + nf * 2);
#pragma unroll
            for (int mf = 0; mf < 2; mf++)
#pragma unroll
                for (int nf = 0; nf < 4; nf++)
                    mma16816(acc[mf * 4 + nf], a + mf * 4, bl_ + nf * 2);
#pragma unroll
            for (int mf = 0; mf < 2; mf++) {
                int ra = wm + mf * 16 + (lane & 15);
                ldsm4(a + mf * 4, Ab + 8192 + swzoff(ra, qa));
            }
#pragma unroll
            for (int mf = 0; mf < 2; mf++)
#pragma unroll
                for (int nf = 0; nf < 4; nf++)
                    mma16816(acc[mf * 4 + nf], a + mf * 4, bh_ + nf * 2);
        }
    };

    if (tid == 0) issue(0, 0);
    for (int s = 0; s < nst; s++) {
        if (s + 1 < nst && tid == 0) issue(s + 1, (s + 1) & 1);
        MBARRIER_WAIT_PARITY((s & 1) ? mb1 : mb0, (s >> 1) & 1);
        compute(s & 1);
        __syncthreads();
    }

#pragma unroll
    for (int mf = 0; mf < 2; mf++)
#pragma unroll
        for (int nf = 0; nf < 4; nf++) {
            float* cc = acc[mf * 4 + nf];
            int col = wn + nf * 8 + (lane & 3) * 2;
#pragma unroll
            for (int rp = 0; rp < 2; rp++) {
                int mrow = bm + wm + mf * 16 + (lane >> 2) + rp * 8;
                *(float2*)(g_X + ((size_t)(b * 512 + mrow)) * 512 + h * 64 + col) =
                    make_float2(cc[rp * 2], cc[rp * 2 + 1]);
            }
        }
}

// ===================== parallel norm01 stats =====================
__global__ __launch_bounds__(256) void stats_kernel(
    const int* __restrict__ sgap, const int* __restrict__ pcount)
{
    __shared__ long long sh[32];
    int idx = blockIdx.x * 256 + threadIdx.x;
    long long a = sgap[idx], b = pcount[idx];
    long long s0 = a, q0 = a * a, s1 = b, q1 = b * b;
#pragma unroll
    for (int off = 16; off; off >>= 1) {
        s0 += __shfl_xor_sync(0xffffffffu, s0, off);
        q0 += __shfl_xor_sync(0xffffffffu, q0, off);
        s1 += __shfl_xor_sync(0xffffffffu, s1, off);
        q1 += __shfl_xor_sync(0xffffffffu, q1, off);
    }
    int wd = threadIdx.x >> 5, ln = threadIdx.x & 31;
    if (ln == 0) { sh[wd] = s0; sh[8+wd] = q0; sh[16+wd] = s1; sh[24+wd] = q1; }
    __syncthreads();
    if (threadIdx.x == 0) {
        long long S0=0,Q0=0,S1=0,Q1=0;
        for (int i = 0; i < 8; i++) { S0+=sh[i]; Q0+=sh[8+i]; S1+=sh[16+i]; Q1+=sh[24+i]; }
        atomicAdd(&g_sacc[0], (unsigned long long)S0);
        atomicAdd(&g_sacc[1], (unsigned long long)Q0);
        atomicAdd(&g_sacc[2], (unsigned long long)S1);
        atomicAdd(&g_sacc[3], (unsigned long long)Q1);
    }
}

// ===================== interference hidden layer -> bf16 blocks ===================
__global__ __launch_bounds__(256) void hidden_kernel(
    const int* __restrict__ sgap, const int* __restrict__ pcount,
    const float* __restrict__ Wi1, const float* __restrict__ bi1)
{
    float n = (float)MTOT;
    float S0 = (float)(long long)g_sacc[0], Q0 = (float)(long long)g_sacc[1];
    float S1 = (float)(long long)g_sacc[2], Q1 = (float)(long long)g_sacc[3];
    float m0 = S0 / n, m1 = S1 / n;
    float v0 = (Q0 - n*m0*m0) / (n - 1.f);
    float v1 = (Q1 - n*m1*m1) / (n - 1.f);
    float inv0 = 1.f / (sqrtf(fmaxf(v0, 0.f)) + 1e-6f);
    float inv1 = 1.f / (sqrtf(fmaxf(v1, 0.f)) + 1e-6f);

    int idx = blockIdx.x * 256 + threadIdx.x;
    int r = idx >> 6, c2 = (idx & 63) * 2;
    float ii0 = 0.5f * (tanhf(((float)sgap[r]   - m0) * inv0) + 1.f);
    float ii1 = 0.5f * (tanhf(((float)pcount[r] - m1) * inv1) + 1.f);
    float h0 = fmaxf(ii0 * Wi1[2*c2+0] + ii1 * Wi1[2*c2+1] + bi1[c2],   0.f);
    float h1 = fmaxf(ii0 * Wi1[2*c2+2] + ii1 * Wi1[2*c2+3] + bi1[c2+1], 0.f);
    float l0, l1;
    uint32_t hp = pack_hi(h0, h1, l0, l1);
    uint32_t lp = pack_lo(l0, l1);
    int mt = r >> 7, rr = r & 127, st = c2 >> 5, kb = (c2 & 31) * 2;
    size_t blk = ((size_t)mt * 4 + st) * 8192 + swzoff(rr, kb);
    char* base = (char*)g_Hb;
    *(uint32_t*)(base + blk)            = hp;
    *(uint32_t*)(base + 2097152u + blk) = lp;
}

// ===================== fused add (X+F) + LayerNorm + pack to bf16 blocks ==========
__global__ __launch_bounds__(256) void addln_pack_kernel(
    const float* __restrict__ gw, const float* __restrict__ bw)
{
    int r = blockIdx.x * 8 + (threadIdx.x >> 5);
    int lane = threadIdx.x & 31;
    const float4* xrow = (const float4*)(g_X + (size_t)r * DM);
    const float4* frow = (const float4*)(g_Y + (size_t)r * DM);
    float4 xv[4];
    float s = 0.f, q = 0.f;
#pragma unroll
    for (int c = 0; c < 4; c++) {
        float4 xa = xrow[lane + 32 * c];
        float4 fa = frow[lane + 32 * c];
        xv[c].x = xa.x + fa.x; xv[c].y = xa.y + fa.y;
        xv[c].z = xa.z + fa.z; xv[c].w = xa.w + fa.w;
        s += xv[c].x + xv[c].y + xv[c].z + xv[c].w;
        q += xv[c].x*xv[c].x + xv[c].y*xv[c].y + xv[c].z*xv[c].z + xv[c].w*xv[c].w;
    }
#pragma unroll
    for (int off = 16; off; off >>= 1) {
        s += __shfl_xor_sync(0xffffffffu, s, off);
        q += __shfl_xor_sync(0xffffffffu, q, off);
    }
    float mu   = s * (1.f / 512.f);
    float rstd = rsqrtf(q * (1.f / 512.f) - mu * mu + 1e-5f);
    int mt = r >> 7, rr = r & 127;
    char* base = (char*)g_Yb;
#pragma unroll
    for (int c = 0; c < 4; c++) {
        float4 g4 = ((const float4*)gw)[lane + 32 * c];
        float4 b4 = ((const float4*)bw)[lane + 32 * c];
        float n0 = (xv[c].x - mu) * rstd * g4.x + b4.x;
        float n1 = (xv[c].y - mu) * rstd * g4.y + b4.y;
        float n2 = (xv[c].z - mu) * rstd * g4.z + b4.z;
        float n3 = (xv[c].w - mu) * rstd * g4.w + b4.w;
        float l0, l1, l2, l3;
        uint2 hp; hp.x = pack_hi(n0, n1, l0, l1); hp.y = pack_hi(n2, n3, l2, l3);
        uint2 lp; lp.x = pack_lo(l0, l1);         lp.y = pack_lo(l2, l3);
        int st = (lane >> 3) + 4 * c, kb = (lane & 7) * 8;
        size_t blk = ((size_t)mt * 16 + st) * 8192 + swzoff(rr, kb);
        *(uint2*)(base + blk)            = hp;
        *(uint2*)(base + 8388608u + blk) = lp;
    }
}

// ===================== launcher (3-stream fork/join; static resources) =============
extern "C" void kernel_launch(void* const* d_in, const int* in_sizes, int n_in,
                              void* d_out, int out_size)
{
    const float* q      = (const float*)d_in[0];
    const float* k      = (const float*)d_in[1];
    const float* v      = (const float*)d_in[2];
    const int*   sgap   = (const int*)d_in[3];
    const int*   pcount = (const int*)d_in[4];
    const float* Wq = (const float*)d_in[5];  const float* bq = (const float*)d_in[6];
    const float* Wk = (const float*)d_in[7];  const float* bk = (const float*)d_in[8];
    const float* Wv = (const float*)d_in[9];  const float* bv = (const float*)d_in[10];
    const float* Wo = (const float*)d_in[11]; const float* bo = (const float*)d_in[12];
    const float* gammas = (const float*)d_in[13];
    const float* ln_g = (const float*)d_in[14]; const float* ln_b = (const float*)d_in[15];
    const float* Wi1 = (const float*)d_in[16];  const float* bi1 = (const float*)d_in[17];
    const float* Wi2 = (const float*)d_in[18];  const float* bi2 = (const float*)d_in[19];
    const float* iscale = (const float*)d_in[20];
    float* out = (float*)d_out;

    char *Ain, *Yb, *Hb;
    unsigned char* Wpk;
    cudaGetSymbolAddress((void**)&Ain, g_Ain);
    cudaGetSymbolAddress((void**)&Yb,  g_Yb);
    cudaGetSymbolAddress((void**)&Hb,  g_Hb);
    cudaGetSymbolAddress((void**)&Wpk, g_Wpk);

    // one-time resource creation (first call = correctness run, before the
    // harness's pre-capture memory baseline; reused by every later call)
    static bool inited = false;
    static cudaStream_t s2, s3;
    static cudaEvent_t eP, eV, eQK, eA1, eF;
    if (!inited) {
        cudaFuncSetAttribute(pgemm_kernel, cudaFuncAttributeMaxDynamicSharedMemorySize, PG_SMEM);
        cudaFuncSetAttribute(qk_kernel, cudaFuncAttributeMaxDynamicSharedMemorySize, SK_SMEM);
        cudaFuncSetAttribute(av_kernel, cudaFuncAttributeMaxDynamicSharedMemorySize, AV_SMEM);
        cudaStreamCreateWithFlags(&s2, cudaStreamNonBlocking);
        cudaStreamCreateWithFlags(&s3, cudaStreamNonBlocking);
        cudaEventCreateWithFlags(&eP,  cudaEventDisableTiming);
        cudaEventCreateWithFlags(&eV,  cudaEventDisableTiming);
        cudaEventCreateWithFlags(&eQK, cudaEventDisableTiming);
        cudaEventCreateWithFlags(&eA1, cudaEventDisableTiming);
        cudaEventCreateWithFlags(&eF,  cudaEventDisableTiming);
        inited = true;
    }

    // main: prep
    prep_kernel<<<14464, 256>>>(Wq, Wk, Wv, Wo, Wi2, Wpk, q, k, v);
    cudaEventRecord(eP, 0);
    cudaStreamWaitEvent(s2, eP, 0);

    // s2: stats -> V projection -> hidden -> F = iscale*(H@Wi2^T+bi2)
    stats_kernel<<<32, 256, 0, s2>>>(sgap, pcount);
    pgemm_kernel<<<dim3(4, 64, 1), 256, PG_SMEM, s2>>>(
        Ain + 2u*16777216u, 8388608L, 0L, (const char*)Wpk + 2097152u, 524288L, 0L,
        512, 6, bv, nullptr, nullptr, nullptr, nullptr);
    cudaEventRecord(eV, s2);
    hidden_kernel<<<2048, 256, 0, s2>>>(sgap, pcount, Wi1, bi1);
    pgemm_kernel<<<dim3(4, 64, 1), 256, PG_SMEM, s2>>>(
        Hb, 2097152L, 0L, (const char*)Wpk + 4194304u, 131072L, 0L,
        128, 8, bi2, nullptr, nullptr, nullptr, iscale);
    cudaEventRecord(eF, s2);

    // main: Q,K projections
    pgemm_kernel<<<dim3(4, 64, 2), 256, PG_SMEM>>>(
        Ain, 8388608L, 16777216L, (const char*)Wpk, 524288L, 1048576L,
        512, 4, bq, bk, nullptr, nullptr, nullptr);
    cudaEventRecord(eQK, 0);
    cudaStreamWaitEvent(s3, eQK, 0);

    // s3: attention half G1 (bh 64..127)
    qk_kernel<<<dim3(6, 64), 256, SK_SMEM, s3>>>(64);
    row_kernel<<<dim3(64, 64), 256, 0, s3>>>(gammas, 64);
    cudaStreamWaitEvent(s3, eV, 0);
    av_kernel<<<dim3(4, 64), 256, AV_SMEM, s3>>>(64);
    cudaEventRecord(eA1, s3);

    // main: attention half G0 (bh 0..63)
    qk_kernel<<<dim3(6, 64), 256, SK_SMEM>>>(0);
    row_kernel<<<dim3(64, 64), 256>>>(gammas, 0);
    cudaStreamWaitEvent(0, eV, 0);
    av_kernel<<<dim3(4, 64), 256, AV_SMEM>>>(0);

    // join: need both halves of X and F
    cudaStreamWaitEvent(0, eA1, 0);
    cudaStreamWaitEvent(0, eF, 0);
    addln_pack_kernel<<<1024, 256>>>(ln_g, ln_b);

    pgemm_kernel<<<dim3(4, 64, 1), 256, PG_SMEM>>>(
        Yb, 8388608L, 0L, (const char*)Wpk + 3145728u, 524288L, 0L,
        512, 0, bo, nullptr, nullptr, out, nullptr);
}

// round 17
// speedup vs baseline: 1.4391x; 1.0006x over previous
#include <cuda_runtime.h>
#include <cuda_bf16.h>
#include <math.h>
#include <cstdint>

#define BSZ 16
#define SEQ 512
#define DM  512
#define NH  8
#define DKH 64
#define MTOT (BSZ*SEQ)
#define NEG_INF (__int_as_float(0xff800000))
#define QKVPLN 4194304u
#define APLN 33554432u

// ===================== scratch =====================
__device__ __nv_bfloat16 g_Ain[3u*2u*4194304u];
__device__ __nv_bfloat16 g_Qb [2*QKVPLN];
__device__ __nv_bfloat16 g_Kb [2*QKVPLN];
__device__ __nv_bfloat16 g_Vtb[2*QKVPLN];
__device__ float         g_S  [APLN];
__device__ __nv_bfloat16 g_A  [2*APLN];
__device__ float g_X [MTOT*DM];
__device__ float g_Y [MTOT*DM];          // holds F = iscale*(H@Wi2^T + bi2)
__device__ __nv_bfloat16 g_Yb[2u*4194304u];
__device__ __nv_bfloat16 g_Hb[2u*1048576u];
__device__ unsigned long long g_sacc[4];
__device__ unsigned char g_Wpk[5u*1024u*1024u];

// ===================== asm helpers =====================
__device__ __forceinline__ uint32_t smem_to_u32(const void* p) {
    uint32_t a;
    asm("{ .reg .u64 t; cvta.to.shared.u64 t, %1; cvt.u32.u64 %0, t; }" : "=r"(a) : "l"(p));
    return a;
}
__device__ __forceinline__ void ldsm4(uint32_t* r, uint32_t addr) {
    asm volatile("ldmatrix.sync.aligned.m8n8.x4.shared.b16 {%0,%1,%2,%3}, [%4];"
        : "=r"(r[0]), "=r"(r[1]), "=r"(r[2]), "=r"(r[3]) : "r"(addr));
}
__device__ __forceinline__ void mma16816(float* c, const uint32_t* a, const uint32_t* b) {
    asm volatile("mma.sync.aligned.m16n8k16.row.col.f32.bf16.bf16.f32 "
        "{%0,%1,%2,%3}, {%4,%5,%6,%7}, {%8,%9}, {%0,%1,%2,%3};"
        : "+f"(c[0]), "+f"(c[1]), "+f"(c[2]), "+f"(c[3])
        : "r"(a[0]), "r"(a[1]), "r"(a[2]), "r"(a[3]), "r"(b[0]), "r"(b[1]));
}
__device__ __forceinline__ uint32_t pack_hi(float x, float y, float& lx, float& ly) {
    __nv_bfloat162 h = __floats2bfloat162_rn(x, y);
    lx = x - __bfloat162float(h.x);
    ly = y - __bfloat162float(h.y);
    return *reinterpret_cast<uint32_t*>(&h);
}
__device__ __forceinline__ uint32_t pack_lo(float lx, float ly) {
    __nv_bfloat162 l = __floats2bfloat162_rn(lx, ly);
    return *reinterpret_cast<uint32_t*>(&l);
}
__device__ __forceinline__ int swzoff(int r, int kb) {
    return r * 64 + ((((kb >> 4) ^ ((r >> 1) & 3)) << 4)) + (kb & 15);
}
#define BULK_G2S(dst, src, bytes, mbar) \
    asm volatile("cp.async.bulk.shared::cluster.global.mbarrier::complete_tx::bytes [%0], [%1], %2, [%3];" \
        :: "r"(dst), "l"(src), "r"(bytes), "r"(mbar) : "memory")
#define MBARRIER_INIT(mbar, cnt) \
    asm volatile("mbarrier.init.shared.b64 [%0], %1;" :: "r"((uint32_t)(mbar)), "r"((uint32_t)(cnt)) : "memory")
#define MBARRIER_EXPECT_TX(mbar, bytes) \
    asm volatile("mbarrier.arrive.expect_tx.shared.b64 _, [%0], %1;" :: "r"((uint32_t)(mbar)), "r"((uint32_t)(bytes)) : "memory")
#define MBARRIER_WAIT_PARITY(mbar, parity) do { \
    uint32_t _m = (uint32_t)(mbar); uint32_t _p = (uint32_t)(parity); uint32_t _d; \
    asm volatile("{\n\t.reg .pred p;\n\tmbarrier.try_wait.parity.acquire.cta.shared::cta.b64 p, [%1], %2;\n\tselp.b32 %0, 1, 0, p;\n\t}" \
        : "=r"(_d) : "r"(_m), "r"(_p) : "memory"); \
    if (!_d) { \
        asm volatile("{\n\t.reg .pred P1;\n\tWL_%=:\n\tmbarrier.try_wait.parity.acquire.cta.shared::cta.b64 P1, [%0], %1, 0x989680;\n\t@P1 bra.uni WD_%=;\n\tbra.uni WL_%=;\n\tWD_%=:\n\t}" \
            :: "r"(_m), "r"(_p) : "memory"); \
    } } while (0)

// ===================== helpers for prep =====================
__device__ __forceinline__ void prep_weight(const float* __restrict__ W,
                                            unsigned char* __restrict__ d,
                                            int K, int bb, int tidx)
{
    int NK = (K == 512) ? 262144 : 65536;
    int S = K >> 5;
    int idx = bb * 256 + tidx;
    int halfK = K >> 1;
    int n = idx / halfK;
    int kk = (idx - n * halfK) * 2;
    float x0 = W[(size_t)n * K + kk];
    float x1 = W[(size_t)n * K + kk + 1];
    float lx, ly;
    uint32_t hp = pack_hi(x0, x1, lx, ly);
    uint32_t lp = pack_lo(lx, ly);
    int nt = n >> 7, rr = n & 127, st = kk >> 5, kb = (kk & 31) * 2;
    size_t blk = ((size_t)nt * S + st) * 8192 + swzoff(rr, kb);
    *(uint32_t*)(d + blk)                  = hp;
    *(uint32_t*)(d + (size_t)NK * 2 + blk) = lp;
}
__device__ __forceinline__ void prep_act(const float* __restrict__ src,
                                         char* __restrict__ dst,
                                         int zx, int tidx)
{
    size_t e = ((size_t)zx * 256 + tidx) * 4;
    float4 x = *(const float4*)(src + e);
    float l0, l1, l2, l3;
    uint2 hp; hp.x = pack_hi(x.x, x.y, l0, l1); hp.y = pack_hi(x.z, x.w, l2, l3);
    uint2 lp; lp.x = pack_lo(l0, l1);           lp.y = pack_lo(l2, l3);
    int r = (int)(e >> 9), kk = (int)(e & 511);
    int mt = r >> 7, rr = r & 127, st = kk >> 5, kb = (kk & 31) * 2;
    size_t blk = ((size_t)mt * 16 + st) * 8192 + swzoff(rr, kb);
    *(uint2*)(dst + blk)            = hp;
    *(uint2*)(dst + 8388608u + blk) = lp;
}

// ===================== prep (Q/K portion): Wq, Wk, q-acts, k-acts ==================
__global__ __launch_bounds__(256) void prep_qk_kernel(
    const float* __restrict__ Wq, const float* __restrict__ Wk,
    unsigned char* __restrict__ wdst,
    const float* __restrict__ q, const float* __restrict__ k)
{
    int bb = blockIdx.x;
    if (bb < 512) {
        prep_weight(Wq, wdst, 512, bb, threadIdx.x);
    } else if (bb < 1024) {
        prep_weight(Wk, wdst + 1048576u, 512, bb - 512, threadIdx.x);
    } else {
        int a = bb - 1024;
        int zy = a >> 12, zx = a & 4095;
        prep_act(zy == 0 ? q : k, (char*)g_Ain + (size_t)zy * 16777216u, zx, threadIdx.x);
    }
}

// ===================== prep (rest): Wv, Wo, Wi2, v-acts, sacc zero =================
__global__ __launch_bounds__(256) void prep_rest_kernel(
    const float* __restrict__ Wv, const float* __restrict__ Wo,
    const float* __restrict__ Wi2, unsigned char* __restrict__ wdst,
    const float* __restrict__ v)
{
    int bb = blockIdx.x;
    if (bb == 0 && threadIdx.x < 4) g_sacc[threadIdx.x] = 0ull;
    if (bb < 512) {
        prep_weight(Wv, wdst + 2097152u, 512, bb, threadIdx.x);
    } else if (bb < 1024) {
        prep_weight(Wo, wdst + 3145728u, 512, bb - 512, threadIdx.x);
    } else if (bb < 1152) {
        prep_weight(Wi2, wdst + 4194304u, 128, bb - 1024, threadIdx.x);
    } else {
        prep_act(v, (char*)g_Ain + 2u * 16777216u, bb - 1152, threadIdx.x);
    }
}

// ===================== unified pre-packed GEMM (2-deep bulk pipeline) ==============
// mode 0: plain. mode 4/5: Q/K planes. mode 6: V^T planes. mode 8: g_Y = scale*(acc+bias)
#define PGB 32768
#define PG_SMEM (2*PGB + 64)

__global__ __launch_bounds__(256, 2) void pgemm_kernel(
    const char* __restrict__ Ab0, long Apl, long Az,
    const char* __restrict__ Bb0, long Bpl, long Bz,
    int K, int mode0,
    const float* __restrict__ b0, const float* __restrict__ b1, const float* __restrict__ b2,
    float* __restrict__ C, const float* __restrict__ scale)
{
    extern __shared__ char sm[];
    const uint32_t sbase = smem_to_u32(sm);
    const uint32_t mb0 = sbase + 2 * PGB, mb1 = mb0 + 8;
    const int tid = threadIdx.x, wid = tid >> 5, lane = tid & 31;
    const int bx = blockIdx.x, by = blockIdx.y, z = blockIdx.z;
    const int mode = mode0 + z;
    const char* Ab = Ab0 + (size_t)z * Az;
    const char* Bb = Bb0 + (size_t)z * Bz;
    const float* bias = (z == 0) ? b0 : (z == 1) ? b1 : b2;
    const int S = K >> 5;
    const int bm = by * 128, bn = bx * 128;

    if (tid == 0) { MBARRIER_INIT(mb0, 1); MBARRIER_INIT(mb1, 1); }
    __syncthreads();

    float acc[16][4];
#pragma unroll
    for (int i = 0; i < 16; i++)
#pragma unroll
        for (int j = 0; j < 4; j++) acc[i][j] = 0.f;

    auto issue = [&](int s, int buf) {
        uint32_t mb = buf ? mb1 : mb0;
        uint32_t d = sbase + buf * PGB;
        MBARRIER_EXPECT_TX(mb, 32768);
        const char* As = Ab + (((size_t)by * S + s) << 13);
        const char* Bs = Bb + (((size_t)bx * S + s) << 13);
        BULK_G2S(d,         As,       8192, mb);
        BULK_G2S(d + 8192,  As + Apl, 8192, mb);
        BULK_G2S(d + 16384, Bs,       8192, mb);
        BULK_G2S(d + 24576, Bs + Bpl, 8192, mb);
    };

    const int wm = (wid >> 2) * 64, wn = (wid & 3) * 32;
    const int boff_n = ((lane >> 4) << 3) + (lane & 7);

    auto compute = [&](int buf) {
        uint32_t Ahi = sbase + buf * PGB;
        uint32_t Bhi = Ahi + 16384;
#pragma unroll
        for (int kh = 0; kh < 2; kh++) {
            const int qa = (kh * 2 + (lane >> 4)) << 4;
            const int qb = (kh * 2 + ((lane >> 3) & 1)) << 4;
            uint32_t bh[8], bl[8], a[16];
#pragma unroll
            for (int nf2 = 0; nf2 < 2; nf2++) {
                int rb = wn + nf2 * 16 + boff_n;
                uint32_t baddr = Bhi + swzoff(rb, qb);
                ldsm4(bh + nf2 * 4, baddr);
                ldsm4(bl + nf2 * 4, baddr + 8192);
            }
#pragma unroll
            for (int mf = 0; mf < 4; mf++) {
                int ra = wm + mf * 16 + (lane & 15);
                ldsm4(a + mf * 4, Ahi + swzoff(ra, qa));
            }
#pragma unroll
            for (int mf = 0; mf < 4; mf++)
#pragma unroll
                for (int nf = 0; nf < 4; nf++)
                    mma16816(acc[mf * 4 + nf], a + mf * 4, bh + nf * 2);
#pragma unroll
            for (int mf = 0; mf < 4; mf++)
#pragma unroll
                for (int nf = 0; nf < 4; nf++)
                    mma16816(acc[mf * 4 + nf], a + mf * 4, bl + nf * 2);
#pragma unroll
            for (int mf = 0; mf < 4; mf++) {
                int ra = wm + mf * 16 + (lane & 15);
                ldsm4(a + mf * 4, Ahi + 8192 + swzoff(ra, qa));
            }
#pragma unroll
            for (int mf = 0; mf < 4; mf++)
#pragma unroll
                for (int nf = 0; nf < 4; nf++)
                    mma16816(acc[mf * 4 + nf], a + mf * 4, bh + nf * 2);
        }
    };

    if (tid == 0) issue(0, 0);
    for (int s = 0; s < S; s++) {
        if (s + 1 < S && tid == 0) issue(s + 1, (s + 1) & 1);
        MBARRIER_WAIT_PARITY((s & 1) ? mb1 : mb0, (s >> 1) & 1);
        compute(s & 1);
        __syncthreads();
    }

    const float isc = (mode == 8) ? scale[0] : 0.f;
#pragma unroll
    for (int mf = 0; mf < 4; mf++) {
#pragma unroll
        for (int nf = 0; nf < 4; nf++) {
            float* cc = acc[mf * 4 + nf];
            int col = bn + wn + nf * 8 + (lane & 3) * 2;
            float bv0 = bias[col], bv1 = bias[col + 1];
#pragma unroll
            for (int rp = 0; rp < 2; rp++) {
                int m = bm + wm + mf * 16 + (lane >> 2) + rp * 8;
                float v0 = cc[rp * 2 + 0] + bv0;
                float v1 = cc[rp * 2 + 1] + bv1;
                if (mode == 0) {
                    *(float2*)(C + (size_t)m * DM + col) = make_float2(v0, v1);
                } else if (mode == 8) {
                    *(float2*)(g_Y + (size_t)m * DM + col) =
                        make_float2(isc * v0, isc * v1);
                } else if (mode == 4 || mode == 5) {
                    if (mode == 4) { v0 *= 0.125f; v1 *= 0.125f; }
                    int bb = m >> 9, si = m & 511, hh = col >> 6, d = col & 63;
                    int bh_ = bb * 8 + hh, mt = si >> 7, rr = si & 127;
                    int st = d >> 5, kb = (d & 31) * 2;
                    size_t blk = (((size_t)(bh_ * 4 + mt) * 2 + st) << 13) + swzoff(rr, kb);
                    char* base = (mode == 4) ? (char*)g_Qb : (char*)g_Kb;
                    float l0, l1;
                    uint32_t hp = pack_hi(v0, v1, l0, l1);
                    uint32_t lp = pack_lo(l0, l1);
                    *(uint32_t*)(base + blk)            = hp;
                    *(uint32_t*)(base + 8388608u + blk) = lp;
                } else {  // mode 6
                    int bb = m >> 9, si = m & 511, hh = col >> 6, d = col & 63;
                    int bh_ = bb * 8 + hh, st = si >> 5, kb = (si & 31) * 2;
                    size_t blk = ((size_t)(bh_ * 16 + st)) * 4096;
                    char* base = (char*)g_Vtb;
                    __nv_bfloat16 h0 = __float2bfloat16(v0);
                    __nv_bfloat16 h1 = __float2bfloat16(v1);
                    int o0 = swzoff(d, kb), o1 = swzoff(d + 1, kb);
                    *(__nv_bfloat16*)(base + blk + o0) = h0;
                    *(__nv_bfloat16*)(base + 8388608u + blk + o0) =
                        __float2bfloat16(v0 - __bfloat162float(h0));
                    *(__nv_bfloat16*)(base + blk + o1) = h1;
                    *(__nv_bfloat16*)(base + 8388608u + blk + o1) =
                        __float2bfloat16(v1 - __bfloat162float(h1));
                }
            }
        }
    }
}

// ===================== QK^T: paired tiles per Q-strip =============================
#define SK_SMEM (98304 + 64)

__global__ __launch_bounds__(256, 2) void qk_kernel(int bh0)
{
    extern __shared__ char sm[];
    const uint32_t sbase = smem_to_u32(sm);
    const uint32_t mbb = sbase + 98304;
    const int t = blockIdx.x;
    const int by  = (t >= 4) ? 3 : (t >= 2) ? 2 : t;
    const int bx0 = (t == 3 || t == 5) ? 2 : 0;
    const int ntl = (t == 0 || t == 3) ? 1 : 2;
    const int bm = by * 128;
    const int bh = bh0 + blockIdx.y;
    const int tid = threadIdx.x, wid = tid >> 5, lane = tid & 31;

    if (tid == 0) {
        MBARRIER_INIT(mbb, 1); MBARRIER_INIT(mbb + 8, 1);
        asm volatile("fence.proxy.async.shared::cta;" ::: "memory");
        const char* Qb = (const char*)g_Qb;
        const char* Kb = (const char*)g_Kb;
        MBARRIER_EXPECT_TX(mbb, 65536);
#pragma unroll
        for (int p = 0; p < 2; p++)
#pragma unroll
            for (int s = 0; s < 2; s++) {
                const char* qsrc = Qb + (size_t)p * 8388608u + (((size_t)(bh * 4 + by) * 2 + s) << 13);
                const char* ksrc = Kb + (size_t)p * 8388608u + (((size_t)(bh * 4 + bx0) * 2 + s) << 13);
                BULK_G2S(sbase + p * 16384 + s * 8192,         qsrc, 8192, mbb);
                BULK_G2S(sbase + 32768 + p * 16384 + s * 8192, ksrc, 8192, mbb);
            }
        if (ntl == 2) {
            MBARRIER_EXPECT_TX(mbb + 8, 32768);
#pragma unroll
            for (int p = 0; p < 2; p++)
#pragma unroll
                for (int s = 0; s < 2; s++) {
                    const char* ksrc = Kb + (size_t)p * 8388608u + (((size_t)(bh * 4 + bx0 + 1) * 2 + s) << 13);
                    BULK_G2S(sbase + 65536 + p * 16384 + s * 8192, ksrc, 8192, mbb + 8);
                }
        }
    }
    __syncthreads();

    const int wm = (wid >> 2) * 64, wn = (wid & 3) * 32;
    const int boff_n = ((lane >> 4) << 3) + (lane & 7);

    for (int ti = 0; ti < ntl; ti++) {
        MBARRIER_WAIT_PARITY(mbb + ti * 8, 0);
        const uint32_t Kbuf = sbase + 32768 + ti * 32768;
        const int bn = (bx0 + ti) * 128;

        float acc[16][4];
#pragma unroll
        for (int i = 0; i < 16; i++)
#pragma unroll
            for (int j = 0; j < 4; j++) acc[i][j] = 0.f;

#pragma unroll
        for (int kh = 0; kh < 4; kh++) {
            const int chunk = (kh >> 1) * 8192;
            const int qa = ((kh & 1) * 2 + (lane >> 4)) << 4;
            const int qb = ((kh & 1) * 2 + ((lane >> 3) & 1)) << 4;
            uint32_t bh_[8], bl_[8], a[16];
#pragma unroll
            for (int nf2 = 0; nf2 < 2; nf2++) {
                int rb = wn + nf2 * 16 + boff_n;
                uint32_t baddr = Kbuf + chunk + swzoff(rb, qb);
                ldsm4(bh_ + nf2 * 4, baddr);
                ldsm4(bl_ + nf2 * 4, baddr + 16384);
            }
#pragma unroll
            for (int mf = 0; mf < 4; mf++) {
                int ra = wm + mf * 16 + (lane & 15);
                ldsm4(a + mf * 4, sbase + chunk + swzoff(ra, qa));
            }
#pragma unroll
            for (int mf = 0; mf < 4; mf++)
#pragma unroll
                for (int nf = 0; nf < 4; nf++)
                    mma16816(acc[mf * 4 + nf], a + mf * 4, bh_ + nf * 2);
#pragma unroll
            for (int mf = 0; mf < 4; mf++)
#pragma unroll
                for (int nf = 0; nf < 4; nf++)
                    mma16816(acc[mf * 4 + nf], a + mf * 4, bl_ + nf * 2);
#pragma unroll
            for (int mf = 0; mf < 4; mf++) {
                int ra = wm + mf * 16 + (lane & 15);
                ldsm4(a + mf * 4, sbase + 16384 + chunk + swzoff(ra, qa));
            }
#pragma unroll
            for (int mf = 0; mf < 4; mf++)
#pragma unroll
                for (int nf = 0; nf < 4; nf++)
                    mma16816(acc[mf * 4 + nf], a + mf * 4, bh_ + nf * 2);
        }

        float* Sp = g_S + (size_t)bh * 512 * 512;
#pragma unroll
        for (int mf = 0; mf < 4; mf++)
#pragma unroll
            for (int nf = 0; nf < 4; nf++) {
                float* cc = acc[mf * 4 + nf];
                int col = bn + wn + nf * 8 + (lane & 3) * 2;
#pragma unroll
                for (int rp = 0; rp < 2; rp++) {
                    int m = bm + wm + mf * 16 + (lane >> 2) + rp * 8;
                    *(float2*)(Sp + (size_t)m * 512 + col) =
                        make_float2(cc[rp * 2], cc[rp * 2 + 1]);
                }
            }
    }
}

// ===================== row kernel (causal-truncated tiles) =========================
__global__ __launch_bounds__(256) void row_kernel(const float* __restrict__ gammas, int bh0)
{
    const int bh = bh0 + blockIdx.y, h = bh & 7;
    const int wid = threadIdx.x >> 5, lane = threadIdx.x & 31;
    const int i = blockIdx.x * 8 + wid;
    const int Ti = i >> 7;
    const int mt = i >> 7, rr = i & 127;
    char* Abase = (char*)g_A;

    if (i == 0) {
        uint2 zz = make_uint2(0u, 0u);
        int st = lane >> 3, kb = (lane & 7) * 8;
        size_t blk = ((size_t)(bh * 4 + 0) * 16 + st) * 8192 + swzoff(0, kb);
        *(uint2*)(Abase + blk)             = zz;
        *(uint2*)(Abase + 67108864u + blk) = zz;
        return;
    }

    float gv = gammas[h];
    float gam = -(fmaxf(gv, 0.f) + log1pf(__expf(-fabsf(gv))));

    const float4* Srow = (const float4*)(g_S + ((size_t)bh * 512 + i) * 512);
    float sc[4][4], e[4][4], ls[4];
#pragma unroll
    for (int t = 0; t < 4; t++) {
        if (t > Ti) { ls[t] = 0.f; continue; }
        float4 sv = Srow[lane + 32 * t];
        int j0 = 4 * (lane + 32 * t);
        sc[t][0] = (j0 + 0 < i) ? sv.x : NEG_INF;
        sc[t][1] = (j0 + 1 < i) ? sv.y : NEG_INF;
        sc[t][2] = (j0 + 2 < i) ? sv.z : NEG_INF;
        sc[t][3] = (j0 + 3 < i) ? sv.w : NEG_INF;
    }

    float m = NEG_INF;
#pragma unroll
    for (int t = 0; t < 4; t++) {
        if (t > Ti) break;
#pragma unroll
        for (int l = 0; l < 4; l++) m = fmaxf(m, sc[t][l]);
    }
#pragma unroll
    for (int off = 16; off; off >>= 1)
        m = fmaxf(m, __shfl_xor_sync(0xffffffffu, m, off));

#pragma unroll
    for (int t = 0; t < 4; t++) {
        if (t > Ti) break;
        ls[t] = 0.f;
#pragma unroll
        for (int l = 0; l < 4; l++) { e[t][l] = __expf(sc[t][l] - m); ls[t] += e[t][l]; }
    }
    float excl[4], tot[4];
#pragma unroll
    for (int t = 0; t < 4; t++) {
        if (t > Ti) break;
        float x = ls[t];
#pragma unroll
        for (int off = 1; off < 32; off <<= 1) {
            float y = __shfl_up_sync(0xffffffffu, x, off);
            if (lane >= off) x += y;
        }
        excl[t] = x - ls[t];
        tot[t]  = __shfl_sync(0xffffffffu, x, 31);
    }
    float baseA[4], T = 0.f;
#pragma unroll
    for (int t = 0; t < 4; t++) {
        if (t > Ti) break;
        baseA[t] = T; T += tot[t];
    }
    float invT = 1.f / T;

#pragma unroll
    for (int t = 0; t < 4; t++) {
        if (t > Ti) break;
        float run = baseA[t] + excl[t];
#pragma unroll
        for (int l = 0; l < 4; l++) {
            run += e[t][l];
            int j = 4 * lane + 128 * t + l;
            float suf  = fmaxf(T - run, 0.f);
            float dist = sqrtf(fmaxf(suf * invT * (float)(i - j), 0.f));
            float tmp  = __expf(dist * gam);
            tmp = fminf(fmaxf(tmp, 1e-5f), 1e5f);
            sc[t][l] = (j < i) ? sc[t][l] * tmp : NEG_INF;
        }
    }

    float m2 = NEG_INF;
#pragma unroll
    for (int t = 0; t < 4; t++) {
        if (t > Ti) break;
#pragma unroll
        for (int l = 0; l < 4; l++) m2 = fmaxf(m2, sc[t][l]);
    }
#pragma unroll
    for (int off = 16; off; off >>= 1)
        m2 = fmaxf(m2, __shfl_xor_sync(0xffffffffu, m2, off));
    float Z = 0.f;
#pragma unroll
    for (int t = 0; t < 4; t++) {
        if (t > Ti) break;
#pragma unroll
        for (int l = 0; l < 4; l++) { e[t][l] = __expf(sc[t][l] - m2); Z += e[t][l]; }
    }
#pragma unroll
    for (int off = 16; off; off >>= 1)
        Z += __shfl_xor_sync(0xffffffffu, Z, off);
    float invZ = 1.f / Z;

#pragma unroll
    for (int t = 0; t < 4; t++) {
        if (t > Ti) break;
        float a0 = e[t][0] * invZ, a1 = e[t][1] * invZ;
        float a2 = e[t][2] * invZ, a3 = e[t][3] * invZ;
        float l0, l1, l2, l3;
        uint2 hp; hp.x = pack_hi(a0, a1, l0, l1); hp.y = pack_hi(a2, a3, l2, l3);
        uint2 lp; lp.x = pack_lo(l0, l1);         lp.y = pack_lo(l2, l3);
        int st = (lane >> 3) + 4 * t, kb = (lane & 7) * 8;
        size_t blk = ((size_t)(bh * 4 + mt) * 16 + st) * 8192 + swzoff(rr, kb);
        *(uint2*)(Abase + blk)             = hp;
        *(uint2*)(Abase + 67108864u + blk) = lp;
    }
}

// ===================== AV batched GEMM (2-deep bulk pipeline, causal) =============
#define AVB 24576
#define AV_SMEM (2*AVB + 64)

__global__ __launch_bounds__(256, 2) void av_kernel(int bh0)
{
    extern __shared__ char sm[];
    const uint32_t sbase = smem_to_u32(sm);
    const uint32_t mb0 = sbase + 2 * AVB, mb1 = mb0 + 8;
    const int mt = blockIdx.x;
    const int bm = mt * 128;
    const int bh = bh0 + blockIdx.y;
    const int b = bh >> 3, h = bh & 7;
    const int tid = threadIdx.x, wid = tid >> 5, lane = tid & 31;
    const int nst = (bm + 128) >> 5;

    if (tid == 0) { MBARRIER_INIT(mb0, 1); MBARRIER_INIT(mb1, 1); }
    __syncthreads();

    float acc[8][4];
#pragma unroll
    for (int i = 0; i < 8; i++)
#pragma unroll
        for (int j = 0; j < 4; j++) acc[i][j] = 0.f;

    auto issue = [&](int s, int buf) {
        uint32_t mb = buf ? mb1 : mb0;
        uint32_t d = sbase + buf * AVB;
        MBARRIER_EXPECT_TX(mb, 24576);
        const char* Ap = (const char*)g_A + (((size_t)(bh * 4 + mt) * 16 + s) << 13);
        const char* Vp = (const char*)g_Vtb + ((size_t)(bh * 16 + s)) * 4096;
        BULK_G2S(d,         Ap,              8192, mb);
        BULK_G2S(d + 8192,  Ap + 67108864u,  8192, mb);
        BULK_G2S(d + 16384, Vp,              4096, mb);
        BULK_G2S(d + 20480, Vp + 8388608u,   4096, mb);
    };

    const int wm = (wid >> 1) * 32, wn = (wid & 1) * 32;
    const int boff_n = ((lane >> 4) << 3) + (lane & 7);

    auto compute = [&](int buf) {
        uint32_t Ab = sbase + buf * AVB;
        uint32_t Vb = Ab + 16384;
#pragma unroll
        for (int kh = 0; kh < 2; kh++) {
            const int qa = (kh * 2 + (lane >> 4)) << 4;
            const int qb = (kh * 2 + ((lane >> 3) & 1)) << 4;
            uint32_t bh_[8], bl_[8], a[8];
#pragma unroll
            for (int nf2 = 0; nf2 < 2; nf2++) {
                int rb = wn + nf2 * 16 + boff_n;
                uint32_t baddr = Vb + swzoff(rb, qb);
                ldsm4(bh_ + nf2 * 4, baddr);
                ldsm4(bl_ + nf2 * 4, baddr + 4096);
            }
#pragma unroll
            for (int mf = 0; mf < 2; mf++) {
                int ra = wm + mf * 16 + (lane & 15);
                ldsm4(a + mf * 4, Ab + swzoff(ra, qa));
            }
#pragma unroll
            for (int mf = 0; mf < 2; mf++)
#pragma unroll
                for (int nf = 0; nf < 4; nf++)
                    mma16816(acc[mf * 4 + nf], a + mf * 4, bh_ + nf * 2);
#pragma unroll
            for (int mf = 0; mf < 2; mf++)
#pragma unroll
                for (int nf = 0; nf < 4; nf++)
                    mma16816(acc[mf * 4 + nf], a + mf * 4, bl_ + nf * 2);
#pragma unroll
            for (int mf = 0; mf < 2; mf++) {
                int ra = wm + mf * 16 + (lane & 15);
                ldsm4(a + mf * 4, Ab + 8192 + swzoff(ra, qa));
            }
#pragma unroll
            for (int mf = 0; mf < 2; mf++)
#pragma unroll
                for (int nf = 0; nf < 4; nf++)
                    mma16816(acc[mf * 4 + nf], a + mf * 4, bh_ + nf * 2);
        }
    };

    if (tid == 0) issue(0, 0);
    for (int s = 0; s < nst; s++) {
        if (s + 1 < nst && tid == 0) issue(s + 1, (s + 1) & 1);
        MBARRIER_WAIT_PARITY((s & 1) ? mb1 : mb0, (s >> 1) & 1);
        compute(s & 1);
        __syncthreads();
    }

#pragma unroll
    for (int mf = 0; mf < 2; mf++)
#pragma unroll
        for (int nf = 0; nf < 4; nf++) {
            float* cc = acc[mf * 4 + nf];
            int col = wn + nf * 8 + (lane & 3) * 2;
#pragma unroll
            for (int rp = 0; rp < 2; rp++) {
                int mrow = bm + wm + mf * 16 + (lane >> 2) + rp * 8;
                *(float2*)(g_X + ((size_t)(b * 512 + mrow)) * 512 + h * 64 + col) =
                    make_float2(cc[rp * 2], cc[rp * 2 + 1]);
            }
        }
}

// ===================== parallel norm01 stats =====================
__global__ __launch_bounds__(256) void stats_kernel(
    const int* __restrict__ sgap, const int* __restrict__ pcount)
{
    __shared__ long long sh[32];
    int idx = blockIdx.x * 256 + threadIdx.x;
    long long a = sgap[idx], b = pcount[idx];
    long long s0 = a, q0 = a * a, s1 = b, q1 = b * b;
#pragma unroll
    for (int off = 16; off; off >>= 1) {
        s0 += __shfl_xor_sync(0xffffffffu, s0, off);
        q0 += __shfl_xor_sync(0xffffffffu, q0, off);
        s1 += __shfl_xor_sync(0xffffffffu, s1, off);
        q1 += __shfl_xor_sync(0xffffffffu, q1, off);
    }
    int wd = threadIdx.x >> 5, ln = threadIdx.x & 31;
    if (ln == 0) { sh[wd] = s0; sh[8+wd] = q0; sh[16+wd] = s1; sh[24+wd] = q1; }
    __syncthreads();
    if (threadIdx.x == 0) {
        long long S0=0,Q0=0,S1=0,Q1=0;
        for (int i = 0; i < 8; i++) { S0+=sh[i]; Q0+=sh[8+i]; S1+=sh[16+i]; Q1+=sh[24+i]; }
        atomicAdd(&g_sacc[0], (unsigned long long)S0);
        atomicAdd(&g_sacc[1], (unsigned long long)Q0);
        atomicAdd(&g_sacc[2], (unsigned long long)S1);
        atomicAdd(&g_sacc[3], (unsigned long long)Q1);
    }
}

// ===================== interference hidden layer -> bf16 blocks ===================
__global__ __launch_bounds__(256) void hidden_kernel(
    const int* __restrict__ sgap, const int* __restrict__ pcount,
    const float* __restrict__ Wi1, const float* __restrict__ bi1)
{
    float n = (float)MTOT;
    float S0 = (float)(long long)g_sacc[0], Q0 = (float)(long long)g_sacc[1];
    float S1 = (float)(long long)g_sacc[2], Q1 = (float)(long long)g_sacc[3];
    float m0 = S0 / n, m1 = S1 / n;
    float v0 = (Q0 - n*m0*m0) / (n - 1.f);
    float v1 = (Q1 - n*m1*m1) / (n - 1.f);
    float inv0 = 1.f / (sqrtf(fmaxf(v0, 0.f)) + 1e-6f);
    float inv1 = 1.f / (sqrtf(fmaxf(v1, 0.f)) + 1e-6f);

    int idx = blockIdx.x * 256 + threadIdx.x;
    int r = idx >> 6, c2 = (idx & 63) * 2;
    float ii0 = 0.5f * (tanhf(((float)sgap[r]   - m0) * inv0) + 1.f);
    float ii1 = 0.5f * (tanhf(((float)pcount[r] - m1) * inv1) + 1.f);
    float h0 = fmaxf(ii0 * Wi1[2*c2+0] + ii1 * Wi1[2*c2+1] + bi1[c2],   0.f);
    float h1 = fmaxf(ii0 * Wi1[2*c2+2] + ii1 * Wi1[2*c2+3] + bi1[c2+1], 0.f);
    float l0, l1;
    uint32_t hp = pack_hi(h0, h1, l0, l1);
    uint32_t lp = pack_lo(l0, l1);
    int mt = r >> 7, rr = r & 127, st = c2 >> 5, kb = (c2 & 31) * 2;
    size_t blk = ((size_t)mt * 4 + st) * 8192 + swzoff(rr, kb);
    char* base = (char*)g_Hb;
    *(uint32_t*)(base + blk)            = hp;
    *(uint32_t*)(base + 2097152u + blk) = lp;
}

// ===================== fused add (X+F) + LayerNorm + pack to bf16 blocks ==========
__global__ __launch_bounds__(256) void addln_pack_kernel(
    const float* __restrict__ gw, const float* __restrict__ bw)
{
    int r = blockIdx.x * 8 + (threadIdx.x >> 5);
    int lane = threadIdx.x & 31;
    const float4* xrow = (const float4*)(g_X + (size_t)r * DM);
    const float4* frow = (const float4*)(g_Y + (size_t)r * DM);
    float4 xv[4];
    float s = 0.f, q = 0.f;
#pragma unroll
    for (int c = 0; c < 4; c++) {
        float4 xa = xrow[lane + 32 * c];
        float4 fa = frow[lane + 32 * c];
        xv[c].x = xa.x + fa.x; xv[c].y = xa.y + fa.y;
        xv[c].z = xa.z + fa.z; xv[c].w = xa.w + fa.w;
        s += xv[c].x + xv[c].y + xv[c].z + xv[c].w;
        q += xv[c].x*xv[c].x + xv[c].y*xv[c].y + xv[c].z*xv[c].z + xv[c].w*xv[c].w;
    }
#pragma unroll
    for (int off = 16; off; off >>= 1) {
        s += __shfl_xor_sync(0xffffffffu, s, off);
        q += __shfl_xor_sync(0xffffffffu, q, off);
    }
    float mu   = s * (1.f / 512.f);
    float rstd = rsqrtf(q * (1.f / 512.f) - mu * mu + 1e-5f);
    int mt = r >> 7, rr = r & 127;
    char* base = (char*)g_Yb;
#pragma unroll
    for (int c = 0; c < 4; c++) {
        float4 g4 = ((const float4*)gw)[lane + 32 * c];
        float4 b4 = ((const float4*)bw)[lane + 32 * c];
        float n0 = (xv[c].x - mu) * rstd * g4.x + b4.x;
        float n1 = (xv[c].y - mu) * rstd * g4.y + b4.y;
        float n2 = (xv[c].z - mu) * rstd * g4.z + b4.z;
        float n3 = (xv[c].w - mu) * rstd * g4.w + b4.w;
        float l0, l1, l2, l3;
        uint2 hp; hp.x = pack_hi(n0, n1, l0, l1); hp.y = pack_hi(n2, n3, l2, l3);
        uint2 lp; lp.x = pack_lo(l0, l1);         lp.y = pack_lo(l2, l3);
        int st = (lane >> 3) + 4 * c, kb = (lane & 7) * 8;
        size_t blk = ((size_t)mt * 16 + st) * 8192 + swzoff(rr, kb);
        *(uint2*)(base + blk)            = hp;
        *(uint2*)(base + 8388608u + blk) = lp;
    }
}

// ===================== launcher (3-stream fork/join; static resources) =============
extern "C" void kernel_launch(void* const* d_in, const int* in_sizes, int n_in,
                              void* d_out, int out_size)
{
    const float* q      = (const float*)d_in[0];
    const float* k      = (const float*)d_in[1];
    const float* v      = (const float*)d_in[2];
    const int*   sgap   = (const int*)d_in[3];
    const int*   pcount = (const int*)d_in[4];
    const float* Wq = (const float*)d_in[5];  const float* bq = (const float*)d_in[6];
    const float* Wk = (const float*)d_in[7];  const float* bk = (const float*)d_in[8];
    const float* Wv = (const float*)d_in[9];  const float* bv = (const float*)d_in[10];
    const float* Wo = (const float*)d_in[11]; const float* bo = (const float*)d_in[12];
    const float* gammas = (const float*)d_in[13];
    const float* ln_g = (const float*)d_in[14]; const float* ln_b = (const float*)d_in[15];
    const float* Wi1 = (const float*)d_in[16];  const float* bi1 = (const float*)d_in[17];
    const float* Wi2 = (const float*)d_in[18];  const float* bi2 = (const float*)d_in[19];
    const float* iscale = (const float*)d_in[20];
    float* out = (float*)d_out;

    char *Ain, *Yb, *Hb;
    unsigned char* Wpk;
    cudaGetSymbolAddress((void**)&Ain, g_Ain);
    cudaGetSymbolAddress((void**)&Yb,  g_Yb);
    cudaGetSymbolAddress((void**)&Hb,  g_Hb);
    cudaGetSymbolAddress((void**)&Wpk, g_Wpk);

    // one-time resource creation (first call = correctness run, before the
    // harness's pre-capture memory baseline; reused by every later call)
    static bool inited = false;
    static cudaStream_t s2, s3;
    static cudaEvent_t eP0, eV, eQK, eA1, eF;
    if (!inited) {
        cudaFuncSetAttribute(pgemm_kernel, cudaFuncAttributeMaxDynamicSharedMemorySize, PG_SMEM);
        cudaFuncSetAttribute(qk_kernel, cudaFuncAttributeMaxDynamicSharedMemorySize, SK_SMEM);
        cudaFuncSetAttribute(av_kernel, cudaFuncAttributeMaxDynamicSharedMemorySize, AV_SMEM);
        cudaStreamCreateWithFlags(&s2, cudaStreamNonBlocking);
        cudaStreamCreateWithFlags(&s3, cudaStreamNonBlocking);
        cudaEventCreateWithFlags(&eP0, cudaEventDisableTiming);
        cudaEventCreateWithFlags(&eV,  cudaEventDisableTiming);
        cudaEventCreateWithFlags(&eQK, cudaEventDisableTiming);
        cudaEventCreateWithFlags(&eA1, cudaEventDisableTiming);
        cudaEventCreateWithFlags(&eF,  cudaEventDisableTiming);
        inited = true;
    }

    // fork s2 from the capture origin BEFORE any work: s2 runs concurrently
    // with prep_qk from t=0 (legal capture fork, unlike R16's orphan stream)
    cudaEventRecord(eP0, 0);
    cudaStreamWaitEvent(s2, eP0, 0);

    // main: Q/K prep only (critical path head shrinks ~36%)
    prep_qk_kernel<<<9216, 256>>>(Wq, Wk, Wpk, q, k);

    // s2: rest of prep -> stats -> V proj -> hidden -> F
    prep_rest_kernel<<<5248, 256, 0, s2>>>(Wv, Wo, Wi2, Wpk, v);
    stats_kernel<<<32, 256, 0, s2>>>(sgap, pcount);
    pgemm_kernel<<<dim3(4, 64, 1), 256, PG_SMEM, s2>>>(
        Ain + 2u*16777216u, 8388608L, 0L, (const char*)Wpk + 2097152u, 524288L, 0L,
        512, 6, bv, nullptr, nullptr, nullptr, nullptr);
    cudaEventRecord(eV, s2);
    hidden_kernel<<<2048, 256, 0, s2>>>(sgap, pcount, Wi1, bi1);
    pgemm_kernel<<<dim3(4, 64, 1), 256, PG_SMEM, s2>>>(
        Hb, 2097152L, 0L, (const char*)Wpk + 4194304u, 131072L, 0L,
        128, 8, bi2, nullptr, nullptr, nullptr, iscale);
    cudaEventRecord(eF, s2);

    // main: Q,K projections
    pgemm_kernel<<<dim3(4, 64, 2), 256, PG_SMEM>>>(
        Ain, 8388608L, 16777216L, (const char*)Wpk, 524288L, 1048576L,
        512, 4, bq, bk, nullptr, nullptr, nullptr);
    cudaEventRecord(eQK, 0);
    cudaStreamWaitEvent(s3, eQK, 0);

    // s3: attention half G1 (bh 64..127)
    qk_kernel<<<dim3(6, 64), 256, SK_SMEM, s3>>>(64);
    row_kernel<<<dim3(64, 64), 256, 0, s3>>>(gammas, 64);
    cudaStreamWaitEvent(s3, eV, 0);
    av_kernel<<<dim3(4, 64), 256, AV_SMEM, s3>>>(64);
    cudaEventRecord(eA1, s3);

    // main: attention half G0 (bh 0..63)
    qk_kernel<<<dim3(6, 64), 256, SK_SMEM>>>(0);
    row_kernel<<<dim3(64, 64), 256>>>(gammas, 0);
    cudaStreamWaitEvent(0, eV, 0);
    av_kernel<<<dim3(4, 64), 256, AV_SMEM>>>(0);

    // join: need both halves of X and F
    cudaStreamWaitEvent(0, eA1, 0);
    cudaStreamWaitEvent(0, eF, 0);
    addln_pack_kernel<<<1024, 256>>>(ln_g, ln_b);

    pgemm_kernel<<<dim3(4, 64, 1), 256, PG_SMEM>>>(
        Yb, 8388608L, 0L, (const char*)Wpk + 3145728u, 524288L, 0L,
        512, 0, bo, nullptr, nullptr, out, nullptr);
}